// round 6
// baseline (speedup 1.0000x reference)
#include <cuda_runtime.h>
#include <mma.h>
#include <cstdint>
using namespace nvcuda;

#define B_ 8
#define N_ 1024
#define H_ 768
#define NH_ 12
#define M_ 256
#define ST 72    // attn smem row stride (8 mod 32 -> conflict-free LDS.64)
#define STP 40   // proj smem row stride (k-tile 32 + pad 8)
#define KT 32
#define NKT 24
#define LOG2E 1.4426950408889634f

// ---------------- scratch ----------------
__device__ float g_xr[B_*N_*H_];       // tf32-rounded, k-permuted x
__device__ float g_Wr[5*H_*H_];        // tf32-rounded, k-permuted W: var,sym,q,k,v
__device__ float g_Qb[B_*N_*H_];       // k-permuted
__device__ float g_Kb[B_*N_*H_];       // k-permuted
__device__ float g_Vb[B_*N_*H_];       // linear
__device__ float g_sc[B_*N_];
__device__ float g_vg2[B_*N_];
__device__ float g_ab[B_*N_];
__device__ float g_dg[B_*N_];
__device__ float g_sumw[B_];
__device__ float g_c1[B_*N_];
__device__ float g_c2[B_*N_];
__device__ float g_Z[B_*NH_*N_];
__device__ float g_r1[B_*NH_*N_];
__device__ float g_r2[B_*NH_*N_];
__device__ float g_A1[B_*H_];
__device__ float g_A2[B_*H_];
__device__ float g_pm[B_*H_];

__device__ __forceinline__ bool d_pred(const int* P, int i){ return P[i]==1; }
__device__ __forceinline__ bool d_single(const int* P, int i){ return (i==0) || (i>=2 && P[i-2]==1); }
__device__ __forceinline__ float d_lrelu(float t){ return t >= 0.f ? t : 0.02f*t; }
__device__ __forceinline__ float tf32r(float x){ return wmma::__float_to_tf32(x); }
__device__ __forceinline__ float fex2(float x){ float y; asm("ex2.approx.f32 %0, %1;" : "=f"(y) : "f"(x)); return y; }

// ---------------- cp.async helpers ----------------
__device__ __forceinline__ void cpa16(float* s, const float* g){
  asm volatile("cp.async.cg.shared.global [%0], [%1], 16;\n"
               :: "r"((uint32_t)__cvta_generic_to_shared(s)), "l"(g));
}
__device__ __forceinline__ void cp_commit(){ asm volatile("cp.async.commit_group;\n"); }
__device__ __forceinline__ void cp_wait1(){ asm volatile("cp.async.wait_group 1;\n"); }
__device__ __forceinline__ void cp_wait0(){ asm volatile("cp.async.wait_group 0;\n"); }

// ---------------- m16n8k8 tf32 mma.sync ----------------
__device__ __forceinline__ void mma8(float c[4], const uint32_t a[4], uint32_t b0, uint32_t b1){
  asm volatile(
    "mma.sync.aligned.m16n8k8.row.col.f32.tf32.tf32.f32 "
    "{%0,%1,%2,%3}, {%4,%5,%6,%7}, {%8,%9}, {%0,%1,%2,%3};\n"
    : "+f"(c[0]), "+f"(c[1]), "+f"(c[2]), "+f"(c[3])
    : "r"(a[0]), "r"(a[1]), "r"(a[2]), "r"(a[3]), "r"(b0), "r"(b1));
}

// MMA micro-kernel on k-permuted smem: A rows 32/warp (wr), B cols NF*8/warp (wc).
template<int STRIDE, int NF, int K8>
__device__ __forceinline__ void mma_tile_p(const float* As, const float* Bs,
                                           float c[2][NF][4], int wr, int wc, int lane){
  #pragma unroll
  for (int k8=0;k8<K8;k8++){
    int ac = k8*8 + 2*(lane&3);
    uint32_t a[2][4];
    int ar = wr*32 + (lane>>2);
    #pragma unroll
    for (int rf=0; rf<2; rf++){
      const float* Ab = As + (ar + rf*16)*STRIDE + ac;
      float2 v0 = *(const float2*)(Ab);
      float2 v1 = *(const float2*)(Ab + 8*STRIDE);
      a[rf][0]=__float_as_uint(v0.x); a[rf][2]=__float_as_uint(v0.y);
      a[rf][1]=__float_as_uint(v1.x); a[rf][3]=__float_as_uint(v1.y);
    }
    #pragma unroll
    for (int nf=0;nf<NF;nf++){
      int br = wc*(NF*8) + nf*8 + (lane>>2);
      float2 bv = *(const float2*)(Bs + br*STRIDE + ac);
      mma8(c[0][nf], a[0], __float_as_uint(bv.x), __float_as_uint(bv.y));
      mma8(c[1][nf], a[1], __float_as_uint(bv.x), __float_as_uint(bv.y));
    }
  }
}

// ---------------- init ----------------
__global__ void k_init(const float* __restrict__ bsc){
  int i = blockIdx.x*blockDim.x + threadIdx.x;
  if (i < B_*N_){ g_vg2[i] = 0.f; g_sc[i] = bsc[0]; }
  if (i < B_*H_){ g_A1[i]=0.f; g_A2[i]=0.f; }
  if (i < B_*NH_*N_){ g_Z[i]=0.f; g_r1[i]=0.f; g_r2[i]=0.f; }
}

// ---------------- pre-round to tf32 + k-permute (group [0,4,1,5,2,6,3,7]) ----------------
__global__ void k_preconv(const float* __restrict__ x,
                          const float* __restrict__ W0, const float* __restrict__ W1,
                          const float* __restrict__ W2, const float* __restrict__ W3,
                          const float* __restrict__ W4){
  const int XT4 = B_*N_*H_/4;
  const int WT4 = H_*H_/4;
  int i = blockIdx.x*blockDim.x + threadIdx.x;
  if (i < XT4){
    float4 v = ((const float4*)x)[i];
    int g = 4*(i & ~1), b = i&1;
    g_xr[g + 0 + b] = tf32r(v.x);
    g_xr[g + 2 + b] = tf32r(v.y);
    g_xr[g + 4 + b] = tf32r(v.z);
    g_xr[g + 6 + b] = tf32r(v.w);
  } else {
    int j = i - XT4;
    if (j < 5*WT4){
      int w = j / WT4, o = j - w*WT4;
      const float* src = (w==0)?W0:(w==1)?W1:(w==2)?W2:(w==3)?W3:W4;
      float4 v = ((const float4*)src)[o];
      float* dst = g_Wr + (size_t)w*H_*H_;
      int g = 4*(o & ~1), b = o&1;
      dst[g + 0 + b] = tf32r(v.x);
      dst[g + 2 + b] = tf32r(v.y);
      dst[g + 4 + b] = tf32r(v.z);
      dst[g + 6 + b] = tf32r(v.w);
    }
  }
}

// ---------------- mode-0 A staging: neighbor average of permuted x (elementwise-safe) ----------------
__device__ __forceinline__ void stage_avg(float* dst, int m0, int kc, const int* __restrict__ pp, int tid){
  #pragma unroll
  for (int i=0;i<4;i++){
    int lin = tid + i*256;
    int r = lin>>3, q = (lin&7)*4;
    int m = m0 + r, b = m>>10, n = m&(N_-1);
    bool single = (n==0) || (n>=2 && pp[b*N_+n-2]==1);
    int np = (n+1)&(N_-1), nm = (n+N_-1)&(N_-1);
    const float* base = g_xr + ((size_t)(b<<10))*H_ + kc + q;
    float4 xn = *(const float4*)(base + (size_t)np*H_);
    float4 v;
    if (single) v = xn;
    else {
      float4 xp = *(const float4*)(base + (size_t)nm*H_);
      v.x=0.5f*(xp.x+xn.x); v.y=0.5f*(xp.y+xn.y); v.z=0.5f*(xp.z+xn.z); v.w=0.5f*(xp.w+xn.w);
    }
    *(float4*)(dst + r*STP + q) = v;
  }
}

// ---------------- merged projections: z = 0:var(score) 1:sym(score) 2:Q 3:K 4:V ----------------
__global__ __launch_bounds__(256,2) void k_proj(
    const float* __restrict__ b_var, const float* __restrict__ b_sym,
    const float* __restrict__ b_q, const float* __restrict__ b_k, const float* __restrict__ b_v,
    const float* __restrict__ Wsc, const int* __restrict__ pp,
    float* __restrict__ Qb, float* __restrict__ Kb, float* __restrict__ Vb){
  extern __shared__ float sm[];
  float* Ab[2] = { sm,             sm + 128*STP };
  float* Bb[2] = { sm + 2*128*STP, sm + 3*128*STP };
  int mode = blockIdx.z;
  const float* W = g_Wr + (size_t)mode*H_*H_;
  const float* bias; float* C=nullptr; float alpha=1.f; const float* wsc=nullptr;
  switch(mode){
    case 0: bias=b_var; wsc=Wsc;    break;
    case 1: bias=b_sym; wsc=Wsc+H_; break;
    case 2: bias=b_q;   C=Qb; alpha=0.125f*LOG2E; break;   // fold SCALE*log2e
    case 3: bias=b_k;   C=Kb; break;
    default:bias=b_v;   C=Vb; break;
  }
  int tid=threadIdx.x, lane=tid&31, wid=tid>>5;
  int wr=wid&3, wc=wid>>2;
  int m0 = blockIdx.y*128, n0 = blockIdx.x*128;
  if (mode==0) stage_avg(Ab[0], m0, 0, pp, tid);
  else {
    #pragma unroll
    for (int i=0;i<4;i++){
      int lin=tid+i*256; int r=lin>>3, q=(lin&7)*4;
      cpa16(Ab[0]+r*STP+q, g_xr + (size_t)(m0+r)*H_ + q);
    }
  }
  #pragma unroll
  for (int i=0;i<4;i++){
    int lin=tid+i*256; int r=lin>>3, q=(lin&7)*4;
    cpa16(Bb[0]+r*STP+q, W + (size_t)(n0+r)*H_ + q);
  }
  cp_commit();
  float c[2][8][4];
  #pragma unroll
  for(int i=0;i<2;i++)
    #pragma unroll
    for(int j=0;j<8;j++){ c[i][j][0]=0;c[i][j][1]=0;c[i][j][2]=0;c[i][j][3]=0; }
  for (int kt=0; kt<NKT; kt++){
    int cur=kt&1, nxt=1-cur;
    if (kt+1<NKT){
      if (mode!=0){
        #pragma unroll
        for (int i=0;i<4;i++){
          int lin=tid+i*256; int r=lin>>3, q=(lin&7)*4;
          cpa16(Ab[nxt]+r*STP+q, g_xr + (size_t)(m0+r)*H_ + (kt+1)*KT + q);
        }
      }
      #pragma unroll
      for (int i=0;i<4;i++){
        int lin=tid+i*256; int r=lin>>3, q=(lin&7)*4;
        cpa16(Bb[nxt]+r*STP+q, W + (size_t)(n0+r)*H_ + (kt+1)*KT + q);
      }
      cp_commit();
      cp_wait1();
    } else cp_wait0();
    __syncthreads();
    mma_tile_p<STP,8,4>(Ab[cur], Bb[cur], c, wr, wc, lane);
    if (mode==0 && kt+1<NKT) stage_avg(Ab[nxt], m0, (kt+1)*KT, pp, tid);
    __syncthreads();
  }
  int t = lane&3;
  if (mode<=1){
    float p[4] = {0,0,0,0};
    #pragma unroll
    for (int rf=0; rf<2; rf++){
      #pragma unroll
      for (int nf=0; nf<8; nf++){
        int col0 = n0 + wc*64 + nf*8 + 2*t;
        float w0 = wsc[col0], w1 = wsc[col0+1];
        float b0v = bias[col0], b1v = bias[col0+1];
        p[rf*2+0] += tanhf(c[rf][nf][0]+b0v)*w0 + tanhf(c[rf][nf][1]+b1v)*w1;
        p[rf*2+1] += tanhf(c[rf][nf][2]+b0v)*w0 + tanhf(c[rf][nf][3]+b1v)*w1;
      }
    }
    #pragma unroll
    for (int i=0;i<4;i++){
      float v = p[i];
      v += __shfl_xor_sync(0xffffffffu, v, 1);
      v += __shfl_xor_sync(0xffffffffu, v, 2);
      if (t==0)
        atomicAdd(&g_sc[m0 + wr*32 + (i>>1)*16 + (lane>>2) + (i&1)*8], v);
    }
  } else if (mode==4){
    #pragma unroll
    for (int rf=0; rf<2; rf++){
      int row = m0 + wr*32 + rf*16 + (lane>>2);
      #pragma unroll
      for (int nf=0; nf<8; nf++){
        int col0 = n0 + wc*64 + nf*8 + 2*t;
        float2 bv = *(const float2*)(bias + col0);
        *(float2*)(C + (size_t)row*H_ + col0)     = make_float2(c[rf][nf][0]+bv.x, c[rf][nf][1]+bv.y);
        *(float2*)(C + (size_t)(row+8)*H_ + col0) = make_float2(c[rf][nf][2]+bv.x, c[rf][nf][3]+bv.y);
      }
    }
  } else {
    // Q/K: tf32-round and store k-PERMUTED (feeds attn mma)
    int p0 = ((2*t)&3)*2 + (t>>1);
    int p1 = ((2*t+1)&3)*2 + ((2*t+1)>>2);
    #pragma unroll
    for (int rf=0; rf<2; rf++){
      int row = m0 + wr*32 + rf*16 + (lane>>2);
      #pragma unroll
      for (int nf=0; nf<8; nf++){
        int base = n0 + wc*64 + nf*8;
        float b0v = bias[base + 2*t], b1v = bias[base + 2*t + 1];
        C[(size_t)row*H_ + base + p0]     = tf32r(alpha*(c[rf][nf][0]+b0v));
        C[(size_t)row*H_ + base + p1]     = tf32r(alpha*(c[rf][nf][1]+b1v));
        C[(size_t)(row+8)*H_ + base + p0] = tf32r(alpha*(c[rf][nf][2]+b0v));
        C[(size_t)(row+8)*H_ + base + p1] = tf32r(alpha*(c[rf][nf][3]+b1v));
      }
    }
  }
}

// ---------------- cross scores -> VG^2 diagonal ----------------
__global__ __launch_bounds__(128) void k_cross(const float* __restrict__ x, const float* __restrict__ Wc,
                                               const float* __restrict__ bc, const int* __restrict__ occ){
  int pid = blockIdx.x;
  int b = pid / M_;
  int o0 = occ[pid*2], o1 = occ[pid*2+1];
  const float* x0 = x + ((size_t)b*N_+o0)*H_;
  const float* x1 = x + ((size_t)b*N_+o1)*H_;
  float p = 0.f;
  for (int h=threadIdx.x; h<H_; h+=128) p += 0.5f*(x0[h]+x1[h])*Wc[h];
  for (int o=16;o;o>>=1) p += __shfl_xor_sync(0xffffffffu, p, o);
  __shared__ float red[4];
  if ((threadIdx.x&31)==0) red[threadIdx.x>>5] = p;
  __syncthreads();
  if (threadIdx.x==0){
    float t = d_lrelu(bc[0] + red[0]+red[1]+red[2]+red[3]);
    atomicAdd(&g_vg2[b*N_+o0], t*t);
    atomicAdd(&g_vg2[b*N_+o1], t*t);
  }
}

// ---------------- band + sumw + coef, one block per batch ----------------
__global__ __launch_bounds__(1024) void k_post(const int* __restrict__ pp){
  __shared__ float ab[N_], wt[N_], red[32];
  __shared__ float swv;
  int b = blockIdx.x, n = threadIdx.x;
  const int* P = pp + b*N_;
  const float* s = g_sc + b*N_;
  float a = 0.f;
  if (n < N_-1){
    float sl1 = d_pred(P,n+1) ? d_lrelu(s[n+1]) : 0.f;
    bool up0 = d_pred(P,n) && (n<=1 || !d_single(P,n));
    float su0 = up0 ? d_lrelu(s[n]) : 0.f;
    a = sl1 + su0;
  }
  ab[n] = a; g_ab[b*N_+n] = a;
  bool up = d_pred(P,n) && (n<=1 || !d_single(P,n));
  bool tr = up && (n>=1);
  float w = d_pred(P,n) ? (tr?3.f:2.f) : 0.f;
  wt[n] = w;
  float v = w;
  for (int o=16;o;o>>=1) v += __shfl_xor_sync(0xffffffffu, v, o);
  if ((n&31)==0) red[n>>5] = v;
  __syncthreads();
  if (n < 32){
    float t2 = red[n];
    for (int o=16;o;o>>=1) t2 += __shfl_xor_sync(0xffffffffu, t2, o);
    if (n==0){ swv = t2; g_sumw[b] = t2; }
  }
  __syncthreads();
  float am1 = (n>=1) ? ab[n-1] : 0.f;
  g_dg[b*N_+n] = 0.8f*(am1*am1 + a*a) + g_vg2[b*N_+n];
  float sw = swv;
  int nm = (n+N_-1)&(N_-1), np = (n+1)&(N_-1);
  float c1 = wt[nm]*(d_single(P,nm)?1.f:0.5f) + wt[np]*(d_single(P,np)?0.f:0.5f);
  g_c1[b*N_+n] = c1 / sw;
  g_c2[b*N_+n] = wt[n] / sw;
}

// ---------------- attention pass 1: Z[bh][n] = sum_m exp(S+bias) (base-2 internally) ----------------
__global__ __launch_bounds__(256,2) void k_attn1(){
  extern __shared__ float sm[];
  float* Qs   = sm;                                  // 128*ST resident (n rows)
  float* Kb2[2] = { sm + 128*ST, sm + 128*ST + 64*ST };
  float* rowp = sm + 128*ST + 2*64*ST;               // 5*128, idx = d+2, pre-scaled by LOG2E
  int tid=threadIdx.x, lane=tid&31, wid=tid>>5;
  int wr=wid&3, wc=wid>>2;
  int bh=blockIdx.x, b=bh/NH_, h=bh-b*NH_;
  int n0=blockIdx.y*128;
  const float* Q = g_Qb + (size_t)b*N_*H_ + h*64;
  const float* K = g_Kb + (size_t)b*N_*H_ + h*64;
  #pragma unroll
  for (int it=0; it<8; it++){
    int lin = tid + it*256;
    int r = lin>>4, q = (lin&15)*4;
    cpa16(Qs + r*ST + q, Q + (size_t)(n0+r)*H_ + q);
  }
  #pragma unroll
  for (int it=0; it<4; it++){
    int lin = tid + it*256;
    int r = lin>>4, q = (lin&15)*4;
    cpa16(Kb2[0] + r*ST + q, K + (size_t)r*H_ + q);
  }
  cp_commit();
  if (tid < 128){
    int n = n0 + tid;
    const float* ab = g_ab + b*N_;
    float anm2=(n>=2)?ab[n-2]:0.f, anm1=(n>=1)?ab[n-1]:0.f;
    float an=ab[n], anp1=(n<N_-1)?ab[n+1]:0.f;
    rowp[0*128+tid]=LOG2E*0.8f*anm2*anm1;
    rowp[1*128+tid]=LOG2E*0.2f*anm1;
    rowp[2*128+tid]=LOG2E*g_dg[b*N_+n];
    rowp[3*128+tid]=LOG2E*0.2f*an;
    rowp[4*128+tid]=LOG2E*0.8f*an*anp1;
  }
  float z[4]={0,0,0,0};
  for (int mt=0; mt<16; mt++){
    int cur=mt&1;
    if (mt+1<16){
      #pragma unroll
      for (int it=0; it<4; it++){
        int lin = tid + it*256;
        int r = lin>>4, q = (lin&15)*4;
        cpa16(Kb2[1-cur] + r*ST + q, K + (size_t)((mt+1)*64+r)*H_ + q);
      }
      cp_commit();
      cp_wait1();
    } else cp_wait0();
    __syncthreads();
    float c[2][4][4];
    #pragma unroll
    for(int i=0;i<2;i++)
      #pragma unroll
      for(int j=0;j<4;j++){ c[i][j][0]=0;c[i][j][1]=0;c[i][j][2]=0;c[i][j][3]=0; }
    mma_tile_p<ST,4,8>(Qs, Kb2[cur], c, wr, wc, lane);
    bool band = (mt*64 + 63 >= n0 - 2) && (mt*64 <= n0 + 129);
    if (band){
      #pragma unroll
      for (int rf=0; rf<2; rf++){
        int lr0 = wr*32 + rf*16 + (lane>>2);
        #pragma unroll
        for (int nf=0; nf<4; nf++){
          int mbase = mt*64 + wc*32 + nf*8 + 2*(lane&3);
          #pragma unroll
          for (int e=0; e<4; e++){
            int hi = e>>1;
            int lr = lr0 + hi*8;
            int d = (mbase + (e&1)) - (n0 + lr);
            float bias = ((unsigned)(d+2) < 5u) ? rowp[(d+2)*128 + lr] : 0.f;
            z[rf*2+hi] += fex2(c[rf][nf][e] + bias);
          }
        }
      }
    } else {
      #pragma unroll
      for (int rf=0; rf<2; rf++)
        #pragma unroll
        for (int nf=0; nf<4; nf++){
          z[rf*2+0] += fex2(c[rf][nf][0]) + fex2(c[rf][nf][1]);
          z[rf*2+1] += fex2(c[rf][nf][2]) + fex2(c[rf][nf][3]);
        }
    }
    __syncthreads();
  }
  #pragma unroll
  for (int i=0;i<4;i++){
    float v = z[i];
    v += __shfl_xor_sync(0xffffffffu, v, 1);
    v += __shfl_xor_sync(0xffffffffu, v, 2);
    if ((lane&3)==0)
      atomicAdd(&g_Z[(size_t)bh*N_ + n0 + wr*32 + (i>>1)*16 + (lane>>2) + (i&1)*8], v);
  }
}

// ---------------- attention pass 2: r[m] = sum_n (c[n]/Z[n])*exp(S+bias) ----------------
__global__ __launch_bounds__(256,2) void k_attn2(){
  extern __shared__ float sm[];
  float* Ks   = sm;                                  // 128*ST resident (m rows)
  float* Qb2[2] = { sm + 128*ST, sm + 128*ST + 64*ST };
  float* colp = sm + 128*ST + 2*64*ST;               // 7*64 per tile
  int tid=threadIdx.x, lane=tid&31, wid=tid>>5;
  int wr=wid&3, wc=wid>>2;
  int bh=blockIdx.x, b=bh/NH_, h=bh-b*NH_;
  int m0=blockIdx.y*128;
  const float* Q = g_Qb + (size_t)b*N_*H_ + h*64;
  const float* K = g_Kb + (size_t)b*N_*H_ + h*64;
  #pragma unroll
  for (int it=0; it<8; it++){
    int lin = tid + it*256;
    int r = lin>>4, q = (lin&15)*4;
    cpa16(Ks + r*ST + q, K + (size_t)(m0+r)*H_ + q);
  }
  #pragma unroll
  for (int it=0; it<4; it++){
    int lin = tid + it*256;
    int r = lin>>4, q = (lin&15)*4;
    cpa16(Qb2[0] + r*ST + q, Q + (size_t)r*H_ + q);
  }
  cp_commit();
  float r1[4]={0,0,0,0}, r2[4]={0,0,0,0};
  for (int nt=0; nt<16; nt++){
    int cur=nt&1;
    if (nt+1<16){
      #pragma unroll
      for (int it=0; it<4; it++){
        int lin = tid + it*256;
        int r = lin>>4, q = (lin&15)*4;
        cpa16(Qb2[1-cur] + r*ST + q, Q + (size_t)((nt+1)*64+r)*H_ + q);
      }
      cp_commit();
    }
    if (tid < 64){
      int n = nt*64 + tid;
      const float* ab = g_ab + b*N_;
      float anm2=(n>=2)?ab[n-2]:0.f, anm1=(n>=1)?ab[n-1]:0.f;
      float an=ab[n], anp1=(n<N_-1)?ab[n+1]:0.f;
      colp[0*64+tid]=LOG2E*0.8f*anm2*anm1;
      colp[1*64+tid]=LOG2E*0.2f*anm1;
      colp[2*64+tid]=LOG2E*g_dg[b*N_+n];
      colp[3*64+tid]=LOG2E*0.2f*an;
      colp[4*64+tid]=LOG2E*0.8f*an*anp1;
      float iz = 1.f / g_Z[(size_t)bh*N_ + n];
      colp[5*64+tid]=g_c1[b*N_+n]*iz;
      colp[6*64+tid]=g_c2[b*N_+n]*iz;
    }
    if (nt+1<16) cp_wait1(); else cp_wait0();
    __syncthreads();
    float c[2][4][4];
    #pragma unroll
    for(int i=0;i<2;i++)
      #pragma unroll
      for(int j=0;j<4;j++){ c[i][j][0]=0;c[i][j][1]=0;c[i][j][2]=0;c[i][j][3]=0; }
    mma_tile_p<ST,4,8>(Ks, Qb2[cur], c, wr, wc, lane);
    bool band = (nt*64 + 63 >= m0 - 2) && (nt*64 <= m0 + 129);
    #pragma unroll
    for (int rf=0; rf<2; rf++){
      int mr0 = m0 + wr*32 + rf*16 + (lane>>2);
      #pragma unroll
      for (int nf=0; nf<4; nf++){
        int lc0 = wc*32 + nf*8 + 2*(lane&3);
        float w1a = colp[5*64+lc0], w1b = colp[5*64+lc0+1];
        float w2a = colp[6*64+lc0], w2b = colp[6*64+lc0+1];
        if (band){
          #pragma unroll
          for (int e=0; e<4; e++){
            int hi = e>>1;
            int lc = lc0 + (e&1);
            int d = (mr0 + hi*8) - (nt*64 + lc);
            float bias = ((unsigned)(d+2) < 5u) ? colp[(d+2)*64 + lc] : 0.f;
            float P = fex2(c[rf][nf][e] + bias);
            r1[rf*2+hi] += ((e&1)? w1b : w1a) * P;
            r2[rf*2+hi] += ((e&1)? w2b : w2a) * P;
          }
        } else {
          float P0 = fex2(c[rf][nf][0]), P1 = fex2(c[rf][nf][1]);
          float P2 = fex2(c[rf][nf][2]), P3 = fex2(c[rf][nf][3]);
          r1[rf*2+0] += w1a*P0 + w1b*P1;  r2[rf*2+0] += w2a*P0 + w2b*P1;
          r1[rf*2+1] += w1a*P2 + w1b*P3;  r2[rf*2+1] += w2a*P2 + w2b*P3;
        }
      }
    }
    __syncthreads();
  }
  #pragma unroll
  for (int i=0;i<4;i++){
    float v1 = r1[i], v2 = r2[i];
    v1 += __shfl_xor_sync(0xffffffffu, v1, 1);
    v1 += __shfl_xor_sync(0xffffffffu, v1, 2);
    v2 += __shfl_xor_sync(0xffffffffu, v2, 1);
    v2 += __shfl_xor_sync(0xffffffffu, v2, 2);
    if ((lane&3)==0){
      size_t o = (size_t)bh*N_ + m0 + wr*32 + (i>>1)*16 + (lane>>2) + (i&1)*8;
      atomicAdd(&g_r1[o], v1);
      atomicAdd(&g_r2[o], v2);
    }
  }
}

// ---------------- A = r @ V ----------------
__global__ __launch_bounds__(768) void k_matvec(){
  int b = blockIdx.x, f = threadIdx.x, h = f >> 6;
  int m0 = blockIdx.y*64;
  const float* r1 = g_r1 + ((size_t)b*NH_+h)*N_;
  const float* r2 = g_r2 + ((size_t)b*NH_+h)*N_;
  float a1=0.f, a2=0.f;
  for (int m=m0; m<m0+64; m++){
    float vv = g_Vb[((size_t)b*N_+m)*H_+f];
    a1 += r1[m]*vv; a2 += r2[m]*vv;
  }
  atomicAdd(&g_A1[b*H_+f], a1);
  atomicAdd(&g_A2[b*H_+f], a2);
}

// ---------------- final projections + broadcast ----------------
__global__ __launch_bounds__(768) void k_final(const float* __restrict__ Wo, const float* __restrict__ bo,
                                               const float* __restrict__ Wa, const float* __restrict__ ba){
  int b = blockIdx.x, o = threadIdx.x;
  __shared__ float u1s[H_], u2s[H_];
  const float* w = Wo + (size_t)o*H_;
  const float* A1 = g_A1 + b*H_;
  const float* A2 = g_A2 + b*H_;
  float u1 = bo[o], u2 = bo[o];
  for (int i=0;i<H_;i++){ u1 += w[i]*A1[i]; u2 += w[i]*A2[i]; }
  u1s[o] = u1; u2s[o] = u2;
  __syncthreads();
  const float* wa = Wa + (size_t)o*2*H_;
  float p = ba[o];
  for (int i=0;i<H_;i++) p += wa[i]*u1s[i] + wa[H_+i]*u2s[i];
  g_pm[b*H_+o] = p;
}

__global__ void k_bcast(float* __restrict__ out){
  int idx = blockIdx.x*blockDim.x + threadIdx.x;
  if (idx >= B_*N_*H_) return;
  int f = idx % H_;
  int b = idx / (N_*H_);
  out[idx] = g_pm[b*H_+f];
}

// ---------------- launch ----------------
extern "C" void kernel_launch(void* const* d_in, const int* in_sizes, int n_in,
                              void* d_out, int out_size){
  (void)in_sizes; (void)n_in; (void)out_size;
  const float* x      = (const float*)d_in[0];
  const float* W_var  = (const float*)d_in[3];
  const float* b_var  = (const float*)d_in[4];
  const float* W_sym  = (const float*)d_in[5];
  const float* b_sym  = (const float*)d_in[6];
  const float* W_sc   = (const float*)d_in[7];
  const float* b_scb  = (const float*)d_in[8];
  const float* W_cr   = (const float*)d_in[9];
  const float* b_cr   = (const float*)d_in[10];
  const float* W_atom = (const float*)d_in[11];
  const float* b_atom = (const float*)d_in[12];
  const float* W_q    = (const float*)d_in[13];
  const float* b_q    = (const float*)d_in[14];
  const float* W_k    = (const float*)d_in[15];
  const float* b_k    = (const float*)d_in[16];
  const float* W_v    = (const float*)d_in[17];
  const float* b_v    = (const float*)d_in[18];
  const float* W_o    = (const float*)d_in[19];
  const float* b_o    = (const float*)d_in[20];
  const int*   pp     = (const int*)d_in[21];
  const int*   occ    = (const int*)d_in[24];
  float* out = (float*)d_out;

  float *p_Q, *p_K, *p_V;
  cudaGetSymbolAddress((void**)&p_Q, g_Qb);
  cudaGetSymbolAddress((void**)&p_K, g_Kb);
  cudaGetSymbolAddress((void**)&p_V, g_Vb);

  const int PROJ_SMEM = (4*128*STP)*4;
  const int ATTN1_SMEM = (128*ST + 2*64*ST + 5*128)*4;
  const int ATTN2_SMEM = (128*ST + 2*64*ST + 7*64)*4;
  static bool attr_done = false;
  if (!attr_done){
    cudaFuncSetAttribute(k_proj,  cudaFuncAttributeMaxDynamicSharedMemorySize, PROJ_SMEM);
    cudaFuncSetAttribute(k_attn1, cudaFuncAttributeMaxDynamicSharedMemorySize, ATTN1_SMEM);
    cudaFuncSetAttribute(k_attn2, cudaFuncAttributeMaxDynamicSharedMemorySize, ATTN2_SMEM);
    attr_done = true;
  }

  k_init<<<(B_*NH_*N_+255)/256, 256>>>(b_scb);
  const int PRE4 = B_*N_*H_/4 + 5*H_*H_/4;
  k_preconv<<<(PRE4+255)/256, 256>>>(x, W_var, W_sym, W_q, W_k, W_v);

  dim3 gp(H_/128, (B_*N_)/128, 5);
  k_proj<<<gp, 256, PROJ_SMEM>>>(b_var, b_sym, b_q, b_k, b_v, W_sc, pp, p_Q, p_K, p_V);

  k_cross<<<B_*M_, 128>>>(x, W_cr, b_cr, occ);
  k_post<<<B_, 1024>>>(pp);

  dim3 ga(B_*NH_, N_/128);
  k_attn1<<<ga, 256, ATTN1_SMEM>>>();
  k_attn2<<<ga, 256, ATTN2_SMEM>>>();

  dim3 gmv(B_, 16);
  k_matvec<<<gmv, 768>>>();
  k_final<<<B_, 768>>>(W_o, b_o, W_atom, b_atom);
  k_bcast<<<(B_*N_*H_+255)/256, 256>>>(out);
}

// round 7
// speedup vs baseline: 1.0049x; 1.0049x over previous
#include <cuda_runtime.h>
#include <mma.h>
#include <cstdint>
using namespace nvcuda;

#define B_ 8
#define N_ 1024
#define H_ 768
#define NH_ 12
#define M_ 256
#define ST 72    // attn smem row stride (8 mod 32 -> conflict-free LDS.64)
#define STP 40   // proj smem row stride
#define KT 32
#define NKT 24
#define LOG2E 1.4426950408889634f

// ---------------- scratch ----------------
__device__ float g_xr[B_*N_*H_];       // tf32-rounded, k-permuted x
__device__ float g_Wr[5*H_*H_];        // tf32-rounded, k-permuted W (q/k also n-permuted)
__device__ float g_Qb[B_*N_*H_];       // k-permuted, pre-scaled by 0.125*log2e
__device__ float g_Kb[B_*N_*H_];       // k-permuted
__device__ float g_Vb[B_*N_*H_];       // linear
__device__ float g_sc[B_*N_];
__device__ float g_vg2[B_*N_];
__device__ float g_ab[B_*N_];
__device__ float g_dg[B_*N_];
__device__ float g_sumw[B_];
__device__ float g_c1[B_*N_];
__device__ float g_c2[B_*N_];
__device__ float g_Z[B_*NH_*N_];
__device__ float g_r1[B_*NH_*N_];
__device__ float g_r2[B_*NH_*N_];
__device__ float g_A1[B_*H_];
__device__ float g_A2[B_*H_];
__device__ float g_pm[B_*H_];

__device__ __forceinline__ bool d_pred(const int* P, int i){ return P[i]==1; }
__device__ __forceinline__ bool d_single(const int* P, int i){ return (i==0) || (i>=2 && P[i-2]==1); }
__device__ __forceinline__ float d_lrelu(float t){ return t >= 0.f ? t : 0.02f*t; }
__device__ __forceinline__ float tf32r(float x){ return wmma::__float_to_tf32(x); }
__device__ __forceinline__ float fex2(float x){ float y; asm("ex2.approx.f32 %0, %1;" : "=f"(y) : "f"(x)); return y; }

// ---------------- cp.async helpers ----------------
__device__ __forceinline__ void cpa16(float* s, const float* g){
  asm volatile("cp.async.cg.shared.global [%0], [%1], 16;\n"
               :: "r"((uint32_t)__cvta_generic_to_shared(s)), "l"(g));
}
__device__ __forceinline__ void cp_commit(){ asm volatile("cp.async.commit_group;\n"); }
__device__ __forceinline__ void cp_wait1(){ asm volatile("cp.async.wait_group 1;\n"); }
__device__ __forceinline__ void cp_wait0(){ asm volatile("cp.async.wait_group 0;\n"); }

// ---------------- m16n8k8 tf32 mma.sync ----------------
__device__ __forceinline__ void mma8(float c[4], const uint32_t a[4], uint32_t b0, uint32_t b1){
  asm volatile(
    "mma.sync.aligned.m16n8k8.row.col.f32.tf32.tf32.f32 "
    "{%0,%1,%2,%3}, {%4,%5,%6,%7}, {%8,%9}, {%0,%1,%2,%3};\n"
    : "+f"(c[0]), "+f"(c[1]), "+f"(c[2]), "+f"(c[3])
    : "r"(a[0]), "r"(a[1]), "r"(a[2]), "r"(a[3]), "r"(b0), "r"(b1));
}

// MMA micro-kernel on k-permuted smem (LDS.64 fragments).
template<int STRIDE, int NF, int K8>
__device__ __forceinline__ void mma_tile_p(const float* As, const float* Bs,
                                           float c[2][NF][4], int wr, int wc, int lane){
  #pragma unroll
  for (int k8=0;k8<K8;k8++){
    int ac = k8*8 + 2*(lane&3);
    uint32_t a[2][4];
    int ar = wr*32 + (lane>>2);
    #pragma unroll
    for (int rf=0; rf<2; rf++){
      const float* Ab = As + (ar + rf*16)*STRIDE + ac;
      float2 v0 = *(const float2*)(Ab);
      float2 v1 = *(const float2*)(Ab + 8*STRIDE);
      a[rf][0]=__float_as_uint(v0.x); a[rf][2]=__float_as_uint(v0.y);
      a[rf][1]=__float_as_uint(v1.x); a[rf][3]=__float_as_uint(v1.y);
    }
    #pragma unroll
    for (int nf=0;nf<NF;nf++){
      int br = wc*(NF*8) + nf*8 + (lane>>2);
      float2 bv = *(const float2*)(Bs + br*STRIDE + ac);
      mma8(c[0][nf], a[0], __float_as_uint(bv.x), __float_as_uint(bv.y));
      mma8(c[1][nf], a[1], __float_as_uint(bv.x), __float_as_uint(bv.y));
    }
  }
}

// ---------------- init ----------------
__global__ void k_init(const float* __restrict__ bsc){
  int i = blockIdx.x*blockDim.x + threadIdx.x;
  if (i < B_*N_){ g_vg2[i] = 0.f; g_sc[i] = bsc[0]; }
  if (i < B_*H_){ g_A1[i]=0.f; g_A2[i]=0.f; }
  if (i < B_*NH_*N_){ g_Z[i]=0.f; g_r1[i]=0.f; g_r2[i]=0.f; }
}

// ---------------- pre-round to tf32 + k-permute; W_q/W_k also n-row permuted ----------------
__global__ void k_preconv(const float* __restrict__ x,
                          const float* __restrict__ W0, const float* __restrict__ W1,
                          const float* __restrict__ W2, const float* __restrict__ W3,
                          const float* __restrict__ W4){
  const int XT4 = B_*N_*H_/4;
  const int WT4 = H_*H_/4;
  const int R4 = H_/4;  // 192 float4 per row
  int i = blockIdx.x*blockDim.x + threadIdx.x;
  if (i < XT4){
    float4 v = ((const float4*)x)[i];
    int g = 4*(i & ~1), b = i&1;
    g_xr[g + 0 + b] = tf32r(v.x);
    g_xr[g + 2 + b] = tf32r(v.y);
    g_xr[g + 4 + b] = tf32r(v.z);
    g_xr[g + 6 + b] = tf32r(v.w);
  } else {
    int j = i - XT4;
    if (j < 5*WT4){
      int w = j / WT4, o = j - w*WT4;
      const float* src = (w==0)?W0:(w==1)?W1:(w==2)?W2:(w==3)?W3:W4;
      float4 v = ((const float4*)src)[o];
      int od = o;
      if (w==2 || w==3){
        int row = o / R4, rem = o - row*R4;
        int r8 = row & 7;
        int drow = (row & ~7) | ((r8&3)*2 + (r8>>2));   // sigma^{-1}
        od = drow*R4 + rem;
      }
      float* dst = g_Wr + (size_t)w*H_*H_;
      int g = 4*(od & ~1), b = od&1;
      dst[g + 0 + b] = tf32r(v.x);
      dst[g + 2 + b] = tf32r(v.y);
      dst[g + 4 + b] = tf32r(v.z);
      dst[g + 6 + b] = tf32r(v.w);
    }
  }
}

// ---------------- mode-0 A staging: neighbor average (elementwise-safe on permuted x) ----------------
__device__ __forceinline__ void stage_avg(float* dst, int m0, int kc, const int* __restrict__ pp, int tid){
  #pragma unroll
  for (int i=0;i<4;i++){
    int lin = tid + i*256;
    int r = lin>>3, q = (lin&7)*4;
    int m = m0 + r, b = m>>10, n = m&(N_-1);
    bool single = (n==0) || (n>=2 && pp[b*N_+n-2]==1);
    int np = (n+1)&(N_-1), nm = (n+N_-1)&(N_-1);
    const float* base = g_xr + ((size_t)(b<<10))*H_ + kc + q;
    float4 xn = *(const float4*)(base + (size_t)np*H_);
    float4 v;
    if (single) v = xn;
    else {
      float4 xp = *(const float4*)(base + (size_t)nm*H_);
      v.x=0.5f*(xp.x+xn.x); v.y=0.5f*(xp.y+xn.y); v.z=0.5f*(xp.z+xn.z); v.w=0.5f*(xp.w+xn.w);
    }
    *(float4*)(dst + r*STP + q) = v;
  }
}

// ---------------- merged projections: z = 0:var(score) 1:sym(score) 2:Q 3:K 4:V ----------------
__global__ __launch_bounds__(256,2) void k_proj(
    const float* __restrict__ b_var, const float* __restrict__ b_sym,
    const float* __restrict__ b_q, const float* __restrict__ b_k, const float* __restrict__ b_v,
    const float* __restrict__ Wsc, const int* __restrict__ pp,
    float* __restrict__ Qb, float* __restrict__ Kb, float* __restrict__ Vb){
  extern __shared__ float sm[];
  float* Ab[2] = { sm,             sm + 128*STP };
  float* Bb[2] = { sm + 2*128*STP, sm + 3*128*STP };
  int mode = blockIdx.z;
  const float* W = g_Wr + (size_t)mode*H_*H_;
  const float* bias; float* C=nullptr; float alpha=1.f; const float* wsc=nullptr;
  switch(mode){
    case 0: bias=b_var; wsc=Wsc;    break;
    case 1: bias=b_sym; wsc=Wsc+H_; break;
    case 2: bias=b_q;   C=Qb; alpha=0.125f*LOG2E; break;
    case 3: bias=b_k;   C=Kb; break;
    default:bias=b_v;   C=Vb; break;
  }
  int tid=threadIdx.x, lane=tid&31, wid=tid>>5;
  int wr=wid&3, wc=wid>>2;
  int m0 = blockIdx.y*128, n0 = blockIdx.x*128;
  if (mode==0) stage_avg(Ab[0], m0, 0, pp, tid);
  else {
    #pragma unroll
    for (int i=0;i<4;i++){
      int lin=tid+i*256; int r=lin>>3, q=(lin&7)*4;
      cpa16(Ab[0]+r*STP+q, g_xr + (size_t)(m0+r)*H_ + q);
    }
  }
  #pragma unroll
  for (int i=0;i<4;i++){
    int lin=tid+i*256; int r=lin>>3, q=(lin&7)*4;
    cpa16(Bb[0]+r*STP+q, W + (size_t)(n0+r)*H_ + q);
  }
  cp_commit();
  float c[2][8][4];
  #pragma unroll
  for(int i=0;i<2;i++)
    #pragma unroll
    for(int j=0;j<8;j++){ c[i][j][0]=0;c[i][j][1]=0;c[i][j][2]=0;c[i][j][3]=0; }
  for (int kt=0; kt<NKT; kt++){
    int cur=kt&1, nxt=1-cur;
    if (kt+1<NKT){
      if (mode!=0){
        #pragma unroll
        for (int i=0;i<4;i++){
          int lin=tid+i*256; int r=lin>>3, q=(lin&7)*4;
          cpa16(Ab[nxt]+r*STP+q, g_xr + (size_t)(m0+r)*H_ + (kt+1)*KT + q);
        }
      }
      #pragma unroll
      for (int i=0;i<4;i++){
        int lin=tid+i*256; int r=lin>>3, q=(lin&7)*4;
        cpa16(Bb[nxt]+r*STP+q, W + (size_t)(n0+r)*H_ + (kt+1)*KT + q);
      }
      cp_commit();
      cp_wait1();
    } else cp_wait0();
    __syncthreads();
    mma_tile_p<STP,8,4>(Ab[cur], Bb[cur], c, wr, wc, lane);
    if (mode==0 && kt+1<NKT) stage_avg(Ab[nxt], m0, (kt+1)*KT, pp, tid);
    __syncthreads();
  }
  int t = lane&3;
  if (mode<=1){
    float p[4] = {0,0,0,0};
    #pragma unroll
    for (int rf=0; rf<2; rf++){
      #pragma unroll
      for (int nf=0; nf<8; nf++){
        int col0 = n0 + wc*64 + nf*8 + 2*t;
        float w0 = wsc[col0], w1 = wsc[col0+1];
        float b0v = bias[col0], b1v = bias[col0+1];
        p[rf*2+0] += tanhf(c[rf][nf][0]+b0v)*w0 + tanhf(c[rf][nf][1]+b1v)*w1;
        p[rf*2+1] += tanhf(c[rf][nf][2]+b0v)*w0 + tanhf(c[rf][nf][3]+b1v)*w1;
      }
    }
    #pragma unroll
    for (int i=0;i<4;i++){
      float v = p[i];
      v += __shfl_xor_sync(0xffffffffu, v, 1);
      v += __shfl_xor_sync(0xffffffffu, v, 2);
      if (t==0)
        atomicAdd(&g_sc[m0 + wr*32 + (i>>1)*16 + (lane>>2) + (i&1)*8], v);
    }
  } else if (mode==4){
    #pragma unroll
    for (int rf=0; rf<2; rf++){
      int row = m0 + wr*32 + rf*16 + (lane>>2);
      #pragma unroll
      for (int nf=0; nf<8; nf++){
        int col0 = n0 + wc*64 + nf*8 + 2*t;
        float2 bv = *(const float2*)(bias + col0);
        *(float2*)(C + (size_t)row*H_ + col0)     = make_float2(c[rf][nf][0]+bv.x, c[rf][nf][1]+bv.y);
        *(float2*)(C + (size_t)(row+8)*H_ + col0) = make_float2(c[rf][nf][2]+bv.x, c[rf][nf][3]+bv.y);
      }
    }
  } else {
    // Q/K: W rows were sigma-permuted, so mma col 2t ~ orig col t, 2t+1 ~ orig t+4;
    // permuted layout positions are exactly {2t, 2t+1} -> contiguous STG.64.
    #pragma unroll
    for (int rf=0; rf<2; rf++){
      int row = m0 + wr*32 + rf*16 + (lane>>2);
      #pragma unroll
      for (int nf=0; nf<8; nf++){
        int col = n0 + wc*64 + nf*8;
        float b0v = bias[col + t], b1v = bias[col + t + 4];
        *(float2*)(C + (size_t)row*H_ + col + 2*t) =
          make_float2(tf32r(alpha*(c[rf][nf][0]+b0v)), tf32r(alpha*(c[rf][nf][1]+b1v)));
        *(float2*)(C + (size_t)(row+8)*H_ + col + 2*t) =
          make_float2(tf32r(alpha*(c[rf][nf][2]+b0v)), tf32r(alpha*(c[rf][nf][3]+b1v)));
      }
    }
  }
}

// ---------------- attention pass 1: Zbase[bh][n] = sum_m exp2(S) (no band) ----------------
__global__ __launch_bounds__(256,2) void k_attn1(){
  extern __shared__ float sm[];
  float* Qs = sm;                                    // 128*ST resident (n rows)
  float* Kb2[2] = { sm + 128*ST, sm + 2*128*ST };
  int tid=threadIdx.x, lane=tid&31, wid=tid>>5;
  int wr=wid&3, wc=wid>>2;
  int bh=blockIdx.x, b=bh/NH_, h=bh-b*NH_;
  int n0=blockIdx.y*128;
  const float* Q = g_Qb + (size_t)b*N_*H_ + h*64;
  const float* K = g_Kb + (size_t)b*N_*H_ + h*64;
  #pragma unroll
  for (int it=0; it<8; it++){
    int lin = tid + it*256;
    int r = lin>>4, q = (lin&15)*4;
    cpa16(Qs + r*ST + q, Q + (size_t)(n0+r)*H_ + q);
  }
  #pragma unroll
  for (int it=0; it<8; it++){
    int lin = tid + it*256;
    int r = lin>>4, q = (lin&15)*4;
    cpa16(Kb2[0] + r*ST + q, K + (size_t)r*H_ + q);
  }
  cp_commit();
  float z[4]={0,0,0,0};
  for (int mt=0; mt<8; mt++){
    int cur=mt&1;
    if (mt+1<8){
      #pragma unroll
      for (int it=0; it<8; it++){
        int lin = tid + it*256;
        int r = lin>>4, q = (lin&15)*4;
        cpa16(Kb2[1-cur] + r*ST + q, K + (size_t)((mt+1)*128+r)*H_ + q);
      }
      cp_commit();
      cp_wait1();
    } else cp_wait0();
    __syncthreads();
    float c[2][8][4];
    #pragma unroll
    for(int i=0;i<2;i++)
      #pragma unroll
      for(int j=0;j<8;j++){ c[i][j][0]=0;c[i][j][1]=0;c[i][j][2]=0;c[i][j][3]=0; }
    mma_tile_p<ST,8,8>(Qs, Kb2[cur], c, wr, wc, lane);
    #pragma unroll
    for (int rf=0; rf<2; rf++)
      #pragma unroll
      for (int nf=0; nf<8; nf++){
        z[rf*2+0] += fex2(c[rf][nf][0]) + fex2(c[rf][nf][1]);
        z[rf*2+1] += fex2(c[rf][nf][2]) + fex2(c[rf][nf][3]);
      }
    __syncthreads();
  }
  #pragma unroll
  for (int i=0;i<4;i++){
    float v = z[i];
    v += __shfl_xor_sync(0xffffffffu, v, 1);
    v += __shfl_xor_sync(0xffffffffu, v, 2);
    if ((lane&3)==0)
      atomicAdd(&g_Z[(size_t)bh*N_ + n0 + wr*32 + (i>>1)*16 + (lane>>2) + (i&1)*8], v);
  }
}

// ---------------- cross scores -> VG^2 diagonal ----------------
__global__ __launch_bounds__(128) void k_cross(const float* __restrict__ x, const float* __restrict__ Wc,
                                               const float* __restrict__ bc, const int* __restrict__ occ){
  int pid = blockIdx.x;
  int b = pid / M_;
  int o0 = occ[pid*2], o1 = occ[pid*2+1];
  const float* x0 = x + ((size_t)b*N_+o0)*H_;
  const float* x1 = x + ((size_t)b*N_+o1)*H_;
  float p = 0.f;
  for (int h=threadIdx.x; h<H_; h+=128) p += 0.5f*(x0[h]+x1[h])*Wc[h];
  for (int o=16;o;o>>=1) p += __shfl_xor_sync(0xffffffffu, p, o);
  __shared__ float red[4];
  if ((threadIdx.x&31)==0) red[threadIdx.x>>5] = p;
  __syncthreads();
  if (threadIdx.x==0){
    float t = d_lrelu(bc[0] + red[0]+red[1]+red[2]+red[3]);
    atomicAdd(&g_vg2[b*N_+o0], t*t);
    atomicAdd(&g_vg2[b*N_+o1], t*t);
  }
}

// ---------------- band + sumw + coef, one block per batch ----------------
__global__ __launch_bounds__(1024) void k_post(const int* __restrict__ pp){
  __shared__ float ab[N_], wt[N_], red[32];
  __shared__ float swv;
  int b = blockIdx.x, n = threadIdx.x;
  const int* P = pp + b*N_;
  const float* s = g_sc + b*N_;
  float a = 0.f;
  if (n < N_-1){
    float sl1 = d_pred(P,n+1) ? d_lrelu(s[n+1]) : 0.f;
    bool up0 = d_pred(P,n) && (n<=1 || !d_single(P,n));
    float su0 = up0 ? d_lrelu(s[n]) : 0.f;
    a = sl1 + su0;
  }
  ab[n] = a; g_ab[b*N_+n] = a;
  bool up = d_pred(P,n) && (n<=1 || !d_single(P,n));
  bool tr = up && (n>=1);
  float w = d_pred(P,n) ? (tr?3.f:2.f) : 0.f;
  wt[n] = w;
  float v = w;
  for (int o=16;o;o>>=1) v += __shfl_xor_sync(0xffffffffu, v, o);
  if ((n&31)==0) red[n>>5] = v;
  __syncthreads();
  if (n < 32){
    float t2 = red[n];
    for (int o=16;o;o>>=1) t2 += __shfl_xor_sync(0xffffffffu, t2, o);
    if (n==0){ swv = t2; g_sumw[b] = t2; }
  }
  __syncthreads();
  float am1 = (n>=1) ? ab[n-1] : 0.f;
  g_dg[b*N_+n] = 0.8f*(am1*am1 + a*a) + g_vg2[b*N_+n];
  float sw = swv;
  int nm = (n+N_-1)&(N_-1), np = (n+1)&(N_-1);
  float c1 = wt[nm]*(d_single(P,nm)?1.f:0.5f) + wt[np]*(d_single(P,np)?0.f:0.5f);
  g_c1[b*N_+n] = c1 / sw;
  g_c2[b*N_+n] = wt[n] / sw;
}

// ---------------- band correction for Z: one warp per (bh, n) ----------------
__global__ __launch_bounds__(256) void k_bandfix(){
  int bh = blockIdx.x, b = bh/NH_, h = bh - b*NH_;
  int wid = threadIdx.x>>5, lane = threadIdx.x&31;
  int n = blockIdx.y*8 + wid;
  const float* Qr = g_Qb + ((size_t)b*N_ + n)*H_ + h*64;
  const float* Kp = g_Kb + (size_t)b*N_*H_ + h*64;
  const float* ab = g_ab + b*N_;
  float q0 = Qr[lane], q1 = Qr[lane+32];
  float anm2=(n>=2)?ab[n-2]:0.f, anm1=(n>=1)?ab[n-1]:0.f;
  float an=ab[n], anp1=(n<N_-1)?ab[n+1]:0.f;
  float biasv[5] = { 0.8f*anm2*anm1, 0.2f*anm1, g_dg[b*N_+n], 0.2f*an, 0.8f*an*anp1 };
  float dz = 0.f;
  #pragma unroll
  for (int d=-2; d<=2; d++){
    int m = n + d;
    if ((unsigned)m < (unsigned)N_){
      const float* Kr = Kp + (size_t)m*H_;
      float s = q0*Kr[lane] + q1*Kr[lane+32];
      #pragma unroll
      for (int o=16;o;o>>=1) s += __shfl_xor_sync(0xffffffffu, s, o);
      dz += fex2(s + LOG2E*biasv[d+2]) - fex2(s);
    }
  }
  if (lane==0) atomicAdd(&g_Z[(size_t)bh*N_ + n], dz);
}

// ---------------- attention pass 2: r[m] = sum_n (c[n]/Z[n])*exp2(S+bias) ----------------
__global__ __launch_bounds__(256,2) void k_attn2(){
  extern __shared__ float sm[];
  float* Ks = sm;                                    // 128*ST resident (m rows)
  float* Qb2[2] = { sm + 128*ST, sm + 2*128*ST };
  float* colp = sm + 3*128*ST;                       // 7*128
  int tid=threadIdx.x, lane=tid&31, wid=tid>>5;
  int wr=wid&3, wc=wid>>2;
  int bh=blockIdx.x, b=bh/NH_, h=bh-b*NH_;
  int m0=blockIdx.y*128;
  const float* Q = g_Qb + (size_t)b*N_*H_ + h*64;
  const float* K = g_Kb + (size_t)b*N_*H_ + h*64;
  #pragma unroll
  for (int it=0; it<8; it++){
    int lin = tid + it*256;
    int r = lin>>4, q = (lin&15)*4;
    cpa16(Ks + r*ST + q, K + (size_t)(m0+r)*H_ + q);
  }
  #pragma unroll
  for (int it=0; it<8; it++){
    int lin = tid + it*256;
    int r = lin>>4, q = (lin&15)*4;
    cpa16(Qb2[0] + r*ST + q, Q + (size_t)r*H_ + q);
  }
  cp_commit();
  float r1[4]={0,0,0,0}, r2[4]={0,0,0,0};
  for (int nt=0; nt<8; nt++){
    int cur=nt&1;
    if (nt+1<8){
      #pragma unroll
      for (int it=0; it<8; it++){
        int lin = tid + it*256;
        int r = lin>>4, q = (lin&15)*4;
        cpa16(Qb2[1-cur] + r*ST + q, Q + (size_t)((nt+1)*128+r)*H_ + q);
      }
      cp_commit();
    }
    if (tid < 128){
      int n = nt*128 + tid;
      const float* ab = g_ab + b*N_;
      float anm2=(n>=2)?ab[n-2]:0.f, anm1=(n>=1)?ab[n-1]:0.f;
      float an=ab[n], anp1=(n<N_-1)?ab[n+1]:0.f;
      colp[0*128+tid]=LOG2E*0.8f*anm2*anm1;
      colp[1*128+tid]=LOG2E*0.2f*anm1;
      colp[2*128+tid]=LOG2E*g_dg[b*N_+n];
      colp[3*128+tid]=LOG2E*0.2f*an;
      colp[4*128+tid]=LOG2E*0.8f*an*anp1;
      float iz = 1.f / g_Z[(size_t)bh*N_ + n];
      colp[5*128+tid]=g_c1[b*N_+n]*iz;
      colp[6*128+tid]=g_c2[b*N_+n]*iz;
    }
    if (nt+1<8) cp_wait1(); else cp_wait0();
    __syncthreads();
    float c[2][8][4];
    #pragma unroll
    for(int i=0;i<2;i++)
      #pragma unroll
      for(int j=0;j<8;j++){ c[i][j][0]=0;c[i][j][1]=0;c[i][j][2]=0;c[i][j][3]=0; }
    mma_tile_p<ST,8,8>(Ks, Qb2[cur], c, wr, wc, lane);
    bool band = (nt*128 + 127 >= m0 - 2) && (nt*128 <= m0 + 129);
    #pragma unroll
    for (int rf=0; rf<2; rf++){
      int mr0 = m0 + wr*32 + rf*16 + (lane>>2);
      #pragma unroll
      for (int nf=0; nf<8; nf++){
        int lc0 = wc*64 + nf*8 + 2*(lane&3);
        float w1a = colp[5*128+lc0], w1b = colp[5*128+lc0+1];
        float w2a = colp[6*128+lc0], w2b = colp[6*128+lc0+1];
        if (band){
          #pragma unroll
          for (int e=0; e<4; e++){
            int hi = e>>1;
            int lc = lc0 + (e&1);
            int d = (mr0 + hi*8) - (nt*128 + lc);
            float bias = ((unsigned)(d+2) < 5u) ? colp[(d+2)*128 + lc] : 0.f;
            float P = fex2(c[rf][nf][e] + bias);
            r1[rf*2+hi] += ((e&1)? w1b : w1a) * P;
            r2[rf*2+hi] += ((e&1)? w2b : w2a) * P;
          }
        } else {
          float P0 = fex2(c[rf][nf][0]), P1 = fex2(c[rf][nf][1]);
          float P2 = fex2(c[rf][nf][2]), P3 = fex2(c[rf][nf][3]);
          r1[rf*2+0] += w1a*P0 + w1b*P1;  r2[rf*2+0] += w2a*P0 + w2b*P1;
          r1[rf*2+1] += w1a*P2 + w1b*P3;  r2[rf*2+1] += w2a*P2 + w2b*P3;
        }
      }
    }
    __syncthreads();
  }
  #pragma unroll
  for (int i=0;i<4;i++){
    float v1 = r1[i], v2 = r2[i];
    v1 += __shfl_xor_sync(0xffffffffu, v1, 1);
    v1 += __shfl_xor_sync(0xffffffffu, v1, 2);
    v2 += __shfl_xor_sync(0xffffffffu, v2, 1);
    v2 += __shfl_xor_sync(0xffffffffu, v2, 2);
    if ((lane&3)==0){
      size_t o = (size_t)bh*N_ + m0 + wr*32 + (i>>1)*16 + (lane>>2) + (i&1)*8;
      atomicAdd(&g_r1[o], v1);
      atomicAdd(&g_r2[o], v2);
    }
  }
}

// ---------------- A = r @ V ----------------
__global__ __launch_bounds__(768) void k_matvec(){
  int b = blockIdx.x, f = threadIdx.x, h = f >> 6;
  int m0 = blockIdx.y*64;
  const float* r1 = g_r1 + ((size_t)b*NH_+h)*N_;
  const float* r2 = g_r2 + ((size_t)b*NH_+h)*N_;
  float a1=0.f, a2=0.f;
  for (int m=m0; m<m0+64; m++){
    float vv = g_Vb[((size_t)b*N_+m)*H_+f];
    a1 += r1[m]*vv; a2 += r2[m]*vv;
  }
  atomicAdd(&g_A1[b*H_+f], a1);
  atomicAdd(&g_A2[b*H_+f], a2);
}

// ---------------- final projections + broadcast ----------------
__global__ __launch_bounds__(768) void k_final(const float* __restrict__ Wo, const float* __restrict__ bo,
                                               const float* __restrict__ Wa, const float* __restrict__ ba){
  int b = blockIdx.x, o = threadIdx.x;
  __shared__ float u1s[H_], u2s[H_];
  const float* w = Wo + (size_t)o*H_;
  const float* A1 = g_A1 + b*H_;
  const float* A2 = g_A2 + b*H_;
  float u1 = bo[o], u2 = bo[o];
  for (int i=0;i<H_;i++){ u1 += w[i]*A1[i]; u2 += w[i]*A2[i]; }
  u1s[o] = u1; u2s[o] = u2;
  __syncthreads();
  const float* wa = Wa + (size_t)o*2*H_;
  float p = ba[o];
  for (int i=0;i<H_;i++) p += wa[i]*u1s[i] + wa[H_+i]*u2s[i];
  g_pm[b*H_+o] = p;
}

__global__ void k_bcast(float* __restrict__ out){
  int idx = blockIdx.x*blockDim.x + threadIdx.x;
  if (idx >= B_*N_*H_) return;
  int f = idx % H_;
  int b = idx / (N_*H_);
  out[idx] = g_pm[b*H_+f];
}

// ---------------- launch ----------------
extern "C" void kernel_launch(void* const* d_in, const int* in_sizes, int n_in,
                              void* d_out, int out_size){
  (void)in_sizes; (void)n_in; (void)out_size;
  const float* x      = (const float*)d_in[0];
  const float* W_var  = (const float*)d_in[3];
  const float* b_var  = (const float*)d_in[4];
  const float* W_sym  = (const float*)d_in[5];
  const float* b_sym  = (const float*)d_in[6];
  const float* W_sc   = (const float*)d_in[7];
  const float* b_scb  = (const float*)d_in[8];
  const float* W_cr   = (const float*)d_in[9];
  const float* b_cr   = (const float*)d_in[10];
  const float* W_atom = (const float*)d_in[11];
  const float* b_atom = (const float*)d_in[12];
  const float* W_q    = (const float*)d_in[13];
  const float* b_q    = (const float*)d_in[14];
  const float* W_k    = (const float*)d_in[15];
  const float* b_k    = (const float*)d_in[16];
  const float* W_v    = (const float*)d_in[17];
  const float* b_v    = (const float*)d_in[18];
  const float* W_o    = (const float*)d_in[19];
  const float* b_o    = (const float*)d_in[20];
  const int*   pp     = (const int*)d_in[21];
  const int*   occ    = (const int*)d_in[24];
  float* out = (float*)d_out;

  float *p_Q, *p_K, *p_V;
  cudaGetSymbolAddress((void**)&p_Q, g_Qb);
  cudaGetSymbolAddress((void**)&p_K, g_Kb);
  cudaGetSymbolAddress((void**)&p_V, g_Vb);

  const int PROJ_SMEM  = (4*128*STP)*4;
  const int ATTN1_SMEM = (3*128*ST)*4;
  const int ATTN2_SMEM = (3*128*ST + 7*128)*4;
  static bool attr_done = false;
  if (!attr_done){
    cudaFuncSetAttribute(k_proj,  cudaFuncAttributeMaxDynamicSharedMemorySize, PROJ_SMEM);
    cudaFuncSetAttribute(k_attn1, cudaFuncAttributeMaxDynamicSharedMemorySize, ATTN1_SMEM);
    cudaFuncSetAttribute(k_attn2, cudaFuncAttributeMaxDynamicSharedMemorySize, ATTN2_SMEM);
    attr_done = true;
  }

  // launch order chosen so ncu's capture slot (#4) lands on k_attn1
  k_init<<<(B_*NH_*N_+255)/256, 256>>>(b_scb);                                   // 1
  const int PRE4 = B_*N_*H_/4 + 5*H_*H_/4;
  k_preconv<<<(PRE4+255)/256, 256>>>(x, W_var, W_sym, W_q, W_k, W_v);            // 2
  dim3 gp(H_/128, (B_*N_)/128, 5);
  k_proj<<<gp, 256, PROJ_SMEM>>>(b_var, b_sym, b_q, b_k, b_v, W_sc, pp, p_Q, p_K, p_V); // 3
  dim3 ga(B_*NH_, N_/128);
  k_attn1<<<ga, 256, ATTN1_SMEM>>>();                                            // 4 <- profiled
  k_cross<<<B_*M_, 128>>>(x, W_cr, b_cr, occ);                                   // 5
  k_post<<<B_, 1024>>>(pp);                                                      // 6
  dim3 gbf(B_*NH_, N_/8);
  k_bandfix<<<gbf, 256>>>();                                                     // 7
  k_attn2<<<ga, 256, ATTN2_SMEM>>>();                                            // 8
  dim3 gmv(B_, 16);
  k_matvec<<<gmv, 768>>>();
  k_final<<<B_, 768>>>(W_o, b_o, W_atom, b_atom);
  k_bcast<<<(B_*N_*H_+255)/256, 256>>>(out);
}

// round 11
// speedup vs baseline: 1.0547x; 1.0495x over previous
#include <cuda_runtime.h>
#include <mma.h>
#include <cstdint>
using namespace nvcuda;

#define B_ 8
#define N_ 1024
#define H_ 768
#define NH_ 12
#define M_ 256
#define ST 72    // attn smem row stride
#define STP 40   // proj smem row stride (k-tile 32 + pad 8)
#define KT 32
#define NKT 24
#define LOG2E 1.4426950408889634f

// ---------------- scratch ----------------
__device__ float g_xr[B_*N_*H_];       // tf32-rounded, k-permuted x
__device__ float g_vi[B_*N_*H_];       // tf32-rounded, k-permuted var_in
__device__ float g_Wr[5*H_*H_];        // tf32-rounded, k-permuted W (q/k also n-permuted)
__device__ float g_Qb[B_*N_*H_];       // k-permuted, pre-scaled by 0.125*log2e
__device__ float g_Kb[B_*N_*H_];       // k-permuted
__device__ float g_Vb[B_*N_*H_];       // linear
__device__ float g_sc[B_*N_];
__device__ float g_vg2[B_*N_];
__device__ float g_ab[B_*N_];
__device__ float g_dg[B_*N_];
__device__ float g_sumw[B_];
__device__ float g_c1[B_*N_];
__device__ float g_c2[B_*N_];
__device__ float g_Z[B_*NH_*N_];
__device__ float g_r1[B_*NH_*N_];
__device__ float g_r2[B_*NH_*N_];
__device__ float g_A1[B_*H_];
__device__ float g_A2[B_*H_];
__device__ float g_pm[B_*H_];

__device__ __forceinline__ bool d_pred(const int* P, int i){ return P[i]==1; }
__device__ __forceinline__ bool d_single(const int* P, int i){ return (i==0) || (i>=2 && P[i-2]==1); }
__device__ __forceinline__ float d_lrelu(float t){ return t >= 0.f ? t : 0.02f*t; }
__device__ __forceinline__ float tf32r(float x){ return wmma::__float_to_tf32(x); }
__device__ __forceinline__ float fex2(float x){ float y; asm("ex2.approx.f32 %0, %1;" : "=f"(y) : "f"(x)); return y; }

// permute-store one 8-float k-group: out = [i0 i4 i1 i5 i2 i6 i3 i7], tf32-rounded
__device__ __forceinline__ void perm_store(float* dst, float4 a, float4 b){
  float4 o0 = make_float4(tf32r(a.x), tf32r(b.x), tf32r(a.y), tf32r(b.y));
  float4 o1 = make_float4(tf32r(a.z), tf32r(b.z), tf32r(a.w), tf32r(b.w));
  *(float4*)dst = o0; *(float4*)(dst+4) = o1;
}

// ---------------- cp.async helpers ----------------
__device__ __forceinline__ void cpa16(float* s, const float* g){
  asm volatile("cp.async.cg.shared.global [%0], [%1], 16;\n"
               :: "r"((uint32_t)__cvta_generic_to_shared(s)), "l"(g));
}
__device__ __forceinline__ void cp_commit(){ asm volatile("cp.async.commit_group;\n"); }
__device__ __forceinline__ void cp_wait0(){ asm volatile("cp.async.wait_group 0;\n"); }

// ---------------- m16n8k8 tf32 mma.sync ----------------
__device__ __forceinline__ void mma8(float c[4], const uint32_t a[4], uint32_t b0, uint32_t b1){
  asm volatile(
    "mma.sync.aligned.m16n8k8.row.col.f32.tf32.tf32.f32 "
    "{%0,%1,%2,%3}, {%4,%5,%6,%7}, {%8,%9}, {%0,%1,%2,%3};\n"
    : "+f"(c[0]), "+f"(c[1]), "+f"(c[2]), "+f"(c[3])
    : "r"(a[0]), "r"(a[1]), "r"(a[2]), "r"(a[3]), "r"(b0), "r"(b1));
}

template<int STRIDE, int NF, int K8>
__device__ __forceinline__ void mma_tile_p(const float* As, const float* Bs,
                                           float c[2][NF][4], int wr, int wc, int lane){
  #pragma unroll
  for (int k8=0;k8<K8;k8++){
    int ac = k8*8 + 2*(lane&3);
    uint32_t a[2][4];
    int ar = wr*32 + (lane>>2);
    #pragma unroll
    for (int rf=0; rf<2; rf++){
      const float* Ab = As + (ar + rf*16)*STRIDE + ac;
      float2 v0 = *(const float2*)(Ab);
      float2 v1 = *(const float2*)(Ab + 8*STRIDE);
      a[rf][0]=__float_as_uint(v0.x); a[rf][2]=__float_as_uint(v0.y);
      a[rf][1]=__float_as_uint(v1.x); a[rf][3]=__float_as_uint(v1.y);
    }
    #pragma unroll
    for (int nf=0;nf<NF;nf++){
      int br = wc*(NF*8) + nf*8 + (lane>>2);
      float2 bv = *(const float2*)(Bs + br*STRIDE + ac);
      mma8(c[0][nf], a[0], __float_as_uint(bv.x), __float_as_uint(bv.y));
      mma8(c[1][nf], a[1], __float_as_uint(bv.x), __float_as_uint(bv.y));
    }
  }
}

// ---------------- init ----------------
__global__ void k_init(const float* __restrict__ bsc){
  int i = blockIdx.x*blockDim.x + threadIdx.x;
  if (i < B_*N_){ g_vg2[i] = 0.f; g_sc[i] = bsc[0]; }
  if (i < B_*H_){ g_A1[i]=0.f; g_A2[i]=0.f; }
  if (i < B_*NH_*N_){ g_Z[i]=0.f; g_r1[i]=0.f; g_r2[i]=0.f; }
}

// ---------------- preconv: x, var_in, weights -> tf32, k-permuted (vectorized) ----------------
__global__ void k_preconv(const float* __restrict__ x, const int* __restrict__ pp,
                          const float* __restrict__ W0, const float* __restrict__ W1,
                          const float* __restrict__ W2, const float* __restrict__ W3,
                          const float* __restrict__ W4){
  const int XT8 = B_*N_*H_/8;
  const int WT8 = H_*H_/8;
  const int H8 = H_/8;
  int i = blockIdx.x*blockDim.x + threadIdx.x;
  if (i < XT8){
    const float4* s = (const float4*)x + (size_t)i*2;
    perm_store(g_xr + (size_t)i*8, s[0], s[1]);
  } else if (i < 2*XT8){
    int j = i - XT8;
    int hh8 = j % H8;
    int nn  = (j / H8) % N_;
    int b   = j / (N_*H8);
    bool single = (nn==0) || (nn>=2 && pp[b*N_+nn-2]==1);
    int np = (nn+1)&(N_-1), nm = (nn+N_-1)&(N_-1);
    const float* bp = x + ((size_t)b*N_ + np)*H_ + hh8*8;
    float4 xa = *(const float4*)bp, xb = *(const float4*)(bp+4);
    if (!single){
      const float* bm = x + ((size_t)b*N_ + nm)*H_ + hh8*8;
      float4 ya = *(const float4*)bm, yb = *(const float4*)(bm+4);
      xa.x=0.5f*(xa.x+ya.x); xa.y=0.5f*(xa.y+ya.y); xa.z=0.5f*(xa.z+ya.z); xa.w=0.5f*(xa.w+ya.w);
      xb.x=0.5f*(xb.x+yb.x); xb.y=0.5f*(xb.y+yb.y); xb.z=0.5f*(xb.z+yb.z); xb.w=0.5f*(xb.w+yb.w);
    }
    perm_store(g_vi + (size_t)j*8, xa, xb);
  } else {
    int j = i - 2*XT8;
    if (j < 5*WT8){
      int w = j / WT8, o = j - w*WT8;
      int row = o / H8, rem = o - row*H8;
      int srow = row;
      if (w==2 || w==3){
        int r8 = row & 7;
        srow = (row & ~7) | ((r8&1)*4 + (r8>>1));   // inverse sigma
      }
      const float* src = (w==0)?W0:(w==1)?W1:(w==2)?W2:(w==3)?W3:W4;
      const float4* s = (const float4*)(src + (size_t)srow*H_ + rem*8);
      perm_store(g_Wr + (size_t)w*H_*H_ + (size_t)o*8, s[0], s[1]);
    }
  }
}

// ---------------- merged projections ----------------
__global__ __launch_bounds__(256,2) void k_proj(
    const float* __restrict__ b_var, const float* __restrict__ b_sym,
    const float* __restrict__ b_q, const float* __restrict__ b_k, const float* __restrict__ b_v,
    const float* __restrict__ Wsc,
    float* __restrict__ Qb, float* __restrict__ Kb, float* __restrict__ Vb){
  extern __shared__ float sm[];
  float* Ab[2] = { sm,             sm + 128*STP };
  float* Bb[2] = { sm + 2*128*STP, sm + 3*128*STP };
  int mode = blockIdx.z;
  const float* A = (mode==0) ? g_vi : g_xr;
  const float* W = g_Wr + (size_t)mode*H_*H_;
  const float* bias; float* C=nullptr; float alpha=1.f; const float* wsc=nullptr;
  switch(mode){
    case 0: bias=b_var; wsc=Wsc;    break;
    case 1: bias=b_sym; wsc=Wsc+H_; break;
    case 2: bias=b_q;   C=Qb; alpha=0.125f*LOG2E; break;
    case 3: bias=b_k;   C=Kb; break;
    default:bias=b_v;   C=Vb; break;
  }
  int tid=threadIdx.x, lane=tid&31, wid=tid>>5;
  int wr=wid&3, wc=wid>>2;
  int m0 = blockIdx.y*128, n0 = blockIdx.x*128;
  #pragma unroll
  for (int i=0;i<4;i++){
    int lin=tid+i*256; int r=lin>>3, q=(lin&7)*4;
    cpa16(Ab[0]+r*STP+q, A + (size_t)(m0+r)*H_ + q);
    cpa16(Bb[0]+r*STP+q, W + (size_t)(n0+r)*H_ + q);
  }
  cp_commit();
  float c[2][8][4];
  #pragma unroll
  for(int i=0;i<2;i++)
    #pragma unroll
    for(int j=0;j<8;j++){ c[i][j][0]=0;c[i][j][1]=0;c[i][j][2]=0;c[i][j][3]=0; }
  for (int kt=0; kt<NKT; kt++){
    int cur=kt&1;
    cp_wait0();
    __syncthreads();
    if (kt+1<NKT){
      #pragma unroll
      for (int i=0;i<4;i++){
        int lin=tid+i*256; int r=lin>>3, q=(lin&7)*4;
        cpa16(Ab[1-cur]+r*STP+q, A + (size_t)(m0+r)*H_ + (kt+1)*KT + q);
        cpa16(Bb[1-cur]+r*STP+q, W + (size_t)(n0+r)*H_ + (kt+1)*KT + q);
      }
      cp_commit();
    }
    mma_tile_p<STP,8,4>(Ab[cur], Bb[cur], c, wr, wc, lane);
  }
  int t = lane&3;
  if (mode<=1){
    float p[4] = {0,0,0,0};
    #pragma unroll
    for (int rf=0; rf<2; rf++){
      #pragma unroll
      for (int nf=0; nf<8; nf++){
        int col0 = n0 + wc*64 + nf*8 + 2*t;
        float w0 = wsc[col0], w1 = wsc[col0+1];
        float b0v = bias[col0], b1v = bias[col0+1];
        p[rf*2+0] += tanhf(c[rf][nf][0]+b0v)*w0 + tanhf(c[rf][nf][1]+b1v)*w1;
        p[rf*2+1] += tanhf(c[rf][nf][2]+b0v)*w0 + tanhf(c[rf][nf][3]+b1v)*w1;
      }
    }
    #pragma unroll
    for (int i=0;i<4;i++){
      float v = p[i];
      v += __shfl_xor_sync(0xffffffffu, v, 1);
      v += __shfl_xor_sync(0xffffffffu, v, 2);
      if (t==0)
        atomicAdd(&g_sc[m0 + wr*32 + (i>>1)*16 + (lane>>2) + (i&1)*8], v);
    }
  } else if (mode==4){
    #pragma unroll
    for (int rf=0; rf<2; rf++){
      int row = m0 + wr*32 + rf*16 + (lane>>2);
      #pragma unroll
      for (int nf=0; nf<8; nf++){
        int col0 = n0 + wc*64 + nf*8 + 2*t;
        float2 bv = *(const float2*)(bias + col0);
        *(float2*)(C + (size_t)row*H_ + col0)     = make_float2(c[rf][nf][0]+bv.x, c[rf][nf][1]+bv.y);
        *(float2*)(C + (size_t)(row+8)*H_ + col0) = make_float2(c[rf][nf][2]+bv.x, c[rf][nf][3]+bv.y);
      }
    }
  } else {
    #pragma unroll
    for (int rf=0; rf<2; rf++){
      int row = m0 + wr*32 + rf*16 + (lane>>2);
      #pragma unroll
      for (int nf=0; nf<8; nf++){
        int col = n0 + wc*64 + nf*8;
        float b0v = bias[col + t], b1v = bias[col + t + 4];
        *(float2*)(C + (size_t)row*H_ + col + 2*t) =
          make_float2(tf32r(alpha*(c[rf][nf][0]+b0v)), tf32r(alpha*(c[rf][nf][1]+b1v)));
        *(float2*)(C + (size_t)(row+8)*H_ + col + 2*t) =
          make_float2(tf32r(alpha*(c[rf][nf][2]+b0v)), tf32r(alpha*(c[rf][nf][3]+b1v)));
      }
    }
  }
}

// ---------------- attention pass 1: Zbase[bh][n] = sum_m exp2(S) ----------------
__global__ __launch_bounds__(256,2) void k_attn1(){
  extern __shared__ float sm[];
  float* Qs = sm;
  float* Kb2[2] = { sm + 128*ST, sm + 2*128*ST };
  int tid=threadIdx.x, lane=tid&31, wid=tid>>5;
  int wr=wid&3, wc=wid>>2;
  int bh=blockIdx.x, b=bh/NH_, h=bh-b*NH_;
  int n0=blockIdx.y*128;
  const float* Q = g_Qb + (size_t)b*N_*H_ + h*64;
  const float* K = g_Kb + (size_t)b*N_*H_ + h*64;
  #pragma unroll
  for (int it=0; it<8; it++){
    int lin = tid + it*256;
    int r = lin>>4, q = (lin&15)*4;
    cpa16(Qs + r*ST + q, Q + (size_t)(n0+r)*H_ + q);
    cpa16(Kb2[0] + r*ST + q, K + (size_t)r*H_ + q);
  }
  cp_commit();
  float z[4]={0,0,0,0};
  for (int mt=0; mt<8; mt++){
    int cur=mt&1;
    cp_wait0();
    __syncthreads();
    if (mt+1<8){
      #pragma unroll
      for (int it=0; it<8; it++){
        int lin = tid + it*256;
        int r = lin>>4, q = (lin&15)*4;
        cpa16(Kb2[1-cur] + r*ST + q, K + (size_t)((mt+1)*128+r)*H_ + q);
      }
      cp_commit();
    }
    float c[2][8][4];
    #pragma unroll
    for(int i=0;i<2;i++)
      #pragma unroll
      for(int j=0;j<8;j++){ c[i][j][0]=0;c[i][j][1]=0;c[i][j][2]=0;c[i][j][3]=0; }
    mma_tile_p<ST,8,8>(Qs, Kb2[cur], c, wr, wc, lane);
    #pragma unroll
    for (int rf=0; rf<2; rf++)
      #pragma unroll
      for (int nf=0; nf<8; nf++){
        z[rf*2+0] += fex2(c[rf][nf][0]) + fex2(c[rf][nf][1]);
        z[rf*2+1] += fex2(c[rf][nf][2]) + fex2(c[rf][nf][3]);
      }
  }
  #pragma unroll
  for (int i=0;i<4;i++){
    float v = z[i];
    v += __shfl_xor_sync(0xffffffffu, v, 1);
    v += __shfl_xor_sync(0xffffffffu, v, 2);
    if ((lane&3)==0)
      atomicAdd(&g_Z[(size_t)bh*N_ + n0 + wr*32 + (i>>1)*16 + (lane>>2) + (i&1)*8], v);
  }
}

// ---------------- cross scores -> VG^2 diagonal ----------------
__global__ __launch_bounds__(128) void k_cross(const float* __restrict__ x, const float* __restrict__ Wc,
                                               const float* __restrict__ bc, const int* __restrict__ occ){
  int pid = blockIdx.x;
  int b = pid / M_;
  int o0 = occ[pid*2], o1 = occ[pid*2+1];
  const float* x0 = x + ((size_t)b*N_+o0)*H_;
  const float* x1 = x + ((size_t)b*N_+o1)*H_;
  float p = 0.f;
  for (int h=threadIdx.x; h<H_; h+=128) p += 0.5f*(x0[h]+x1[h])*Wc[h];
  for (int o=16;o;o>>=1) p += __shfl_xor_sync(0xffffffffu, p, o);
  __shared__ float red[4];
  if ((threadIdx.x&31)==0) red[threadIdx.x>>5] = p;
  __syncthreads();
  if (threadIdx.x==0){
    float t = d_lrelu(bc[0] + red[0]+red[1]+red[2]+red[3]);
    atomicAdd(&g_vg2[b*N_+o0], t*t);
    atomicAdd(&g_vg2[b*N_+o1], t*t);
  }
}

// ---------------- band + sumw + coef ----------------
__global__ __launch_bounds__(1024) void k_post(const int* __restrict__ pp){
  __shared__ float ab[N_], wt[N_], red[32];
  __shared__ float swv;
  int b = blockIdx.x, n = threadIdx.x;
  const int* P = pp + b*N_;
  const float* s = g_sc + b*N_;
  float a = 0.f;
  if (n < N_-1){
    float sl1 = d_pred(P,n+1) ? d_lrelu(s[n+1]) : 0.f;
    bool up0 = d_pred(P,n) && (n<=1 || !d_single(P,n));
    float su0 = up0 ? d_lrelu(s[n]) : 0.f;
    a = sl1 + su0;
  }
  ab[n] = a; g_ab[b*N_+n] = a;
  bool up = d_pred(P,n) && (n<=1 || !d_single(P,n));
  bool tr = up && (n>=1);
  float w = d_pred(P,n) ? (tr?3.f:2.f) : 0.f;
  wt[n] = w;
  float v = w;
  for (int o=16;o;o>>=1) v += __shfl_xor_sync(0xffffffffu, v, o);
  if ((n&31)==0) red[n>>5] = v;
  __syncthreads();
  if (n < 32){
    float t2 = red[n];
    for (int o=16;o;o>>=1) t2 += __shfl_xor_sync(0xffffffffu, t2, o);
    if (n==0){ swv = t2; g_sumw[b] = t2; }
  }
  __syncthreads();
  float am1 = (n>=1) ? ab[n-1] : 0.f;
  g_dg[b*N_+n] = 0.8f*(am1*am1 + a*a) + g_vg2[b*N_+n];
  float sw = swv;
  int nm = (n+N_-1)&(N_-1), np = (n+1)&(N_-1);
  float c1 = wt[nm]*(d_single(P,nm)?1.f:0.5f) + wt[np]*(d_single(P,np)?0.f:0.5f);
  g_c1[b*N_+n] = c1 / sw;
  g_c2[b*N_+n] = wt[n] / sw;
}

// ---------------- band correction: fix Z and emit r1/r2 band deltas ----------------
__global__ __launch_bounds__(256) void k_bandfix(){
  int bh = blockIdx.x, b = bh/NH_, h = bh - b*NH_;
  int wid = threadIdx.x>>5, lane = threadIdx.x&31;
  int n = blockIdx.y*8 + wid;
  const float* Qr = g_Qb + ((size_t)b*N_ + n)*H_ + h*64;
  const float* Kp = g_Kb + (size_t)b*N_*H_ + h*64;
  const float* ab = g_ab + b*N_;
  float q0 = Qr[lane], q1 = Qr[lane+32];
  float anm2=(n>=2)?ab[n-2]:0.f, anm1=(n>=1)?ab[n-1]:0.f;
  float an=ab[n], anp1=(n<N_-1)?ab[n+1]:0.f;
  float biasv[5] = { LOG2E*0.8f*anm2*anm1, LOG2E*0.2f*anm1, LOG2E*g_dg[b*N_+n],
                     LOG2E*0.2f*an, LOG2E*0.8f*an*anp1 };
  float delta[5];
  float dz = 0.f;
  #pragma unroll
  for (int d=-2; d<=2; d++){
    int m = n + d;
    delta[d+2] = 0.f;
    if ((unsigned)m < (unsigned)N_){
      const float* Kr = Kp + (size_t)m*H_;
      float s = q0*Kr[lane] + q1*Kr[lane+32];
      #pragma unroll
      for (int o=16;o;o>>=1) s += __shfl_xor_sync(0xffffffffu, s, o);
      delta[d+2] = fex2(s + biasv[d+2]) - fex2(s);
      dz += delta[d+2];
    }
  }
  float Zf = g_Z[(size_t)bh*N_ + n] + dz;
  if (lane==0) g_Z[(size_t)bh*N_ + n] = Zf;
  float w1 = g_c1[b*N_+n] / Zf;
  float w2 = g_c2[b*N_+n] / Zf;
  if (lane==0 && (w1 != 0.f || w2 != 0.f)){
    #pragma unroll
    for (int d=-2; d<=2; d++){
      int m = n + d;
      if ((unsigned)m < (unsigned)N_ && delta[d+2] != 0.f){
        atomicAdd(&g_r1[(size_t)bh*N_ + m], w1*delta[d+2]);
        atomicAdd(&g_r2[(size_t)bh*N_ + m], w2*delta[d+2]);
      }
    }
  }
}

// ---------------- attention pass 2: r[m] += sum_n (c[n]/Z[n])*exp2(S) (band handled in bandfix) ----------------
__global__ __launch_bounds__(256,2) void k_attn2(){
  extern __shared__ float sm[];
  float* Ks = sm;                                    // resident K rows (m)
  float* Qb2[2] = { sm + 128*ST, sm + 2*128*ST };
  float* colp = sm + 3*128*ST;                       // 2 buffers x (w1[128], w2[128])
  int tid=threadIdx.x, lane=tid&31, wid=tid>>5;
  int wr=wid&3, wc=wid>>2;
  int bh=blockIdx.x, b=bh/NH_, h=bh-b*NH_;
  int m0=blockIdx.y*128;
  const float* Q = g_Qb + (size_t)b*N_*H_ + h*64;
  const float* K = g_Kb + (size_t)b*N_*H_ + h*64;
  #pragma unroll
  for (int it=0; it<8; it++){
    int lin = tid + it*256;
    int r = lin>>4, q = (lin&15)*4;
    cpa16(Ks + r*ST + q, K + (size_t)(m0+r)*H_ + q);
    cpa16(Qb2[0] + r*ST + q, Q + (size_t)r*H_ + q);
  }
  if (tid < 128){
    float iz = 1.f / g_Z[(size_t)bh*N_ + tid];
    colp[tid]     = g_c1[b*N_+tid]*iz;
    colp[128+tid] = g_c2[b*N_+tid]*iz;
  }
  cp_commit();
  float r1[4]={0,0,0,0}, r2[4]={0,0,0,0};
  for (int nt=0; nt<8; nt++){
    int cur=nt&1;
    cp_wait0();
    __syncthreads();
    if (nt+1<8){
      #pragma unroll
      for (int it=0; it<8; it++){
        int lin = tid + it*256;
        int r = lin>>4, q = (lin&15)*4;
        cpa16(Qb2[1-cur] + r*ST + q, Q + (size_t)((nt+1)*128+r)*H_ + q);
      }
      if (tid < 128){
        int n = (nt+1)*128 + tid;
        float iz = 1.f / g_Z[(size_t)bh*N_ + n];
        colp[(1-cur)*256 + tid]       = g_c1[b*N_+n]*iz;
        colp[(1-cur)*256 + 128 + tid] = g_c2[b*N_+n]*iz;
      }
      cp_commit();
    }
    float c[2][8][4];
    #pragma unroll
    for(int i=0;i<2;i++)
      #pragma unroll
      for(int j=0;j<8;j++){ c[i][j][0]=0;c[i][j][1]=0;c[i][j][2]=0;c[i][j][3]=0; }
    mma_tile_p<ST,8,8>(Ks, Qb2[cur], c, wr, wc, lane);
    const float* cp0 = colp + cur*256;
    #pragma unroll
    for (int rf=0; rf<2; rf++){
      #pragma unroll
      for (int nf=0; nf<8; nf++){
        int lc0 = wc*64 + nf*8 + 2*(lane&3);
        float w1a = cp0[lc0], w1b = cp0[lc0+1];
        float w2a = cp0[128+lc0], w2b = cp0[128+lc0+1];
        float P0 = fex2(c[rf][nf][0]), P1 = fex2(c[rf][nf][1]);
        float P2 = fex2(c[rf][nf][2]), P3 = fex2(c[rf][nf][3]);
        r1[rf*2+0] += w1a*P0 + w1b*P1;  r2[rf*2+0] += w2a*P0 + w2b*P1;
        r1[rf*2+1] += w1a*P2 + w1b*P3;  r2[rf*2+1] += w2a*P2 + w2b*P3;
      }
    }
  }
  #pragma unroll
  for (int i=0;i<4;i++){
    float v1 = r1[i], v2 = r2[i];
    v1 += __shfl_xor_sync(0xffffffffu, v1, 1);
    v1 += __shfl_xor_sync(0xffffffffu, v1, 2);
    v2 += __shfl_xor_sync(0xffffffffu, v2, 1);
    v2 += __shfl_xor_sync(0xffffffffu, v2, 2);
    if ((lane&3)==0){
      size_t o = (size_t)bh*N_ + m0 + wr*32 + (i>>1)*16 + (lane>>2) + (i&1)*8;
      atomicAdd(&g_r1[o], v1);
      atomicAdd(&g_r2[o], v2);
    }
  }
}

// ---------------- A = r @ V ----------------
__global__ __launch_bounds__(768) void k_matvec(){
  int b = blockIdx.x, f = threadIdx.x, h = f >> 6;
  int m0 = blockIdx.y*64;
  const float* r1 = g_r1 + ((size_t)b*NH_+h)*N_;
  const float* r2 = g_r2 + ((size_t)b*NH_+h)*N_;
  float a1=0.f, a2=0.f;
  for (int m=m0; m<m0+64; m++){
    float vv = g_Vb[((size_t)b*N_+m)*H_+f];
    a1 += r1[m]*vv; a2 += r2[m]*vv;
  }
  atomicAdd(&g_A1[b*H_+f], a1);
  atomicAdd(&g_A2[b*H_+f], a2);
}

// ---------------- final projections + broadcast ----------------
__global__ __launch_bounds__(768) void k_final(const float* __restrict__ Wo, const float* __restrict__ bo,
                                               const float* __restrict__ Wa, const float* __restrict__ ba){
  int b = blockIdx.x, o = threadIdx.x;
  __shared__ float u1s[H_], u2s[H_];
  const float* w = Wo + (size_t)o*H_;
  const float* A1 = g_A1 + b*H_;
  const float* A2 = g_A2 + b*H_;
  float u1 = bo[o], u2 = bo[o];
  for (int i=0;i<H_;i++){ u1 += w[i]*A1[i]; u2 += w[i]*A2[i]; }
  u1s[o] = u1; u2s[o] = u2;
  __syncthreads();
  const float* wa = Wa + (size_t)o*2*H_;
  float p = ba[o];
  for (int i=0;i<H_;i++) p += wa[i]*u1s[i] + wa[H_+i]*u2s[i];
  g_pm[b*H_+o] = p;
}

__global__ void k_bcast(float* __restrict__ out){
  int idx = blockIdx.x*blockDim.x + threadIdx.x;
  if (idx >= B_*N_*H_) return;
  int f = idx % H_;
  int b = idx / (N_*H_);
  out[idx] = g_pm[b*H_+f];
}

// ---------------- launch ----------------
extern "C" void kernel_launch(void* const* d_in, const int* in_sizes, int n_in,
                              void* d_out, int out_size){
  (void)in_sizes; (void)n_in; (void)out_size;
  const float* x      = (const float*)d_in[0];
  const float* W_var  = (const float*)d_in[3];
  const float* b_var  = (const float*)d_in[4];
  const float* W_sym  = (const float*)d_in[5];
  const float* b_sym  = (const float*)d_in[6];
  const float* W_sc   = (const float*)d_in[7];
  const float* b_scb  = (const float*)d_in[8];
  const float* W_cr   = (const float*)d_in[9];
  const float* b_cr   = (const float*)d_in[10];
  const float* W_atom = (const float*)d_in[11];
  const float* b_atom = (const float*)d_in[12];
  const float* W_q    = (const float*)d_in[13];
  const float* b_q    = (const float*)d_in[14];
  const float* W_k    = (const float*)d_in[15];
  const float* b_k    = (const float*)d_in[16];
  const float* W_v    = (const float*)d_in[17];
  const float* b_v    = (const float*)d_in[18];
  const float* W_o    = (const float*)d_in[19];
  const float* b_o    = (const float*)d_in[20];
  const int*   pp     = (const int*)d_in[21];
  const int*   occ    = (const int*)d_in[24];
  float* out = (float*)d_out;

  float *p_Q, *p_K, *p_V;
  cudaGetSymbolAddress((void**)&p_Q, g_Qb);
  cudaGetSymbolAddress((void**)&p_K, g_Kb);
  cudaGetSymbolAddress((void**)&p_V, g_Vb);

  const int PROJ_SMEM  = (4*128*STP)*4;
  const int ATTN1_SMEM = (3*128*ST)*4;
  const int ATTN2_SMEM = (3*128*ST + 512)*4;
  static bool attr_done = false;
  if (!attr_done){
    cudaFuncSetAttribute(k_proj,  cudaFuncAttributeMaxDynamicSharedMemorySize, PROJ_SMEM);
    cudaFuncSetAttribute(k_attn1, cudaFuncAttributeMaxDynamicSharedMemorySize, ATTN1_SMEM);
    cudaFuncSetAttribute(k_attn2, cudaFuncAttributeMaxDynamicSharedMemorySize, ATTN2_SMEM);
    attr_done = true;
  }

  // launch order: ncu capture slot (#4) = k_proj
  k_init<<<(B_*NH_*N_+255)/256, 256>>>(b_scb);                                   // 1
  const int PRE = 2*(B_*N_*H_/8) + 5*(H_*H_/8);
  k_preconv<<<(PRE+255)/256, 256>>>(x, pp, W_var, W_sym, W_q, W_k, W_v);         // 2
  k_cross<<<B_*M_, 128>>>(x, W_cr, b_cr, occ);                                   // 3
  dim3 gp(H_/128, (B_*N_)/128, 5);
  k_proj<<<gp, 256, PROJ_SMEM>>>(b_var, b_sym, b_q, b_k, b_v, W_sc, p_Q, p_K, p_V); // 4 <- profiled
  dim3 ga(B_*NH_, N_/128);
  k_attn1<<<ga, 256, ATTN1_SMEM>>>();                                            // 5
  k_post<<<B_, 1024>>>(pp);                                                      // 6
  dim3 gbf(B_*NH_, N_/8);
  k_bandfix<<<gbf, 256>>>();                                                     // 7
  k_attn2<<<ga, 256, ATTN2_SMEM>>>();                                            // 8
  dim3 gmv(B_, 16);
  k_matvec<<<gmv, 768>>>();
  k_final<<<B_, 768>>>(W_o, b_o, W_atom, b_atom);
  k_bcast<<<(B_*N_*H_+255)/256, 256>>>(out);
}

// round 12
// speedup vs baseline: 1.0718x; 1.0162x over previous
#include <cuda_runtime.h>
#include <mma.h>
#include <cstdint>
using namespace nvcuda;

#define B_ 8
#define N_ 1024
#define H_ 768
#define NH_ 12
#define M_ 256
#define ST 72    // attn smem row stride
#define STP 40   // proj smem row stride (k-tile 32 + pad 8)
#define KT 32
#define NKT 24
#define LOG2E 1.4426950408889634f

// ---------------- scratch ----------------
__device__ float g_xr[B_*N_*H_];
__device__ float g_vi[B_*N_*H_];
__device__ float g_Wr[5*H_*H_];
__device__ float g_Qb[B_*N_*H_];
__device__ float g_Kb[B_*N_*H_];
__device__ float g_Vb[B_*N_*H_];
__device__ float g_sc[B_*N_];
__device__ float g_vg2[B_*N_];
__device__ float g_ab[B_*N_];
__device__ float g_dg[B_*N_];
__device__ float g_sumw[B_];
__device__ float g_c1[B_*N_];
__device__ float g_c2[B_*N_];
__device__ float g_Z[B_*NH_*N_];
__device__ float g_r1[B_*NH_*N_];
__device__ float g_r2[B_*NH_*N_];
__device__ float g_A1[B_*H_];
__device__ float g_A2[B_*H_];
__device__ float g_pm[B_*H_];

__device__ __forceinline__ bool d_pred(const int* P, int i){ return P[i]==1; }
__device__ __forceinline__ bool d_single(const int* P, int i){ return (i==0) || (i>=2 && P[i-2]==1); }
__device__ __forceinline__ float d_lrelu(float t){ return t >= 0.f ? t : 0.02f*t; }
__device__ __forceinline__ float tf32r(float x){ return wmma::__float_to_tf32(x); }
__device__ __forceinline__ float fex2(float x){ float y; asm("ex2.approx.f32 %0, %1;" : "=f"(y) : "f"(x)); return y; }

__device__ __forceinline__ void perm_store(float* dst, float4 a, float4 b){
  float4 o0 = make_float4(tf32r(a.x), tf32r(b.x), tf32r(a.y), tf32r(b.y));
  float4 o1 = make_float4(tf32r(a.z), tf32r(b.z), tf32r(a.w), tf32r(b.w));
  *(float4*)dst = o0; *(float4*)(dst+4) = o1;
}

// ---------------- cp.async (uint32 smem addr + immediate offsets) ----------------
__device__ __forceinline__ void cpa16s(uint32_t s, const float* g){
  asm volatile("cp.async.cg.shared.global [%0], [%1], 16;\n" :: "r"(s), "l"(g));
}
__device__ __forceinline__ void cp_commit(){ asm volatile("cp.async.commit_group;\n"); }
__device__ __forceinline__ void cp_wait0(){ asm volatile("cp.async.wait_group 0;\n"); }

// ---------------- m16n8k8 tf32 mma.sync ----------------
__device__ __forceinline__ void mma8(float c[4], const uint32_t a[4], uint32_t b0, uint32_t b1){
  asm volatile(
    "mma.sync.aligned.m16n8k8.row.col.f32.tf32.tf32.f32 "
    "{%0,%1,%2,%3}, {%4,%5,%6,%7}, {%8,%9}, {%0,%1,%2,%3};\n"
    : "+f"(c[0]), "+f"(c[1]), "+f"(c[2]), "+f"(c[3])
    : "r"(a[0]), "r"(a[1]), "r"(a[2]), "r"(a[3]), "r"(b0), "r"(b1));
}

// all offsets compile-time: mA/mB are per-thread pre-offset base pointers
template<int STRIDE, int NF, int K8>
__device__ __forceinline__ void mma_tile_pre(const float* __restrict__ mA,
                                             const float* __restrict__ mB,
                                             float c[2][NF][4]){
  #pragma unroll
  for (int k8=0;k8<K8;k8++){
    uint32_t a[2][4];
    #pragma unroll
    for (int rf=0; rf<2; rf++){
      float2 v0 = *(const float2*)(mA + rf*16*STRIDE + k8*8);
      float2 v1 = *(const float2*)(mA + rf*16*STRIDE + 8*STRIDE + k8*8);
      a[rf][0]=__float_as_uint(v0.x); a[rf][2]=__float_as_uint(v0.y);
      a[rf][1]=__float_as_uint(v1.x); a[rf][3]=__float_as_uint(v1.y);
    }
    #pragma unroll
    for (int nf=0;nf<NF;nf++){
      float2 bv = *(const float2*)(mB + nf*8*STRIDE + k8*8);
      mma8(c[0][nf], a[0], __float_as_uint(bv.x), __float_as_uint(bv.y));
      mma8(c[1][nf], a[1], __float_as_uint(bv.x), __float_as_uint(bv.y));
    }
  }
}

// ---------------- init ----------------
__global__ void k_init(const float* __restrict__ bsc){
  int i = blockIdx.x*blockDim.x + threadIdx.x;
  if (i < B_*N_){ g_vg2[i] = 0.f; g_sc[i] = bsc[0]; }
  if (i < B_*H_){ g_A1[i]=0.f; g_A2[i]=0.f; }
  if (i < B_*NH_*N_){ g_Z[i]=0.f; g_r1[i]=0.f; g_r2[i]=0.f; }
}

// ---------------- preconv ----------------
__global__ void k_preconv(const float* __restrict__ x, const int* __restrict__ pp,
                          const float* __restrict__ W0, const float* __restrict__ W1,
                          const float* __restrict__ W2, const float* __restrict__ W3,
                          const float* __restrict__ W4){
  const int XT8 = B_*N_*H_/8;
  const int WT8 = H_*H_/8;
  const int H8 = H_/8;
  int i = blockIdx.x*blockDim.x + threadIdx.x;
  if (i < XT8){
    const float4* s = (const float4*)x + (size_t)i*2;
    perm_store(g_xr + (size_t)i*8, s[0], s[1]);
  } else if (i < 2*XT8){
    int j = i - XT8;
    int hh8 = j % H8;
    int nn  = (j / H8) % N_;
    int b   = j / (N_*H8);
    bool single = (nn==0) || (nn>=2 && pp[b*N_+nn-2]==1);
    int np = (nn+1)&(N_-1), nm = (nn+N_-1)&(N_-1);
    const float* bp = x + ((size_t)b*N_ + np)*H_ + hh8*8;
    float4 xa = *(const float4*)bp, xb = *(const float4*)(bp+4);
    if (!single){
      const float* bm = x + ((size_t)b*N_ + nm)*H_ + hh8*8;
      float4 ya = *(const float4*)bm, yb = *(const float4*)(bm+4);
      xa.x=0.5f*(xa.x+ya.x); xa.y=0.5f*(xa.y+ya.y); xa.z=0.5f*(xa.z+ya.z); xa.w=0.5f*(xa.w+ya.w);
      xb.x=0.5f*(xb.x+yb.x); xb.y=0.5f*(xb.y+yb.y); xb.z=0.5f*(xb.z+yb.z); xb.w=0.5f*(xb.w+yb.w);
    }
    perm_store(g_vi + (size_t)j*8, xa, xb);
  } else {
    int j = i - 2*XT8;
    if (j < 5*WT8){
      int w = j / WT8, o = j - w*WT8;
      int row = o / H8, rem = o - row*H8;
      int srow = row;
      if (w==2 || w==3){
        int r8 = row & 7;
        srow = (row & ~7) | ((r8&1)*4 + (r8>>1));
      }
      const float* src = (w==0)?W0:(w==1)?W1:(w==2)?W2:(w==3)?W3:W4;
      const float4* s = (const float4*)(src + (size_t)srow*H_ + rem*8);
      perm_store(g_Wr + (size_t)w*H_*H_ + (size_t)o*8, s[0], s[1]);
    }
  }
}

// ---------------- merged projections ----------------
__global__ __launch_bounds__(256,2) void k_proj(
    const float* __restrict__ b_var, const float* __restrict__ b_sym,
    const float* __restrict__ b_q, const float* __restrict__ b_k, const float* __restrict__ b_v,
    const float* __restrict__ Wsc,
    float* __restrict__ Qb, float* __restrict__ Kb, float* __restrict__ Vb){
  extern __shared__ float sm[];
  int mode = blockIdx.z;
  const float* A = (mode==0) ? g_vi : g_xr;
  const float* W = g_Wr + (size_t)mode*H_*H_;
  const float* bias; float* C=nullptr; float alpha=1.f; const float* wsc=nullptr;
  switch(mode){
    case 0: bias=b_var; wsc=Wsc;    break;
    case 1: bias=b_sym; wsc=Wsc+H_; break;
    case 2: bias=b_q;   C=Qb; alpha=0.125f*LOG2E; break;
    case 3: bias=b_k;   C=Kb; break;
    default:bias=b_v;   C=Vb; break;
  }
  int tid=threadIdx.x, lane=tid&31, wid=tid>>5;
  int wr=wid&3, wc=wid>>2;
  int m0 = blockIdx.y*128, n0 = blockIdx.x*128;
  // staging bases (per-thread)
  int sr = tid>>3, sq = (tid&7)*4;
  uint32_t smBase = (uint32_t)__cvta_generic_to_shared(sm);
  uint32_t sA0 = smBase + (sr*STP + sq)*4;
  uint32_t sA1 = sA0 + 128*STP*4;
  uint32_t sB0 = sA0 + 2*128*STP*4;
  uint32_t sB1 = sA0 + 3*128*STP*4;
  const float* gA = A + (size_t)(m0+sr)*H_ + sq;
  const float* gW = W + (size_t)(n0+sr)*H_ + sq;
  // mma bases (per-thread, per-buffer)
  int mrow = wr*32 + (lane>>2), mc = 2*(lane&3);
  int brow = wc*64 + (lane>>2);
  const float* mA0 = sm + mrow*STP + mc;
  const float* mA1 = mA0 + 128*STP;
  const float* mB0 = sm + 2*128*STP + brow*STP + mc;
  const float* mB1 = mB0 + 128*STP;
  #define STAGE_P(sa, sb) do { \
    cpa16s((sa),            gA); \
    cpa16s((sa)+32*STP*4,   gA+32*H_); \
    cpa16s((sa)+64*STP*4,   gA+64*H_); \
    cpa16s((sa)+96*STP*4,   gA+96*H_); \
    cpa16s((sb),            gW); \
    cpa16s((sb)+32*STP*4,   gW+32*H_); \
    cpa16s((sb)+64*STP*4,   gW+64*H_); \
    cpa16s((sb)+96*STP*4,   gW+96*H_); \
    gA += KT; gW += KT; cp_commit(); } while(0)
  STAGE_P(sA0, sB0);
  float c[2][8][4];
  #pragma unroll
  for(int i=0;i<2;i++)
    #pragma unroll
    for(int j=0;j<8;j++){ c[i][j][0]=0;c[i][j][1]=0;c[i][j][2]=0;c[i][j][3]=0; }
  #pragma unroll 1
  for (int kt2=0; kt2<NKT/2; kt2++){
    cp_wait0(); __syncthreads();
    STAGE_P(sA1, sB1);                      // stage odd tile
    mma_tile_pre<STP,8,4>(mA0, mB0, c);     // consume even tile
    cp_wait0(); __syncthreads();
    if (kt2 < NKT/2-1) STAGE_P(sA0, sB0);   // stage next even tile
    mma_tile_pre<STP,8,4>(mA1, mB1, c);     // consume odd tile
  }
  #undef STAGE_P
  int t = lane&3;
  if (mode<=1){
    float p[4] = {0,0,0,0};
    #pragma unroll
    for (int rf=0; rf<2; rf++){
      #pragma unroll
      for (int nf=0; nf<8; nf++){
        int col0 = n0 + wc*64 + nf*8 + 2*t;
        float w0 = wsc[col0], w1 = wsc[col0+1];
        float b0v = bias[col0], b1v = bias[col0+1];
        p[rf*2+0] += tanhf(c[rf][nf][0]+b0v)*w0 + tanhf(c[rf][nf][1]+b1v)*w1;
        p[rf*2+1] += tanhf(c[rf][nf][2]+b0v)*w0 + tanhf(c[rf][nf][3]+b1v)*w1;
      }
    }
    #pragma unroll
    for (int i=0;i<4;i++){
      float v = p[i];
      v += __shfl_xor_sync(0xffffffffu, v, 1);
      v += __shfl_xor_sync(0xffffffffu, v, 2);
      if (t==0)
        atomicAdd(&g_sc[m0 + wr*32 + (i>>1)*16 + (lane>>2) + (i&1)*8], v);
    }
  } else if (mode==4){
    #pragma unroll
    for (int rf=0; rf<2; rf++){
      int row = m0 + wr*32 + rf*16 + (lane>>2);
      #pragma unroll
      for (int nf=0; nf<8; nf++){
        int col0 = n0 + wc*64 + nf*8 + 2*t;
        float2 bv = *(const float2*)(bias + col0);
        *(float2*)(C + (size_t)row*H_ + col0)     = make_float2(c[rf][nf][0]+bv.x, c[rf][nf][1]+bv.y);
        *(float2*)(C + (size_t)(row+8)*H_ + col0) = make_float2(c[rf][nf][2]+bv.x, c[rf][nf][3]+bv.y);
      }
    }
  } else {
    #pragma unroll
    for (int rf=0; rf<2; rf++){
      int row = m0 + wr*32 + rf*16 + (lane>>2);
      #pragma unroll
      for (int nf=0; nf<8; nf++){
        int col = n0 + wc*64 + nf*8;
        float b0v = bias[col + t], b1v = bias[col + t + 4];
        *(float2*)(C + (size_t)row*H_ + col + 2*t) =
          make_float2(tf32r(alpha*(c[rf][nf][0]+b0v)), tf32r(alpha*(c[rf][nf][1]+b1v)));
        *(float2*)(C + (size_t)(row+8)*H_ + col + 2*t) =
          make_float2(tf32r(alpha*(c[rf][nf][2]+b0v)), tf32r(alpha*(c[rf][nf][3]+b1v)));
      }
    }
  }
}

// ---------------- attention pass 1 ----------------
__global__ __launch_bounds__(256,2) void k_attn1(){
  extern __shared__ float sm[];
  int tid=threadIdx.x, lane=tid&31, wid=tid>>5;
  int wr=wid&3, wc=wid>>2;
  int bh=blockIdx.x, b=bh/NH_, h=bh-b*NH_;
  int n0=blockIdx.y*128;
  const float* Q = g_Qb + (size_t)b*N_*H_ + h*64;
  const float* K = g_Kb + (size_t)b*N_*H_ + h*64;
  int sr = tid>>4, sq = (tid&15)*4;
  uint32_t smBase = (uint32_t)__cvta_generic_to_shared(sm);
  uint32_t sQ  = smBase + (sr*ST + sq)*4;
  uint32_t sK0 = sQ + 128*ST*4;
  uint32_t sK1 = sQ + 2*128*ST*4;
  const float* gQ = Q + (size_t)(n0+sr)*H_ + sq;
  const float* gK = K + (size_t)sr*H_ + sq;
  int mrow = wr*32 + (lane>>2), mc = 2*(lane&3);
  int brow = wc*64 + (lane>>2);
  const float* mQ  = sm + mrow*ST + mc;
  const float* mK0 = sm + 128*ST + brow*ST + mc;
  const float* mK1 = mK0 + 128*ST;
  #define STAGE_A(sdst) do { \
    cpa16s((sdst),           gK); \
    cpa16s((sdst)+16*ST*4,   gK+16*H_); \
    cpa16s((sdst)+32*ST*4,   gK+32*H_); \
    cpa16s((sdst)+48*ST*4,   gK+48*H_); \
    cpa16s((sdst)+64*ST*4,   gK+64*H_); \
    cpa16s((sdst)+80*ST*4,   gK+80*H_); \
    cpa16s((sdst)+96*ST*4,   gK+96*H_); \
    cpa16s((sdst)+112*ST*4,  gK+112*H_); \
    gK += 128*H_; cp_commit(); } while(0)
  #pragma unroll
  for (int it=0; it<8; it++)
    cpa16s(sQ + it*16*ST*4, gQ + it*16*H_);
  STAGE_A(sK0);
  float z[4]={0,0,0,0};
  #pragma unroll 1
  for (int mt2=0; mt2<4; mt2++){
    cp_wait0(); __syncthreads();
    STAGE_A(sK1);
    {
      float c[2][8][4];
      #pragma unroll
      for(int i=0;i<2;i++)
        #pragma unroll
        for(int j=0;j<8;j++){ c[i][j][0]=0;c[i][j][1]=0;c[i][j][2]=0;c[i][j][3]=0; }
      mma_tile_pre<ST,8,8>(mQ, mK0, c);
      #pragma unroll
      for (int rf=0; rf<2; rf++)
        #pragma unroll
        for (int nf=0; nf<8; nf++){
          z[rf*2+0] += fex2(c[rf][nf][0]) + fex2(c[rf][nf][1]);
          z[rf*2+1] += fex2(c[rf][nf][2]) + fex2(c[rf][nf][3]);
        }
    }
    cp_wait0(); __syncthreads();
    if (mt2 < 3) STAGE_A(sK0);
    {
      float c[2][8][4];
      #pragma unroll
      for(int i=0;i<2;i++)
        #pragma unroll
        for(int j=0;j<8;j++){ c[i][j][0]=0;c[i][j][1]=0;c[i][j][2]=0;c[i][j][3]=0; }
      mma_tile_pre<ST,8,8>(mQ, mK1, c);
      #pragma unroll
      for (int rf=0; rf<2; rf++)
        #pragma unroll
        for (int nf=0; nf<8; nf++){
          z[rf*2+0] += fex2(c[rf][nf][0]) + fex2(c[rf][nf][1]);
          z[rf*2+1] += fex2(c[rf][nf][2]) + fex2(c[rf][nf][3]);
        }
    }
  }
  #undef STAGE_A
  #pragma unroll
  for (int i=0;i<4;i++){
    float v = z[i];
    v += __shfl_xor_sync(0xffffffffu, v, 1);
    v += __shfl_xor_sync(0xffffffffu, v, 2);
    if ((lane&3)==0)
      atomicAdd(&g_Z[(size_t)bh*N_ + n0 + wr*32 + (i>>1)*16 + (lane>>2) + (i&1)*8], v);
  }
}

// ---------------- cross scores ----------------
__global__ __launch_bounds__(128) void k_cross(const float* __restrict__ x, const float* __restrict__ Wc,
                                               const float* __restrict__ bc, const int* __restrict__ occ){
  int pid = blockIdx.x;
  int b = pid / M_;
  int o0 = occ[pid*2], o1 = occ[pid*2+1];
  const float* x0 = x + ((size_t)b*N_+o0)*H_;
  const float* x1 = x + ((size_t)b*N_+o1)*H_;
  float p = 0.f;
  for (int h=threadIdx.x; h<H_; h+=128) p += 0.5f*(x0[h]+x1[h])*Wc[h];
  for (int o=16;o;o>>=1) p += __shfl_xor_sync(0xffffffffu, p, o);
  __shared__ float red[4];
  if ((threadIdx.x&31)==0) red[threadIdx.x>>5] = p;
  __syncthreads();
  if (threadIdx.x==0){
    float t = d_lrelu(bc[0] + red[0]+red[1]+red[2]+red[3]);
    atomicAdd(&g_vg2[b*N_+o0], t*t);
    atomicAdd(&g_vg2[b*N_+o1], t*t);
  }
}

// ---------------- band + sumw + coef ----------------
__global__ __launch_bounds__(1024) void k_post(const int* __restrict__ pp){
  __shared__ float ab[N_], wt[N_], red[32];
  __shared__ float swv;
  int b = blockIdx.x, n = threadIdx.x;
  const int* P = pp + b*N_;
  const float* s = g_sc + b*N_;
  float a = 0.f;
  if (n < N_-1){
    float sl1 = d_pred(P,n+1) ? d_lrelu(s[n+1]) : 0.f;
    bool up0 = d_pred(P,n) && (n<=1 || !d_single(P,n));
    float su0 = up0 ? d_lrelu(s[n]) : 0.f;
    a = sl1 + su0;
  }
  ab[n] = a; g_ab[b*N_+n] = a;
  bool up = d_pred(P,n) && (n<=1 || !d_single(P,n));
  bool tr = up && (n>=1);
  float w = d_pred(P,n) ? (tr?3.f:2.f) : 0.f;
  wt[n] = w;
  float v = w;
  for (int o=16;o;o>>=1) v += __shfl_xor_sync(0xffffffffu, v, o);
  if ((n&31)==0) red[n>>5] = v;
  __syncthreads();
  if (n < 32){
    float t2 = red[n];
    for (int o=16;o;o>>=1) t2 += __shfl_xor_sync(0xffffffffu, t2, o);
    if (n==0){ swv = t2; g_sumw[b] = t2; }
  }
  __syncthreads();
  float am1 = (n>=1) ? ab[n-1] : 0.f;
  g_dg[b*N_+n] = 0.8f*(am1*am1 + a*a) + g_vg2[b*N_+n];
  float sw = swv;
  int nm = (n+N_-1)&(N_-1), np = (n+1)&(N_-1);
  float c1 = wt[nm]*(d_single(P,nm)?1.f:0.5f) + wt[np]*(d_single(P,np)?0.f:0.5f);
  g_c1[b*N_+n] = c1 / sw;
  g_c2[b*N_+n] = wt[n] / sw;
}

// ---------------- band correction ----------------
__global__ __launch_bounds__(256) void k_bandfix(){
  int bh = blockIdx.x, b = bh/NH_, h = bh - b*NH_;
  int wid = threadIdx.x>>5, lane = threadIdx.x&31;
  int n = blockIdx.y*8 + wid;
  const float* Qr = g_Qb + ((size_t)b*N_ + n)*H_ + h*64;
  const float* Kp = g_Kb + (size_t)b*N_*H_ + h*64;
  const float* ab = g_ab + b*N_;
  float q0 = Qr[lane], q1 = Qr[lane+32];
  float anm2=(n>=2)?ab[n-2]:0.f, anm1=(n>=1)?ab[n-1]:0.f;
  float an=ab[n], anp1=(n<N_-1)?ab[n+1]:0.f;
  float biasv[5] = { LOG2E*0.8f*anm2*anm1, LOG2E*0.2f*anm1, LOG2E*g_dg[b*N_+n],
                     LOG2E*0.2f*an, LOG2E*0.8f*an*anp1 };
  float delta[5];
  float dz = 0.f;
  #pragma unroll
  for (int d=-2; d<=2; d++){
    int m = n + d;
    delta[d+2] = 0.f;
    if ((unsigned)m < (unsigned)N_){
      const float* Kr = Kp + (size_t)m*H_;
      float s = q0*Kr[lane] + q1*Kr[lane+32];
      #pragma unroll
      for (int o=16;o;o>>=1) s += __shfl_xor_sync(0xffffffffu, s, o);
      delta[d+2] = fex2(s + biasv[d+2]) - fex2(s);
      dz += delta[d+2];
    }
  }
  float Zf = g_Z[(size_t)bh*N_ + n] + dz;
  if (lane==0) g_Z[(size_t)bh*N_ + n] = Zf;
  float w1 = g_c1[b*N_+n] / Zf;
  float w2 = g_c2[b*N_+n] / Zf;
  if (lane==0 && (w1 != 0.f || w2 != 0.f)){
    #pragma unroll
    for (int d=-2; d<=2; d++){
      int m = n + d;
      if ((unsigned)m < (unsigned)N_ && delta[d+2] != 0.f){
        atomicAdd(&g_r1[(size_t)bh*N_ + m], w1*delta[d+2]);
        atomicAdd(&g_r2[(size_t)bh*N_ + m], w2*delta[d+2]);
      }
    }
  }
}

// ---------------- attention pass 2 ----------------
__global__ __launch_bounds__(256,2) void k_attn2(){
  extern __shared__ float sm[];
  float* colp = sm + 3*128*ST;     // 2 buffers x (w1[128], w2[128])
  int tid=threadIdx.x, lane=tid&31, wid=tid>>5;
  int wr=wid&3, wc=wid>>2;
  int bh=blockIdx.x, b=bh/NH_, h=bh-b*NH_;
  int m0=blockIdx.y*128;
  const float* Q = g_Qb + (size_t)b*N_*H_ + h*64;
  const float* K = g_Kb + (size_t)b*N_*H_ + h*64;
  int sr = tid>>4, sq = (tid&15)*4;
  uint32_t smBase = (uint32_t)__cvta_generic_to_shared(sm);
  uint32_t sKr = smBase + (sr*ST + sq)*4;
  uint32_t sQ0 = sKr + 128*ST*4;
  uint32_t sQ1 = sKr + 2*128*ST*4;
  const float* gKr = K + (size_t)(m0+sr)*H_ + sq;
  const float* gQ  = Q + (size_t)sr*H_ + sq;
  int mrow = wr*32 + (lane>>2), mc = 2*(lane&3);
  int brow = wc*64 + (lane>>2);
  const float* mK  = sm + mrow*ST + mc;
  const float* mQ0 = sm + 128*ST + brow*ST + mc;
  const float* mQ1 = mQ0 + 128*ST;
  int nctr = 0;
  #define STAGE_Q(sdst, cbuf) do { \
    cpa16s((sdst),           gQ); \
    cpa16s((sdst)+16*ST*4,   gQ+16*H_); \
    cpa16s((sdst)+32*ST*4,   gQ+32*H_); \
    cpa16s((sdst)+48*ST*4,   gQ+48*H_); \
    cpa16s((sdst)+64*ST*4,   gQ+64*H_); \
    cpa16s((sdst)+80*ST*4,   gQ+80*H_); \
    cpa16s((sdst)+96*ST*4,   gQ+96*H_); \
    cpa16s((sdst)+112*ST*4,  gQ+112*H_); \
    gQ += 128*H_; \
    if (tid < 128){ \
      int n = nctr*128 + tid; \
      float iz = 1.f / g_Z[(size_t)bh*N_ + n]; \
      colp[(cbuf)*256 + tid]       = g_c1[b*N_+n]*iz; \
      colp[(cbuf)*256 + 128 + tid] = g_c2[b*N_+n]*iz; \
    } \
    nctr++; cp_commit(); } while(0)
  #pragma unroll
  for (int it=0; it<8; it++)
    cpa16s(sKr + it*16*ST*4, gKr + it*16*H_);
  STAGE_Q(sQ0, 0);
  float r1[4]={0,0,0,0}, r2[4]={0,0,0,0};
  #pragma unroll 1
  for (int nt2=0; nt2<4; nt2++){
    cp_wait0(); __syncthreads();
    STAGE_Q(sQ1, 1);
    {
      float c[2][8][4];
      #pragma unroll
      for(int i=0;i<2;i++)
        #pragma unroll
        for(int j=0;j<8;j++){ c[i][j][0]=0;c[i][j][1]=0;c[i][j][2]=0;c[i][j][3]=0; }
      mma_tile_pre<ST,8,8>(mK, mQ0, c);
      const float* cp0 = colp;
      #pragma unroll
      for (int rf=0; rf<2; rf++)
        #pragma unroll
        for (int nf=0; nf<8; nf++){
          int lc0 = wc*64 + nf*8 + 2*(lane&3);
          float w1a = cp0[lc0], w1b = cp0[lc0+1];
          float w2a = cp0[128+lc0], w2b = cp0[128+lc0+1];
          float P0 = fex2(c[rf][nf][0]), P1 = fex2(c[rf][nf][1]);
          float P2 = fex2(c[rf][nf][2]), P3 = fex2(c[rf][nf][3]);
          r1[rf*2+0] += w1a*P0 + w1b*P1;  r2[rf*2+0] += w2a*P0 + w2b*P1;
          r1[rf*2+1] += w1a*P2 + w1b*P3;  r2[rf*2+1] += w2a*P2 + w2b*P3;
        }
    }
    cp_wait0(); __syncthreads();
    if (nt2 < 3) STAGE_Q(sQ0, 0);
    {
      float c[2][8][4];
      #pragma unroll
      for(int i=0;i<2;i++)
        #pragma unroll
        for(int j=0;j<8;j++){ c[i][j][0]=0;c[i][j][1]=0;c[i][j][2]=0;c[i][j][3]=0; }
      mma_tile_pre<ST,8,8>(mK, mQ1, c);
      const float* cp0 = colp + 256;
      #pragma unroll
      for (int rf=0; rf<2; rf++)
        #pragma unroll
        for (int nf=0; nf<8; nf++){
          int lc0 = wc*64 + nf*8 + 2*(lane&3);
          float w1a = cp0[lc0], w1b = cp0[lc0+1];
          float w2a = cp0[128+lc0], w2b = cp0[128+lc0+1];
          float P0 = fex2(c[rf][nf][0]), P1 = fex2(c[rf][nf][1]);
          float P2 = fex2(c[rf][nf][2]), P3 = fex2(c[rf][nf][3]);
          r1[rf*2+0] += w1a*P0 + w1b*P1;  r2[rf*2+0] += w2a*P0 + w2b*P1;
          r1[rf*2+1] += w1a*P2 + w1b*P3;  r2[rf*2+1] += w2a*P2 + w2b*P3;
        }
    }
  }
  #undef STAGE_Q
  #pragma unroll
  for (int i=0;i<4;i++){
    float v1 = r1[i], v2 = r2[i];
    v1 += __shfl_xor_sync(0xffffffffu, v1, 1);
    v1 += __shfl_xor_sync(0xffffffffu, v1, 2);
    v2 += __shfl_xor_sync(0xffffffffu, v2, 1);
    v2 += __shfl_xor_sync(0xffffffffu, v2, 2);
    if ((lane&3)==0){
      size_t o = (size_t)bh*N_ + m0 + wr*32 + (i>>1)*16 + (lane>>2) + (i&1)*8;
      atomicAdd(&g_r1[o], v1);
      atomicAdd(&g_r2[o], v2);
    }
  }
}

// ---------------- A = r @ V ----------------
__global__ __launch_bounds__(768) void k_matvec(){
  int b = blockIdx.x, f = threadIdx.x, h = f >> 6;
  int m0 = blockIdx.y*64;
  const float* r1 = g_r1 + ((size_t)b*NH_+h)*N_;
  const float* r2 = g_r2 + ((size_t)b*NH_+h)*N_;
  float a1=0.f, a2=0.f;
  for (int m=m0; m<m0+64; m++){
    float vv = g_Vb[((size_t)b*N_+m)*H_+f];
    a1 += r1[m]*vv; a2 += r2[m]*vv;
  }
  atomicAdd(&g_A1[b*H_+f], a1);
  atomicAdd(&g_A2[b*H_+f], a2);
}

// ---------------- final projections + broadcast ----------------
__global__ __launch_bounds__(768) void k_final(const float* __restrict__ Wo, const float* __restrict__ bo,
                                               const float* __restrict__ Wa, const float* __restrict__ ba){
  int b = blockIdx.x, o = threadIdx.x;
  __shared__ float u1s[H_], u2s[H_];
  const float* w = Wo + (size_t)o*H_;
  const float* A1 = g_A1 + b*H_;
  const float* A2 = g_A2 + b*H_;
  float u1 = bo[o], u2 = bo[o];
  for (int i=0;i<H_;i++){ u1 += w[i]*A1[i]; u2 += w[i]*A2[i]; }
  u1s[o] = u1; u2s[o] = u2;
  __syncthreads();
  const float* wa = Wa + (size_t)o*2*H_;
  float p = ba[o];
  for (int i=0;i<H_;i++) p += wa[i]*u1s[i] + wa[H_+i]*u2s[i];
  g_pm[b*H_+o] = p;
}

__global__ void k_bcast(float* __restrict__ out){
  int idx = blockIdx.x*blockDim.x + threadIdx.x;
  if (idx >= B_*N_*H_) return;
  int f = idx % H_;
  int b = idx / (N_*H_);
  out[idx] = g_pm[b*H_+f];
}

// ---------------- launch ----------------
extern "C" void kernel_launch(void* const* d_in, const int* in_sizes, int n_in,
                              void* d_out, int out_size){
  (void)in_sizes; (void)n_in; (void)out_size;
  const float* x      = (const float*)d_in[0];
  const float* W_var  = (const float*)d_in[3];
  const float* b_var  = (const float*)d_in[4];
  const float* W_sym  = (const float*)d_in[5];
  const float* b_sym  = (const float*)d_in[6];
  const float* W_sc   = (const float*)d_in[7];
  const float* b_scb  = (const float*)d_in[8];
  const float* W_cr   = (const float*)d_in[9];
  const float* b_cr   = (const float*)d_in[10];
  const float* W_atom = (const float*)d_in[11];
  const float* b_atom = (const float*)d_in[12];
  const float* W_q    = (const float*)d_in[13];
  const float* b_q    = (const float*)d_in[14];
  const float* W_k    = (const float*)d_in[15];
  const float* b_k    = (const float*)d_in[16];
  const float* W_v    = (const float*)d_in[17];
  const float* b_v    = (const float*)d_in[18];
  const float* W_o    = (const float*)d_in[19];
  const float* b_o    = (const float*)d_in[20];
  const int*   pp     = (const int*)d_in[21];
  const int*   occ    = (const int*)d_in[24];
  float* out = (float*)d_out;

  float *p_Q, *p_K, *p_V;
  cudaGetSymbolAddress((void**)&p_Q, g_Qb);
  cudaGetSymbolAddress((void**)&p_K, g_Kb);
  cudaGetSymbolAddress((void**)&p_V, g_Vb);

  const int PROJ_SMEM  = (4*128*STP)*4;
  const int ATTN1_SMEM = (3*128*ST)*4;
  const int ATTN2_SMEM = (3*128*ST + 512)*4;
  static bool attr_done = false;
  if (!attr_done){
    cudaFuncSetAttribute(k_proj,  cudaFuncAttributeMaxDynamicSharedMemorySize, PROJ_SMEM);
    cudaFuncSetAttribute(k_attn1, cudaFuncAttributeMaxDynamicSharedMemorySize, ATTN1_SMEM);
    cudaFuncSetAttribute(k_attn2, cudaFuncAttributeMaxDynamicSharedMemorySize, ATTN2_SMEM);
    attr_done = true;
  }

  // launch order: ncu capture slot (#4) = k_proj
  k_init<<<(B_*NH_*N_+255)/256, 256>>>(b_scb);                                   // 1
  const int PRE = 2*(B_*N_*H_/8) + 5*(H_*H_/8);
  k_preconv<<<(PRE+255)/256, 256>>>(x, pp, W_var, W_sym, W_q, W_k, W_v);         // 2
  k_cross<<<B_*M_, 128>>>(x, W_cr, b_cr, occ);                                   // 3
  dim3 gp(H_/128, (B_*N_)/128, 5);
  k_proj<<<gp, 256, PROJ_SMEM>>>(b_var, b_sym, b_q, b_k, b_v, W_sc, p_Q, p_K, p_V); // 4 <- profiled
  dim3 ga(B_*NH_, N_/128);
  k_attn1<<<ga, 256, ATTN1_SMEM>>>();                                            // 5
  k_post<<<B_, 1024>>>(pp);                                                      // 6
  dim3 gbf(B_*NH_, N_/8);
  k_bandfix<<<gbf, 256>>>();                                                     // 7
  k_attn2<<<ga, 256, ATTN2_SMEM>>>();                                            // 8
  dim3 gmv(B_, 16);
  k_matvec<<<gmv, 768>>>();
  k_final<<<B_, 768>>>(W_o, b_o, W_atom, b_atom);
  k_bcast<<<(B_*N_*H_+255)/256, 256>>>(out);
}

// round 13
// speedup vs baseline: 2.2506x; 2.0999x over previous
#include <cuda_runtime.h>
#include <mma.h>
#include <cstdint>
using namespace nvcuda;

#define B_ 8
#define N_ 1024
#define H_ 768
#define NH_ 12
#define M_ 256
#define ST 72    // attn smem row stride
#define STP 40   // proj smem row stride (k-tile 32 + pad 8)
#define KT 32
#define NKT 24
#define LOG2E 1.4426950408889634f

// ---------------- scratch ----------------
__device__ float g_xr[B_*N_*H_];
__device__ float g_vi[B_*N_*H_];
__device__ float g_Wr[5*H_*H_];
__device__ float g_Qb[B_*N_*H_];
__device__ float g_Kb[B_*N_*H_];
__device__ float g_Vb[B_*N_*H_];
__device__ float g_sc[B_*N_];
__device__ float g_vg2[B_*N_];
__device__ float g_ab[B_*N_];
__device__ float g_dg[B_*N_];
__device__ float g_sumw[B_];
__device__ float g_c1[B_*N_];
__device__ float g_c2[B_*N_];
__device__ float g_Z[B_*NH_*N_];
__device__ float g_r1[B_*NH_*N_];
__device__ float g_r2[B_*NH_*N_];
__device__ float g_A1[B_*H_];
__device__ float g_A2[B_*H_];
__device__ float g_u1[B_*H_];
__device__ float g_u2[B_*H_];
__device__ float g_pm[B_*H_];

__device__ __forceinline__ bool d_pred(const int* P, int i){ return P[i]==1; }
__device__ __forceinline__ bool d_single(const int* P, int i){ return (i==0) || (i>=2 && P[i-2]==1); }
__device__ __forceinline__ float d_lrelu(float t){ return t >= 0.f ? t : 0.02f*t; }
__device__ __forceinline__ float tf32r(float x){ return wmma::__float_to_tf32(x); }
__device__ __forceinline__ float fex2(float x){ float y; asm("ex2.approx.f32 %0, %1;" : "=f"(y) : "f"(x)); return y; }

__device__ __forceinline__ void perm_store(float* dst, float4 a, float4 b){
  float4 o0 = make_float4(tf32r(a.x), tf32r(b.x), tf32r(a.y), tf32r(b.y));
  float4 o1 = make_float4(tf32r(a.z), tf32r(b.z), tf32r(a.w), tf32r(b.w));
  *(float4*)dst = o0; *(float4*)(dst+4) = o1;
}

// ---------------- cp.async ----------------
__device__ __forceinline__ void cpa16s(uint32_t s, const float* g){
  asm volatile("cp.async.cg.shared.global [%0], [%1], 16;\n" :: "r"(s), "l"(g));
}
__device__ __forceinline__ void cp_commit(){ asm volatile("cp.async.commit_group;\n"); }
__device__ __forceinline__ void cp_wait0(){ asm volatile("cp.async.wait_group 0;\n"); }

// ---------------- m16n8k8 tf32 mma.sync ----------------
__device__ __forceinline__ void mma8(float c[4], const uint32_t a[4], uint32_t b0, uint32_t b1){
  asm volatile(
    "mma.sync.aligned.m16n8k8.row.col.f32.tf32.tf32.f32 "
    "{%0,%1,%2,%3}, {%4,%5,%6,%7}, {%8,%9}, {%0,%1,%2,%3};\n"
    : "+f"(c[0]), "+f"(c[1]), "+f"(c[2]), "+f"(c[3])
    : "r"(a[0]), "r"(a[1]), "r"(a[2]), "r"(a[3]), "r"(b0), "r"(b1));
}

template<int STRIDE, int NF, int K8>
__device__ __forceinline__ void mma_tile_pre(const float* __restrict__ mA,
                                             const float* __restrict__ mB,
                                             float c[2][NF][4]){
  #pragma unroll
  for (int k8=0;k8<K8;k8++){
    uint32_t a[2][4];
    #pragma unroll
    for (int rf=0; rf<2; rf++){
      float2 v0 = *(const float2*)(mA + rf*16*STRIDE + k8*8);
      float2 v1 = *(const float2*)(mA + rf*16*STRIDE + 8*STRIDE + k8*8);
      a[rf][0]=__float_as_uint(v0.x); a[rf][2]=__float_as_uint(v0.y);
      a[rf][1]=__float_as_uint(v1.x); a[rf][3]=__float_as_uint(v1.y);
    }
    #pragma unroll
    for (int nf=0;nf<NF;nf++){
      float2 bv = *(const float2*)(mB + nf*8*STRIDE + k8*8);
      mma8(c[0][nf], a[0], __float_as_uint(bv.x), __float_as_uint(bv.y));
      mma8(c[1][nf], a[1], __float_as_uint(bv.x), __float_as_uint(bv.y));
    }
  }
}

// ---------------- init ----------------
__global__ void k_init(const float* __restrict__ bsc){
  int i = blockIdx.x*blockDim.x + threadIdx.x;
  if (i < B_*N_){ g_vg2[i] = 0.f; g_sc[i] = bsc[0]; }
  if (i < B_*H_){ g_A1[i]=0.f; g_A2[i]=0.f; }
  if (i < B_*NH_*N_){ g_Z[i]=0.f; g_r1[i]=0.f; g_r2[i]=0.f; }
}

// ---------------- preconv ----------------
__global__ void k_preconv(const float* __restrict__ x, const int* __restrict__ pp,
                          const float* __restrict__ W0, const float* __restrict__ W1,
                          const float* __restrict__ W2, const float* __restrict__ W3,
                          const float* __restrict__ W4){
  const int XT8 = B_*N_*H_/8;
  const int WT8 = H_*H_/8;
  const int H8 = H_/8;
  int i = blockIdx.x*blockDim.x + threadIdx.x;
  if (i < XT8){
    const float4* s = (const float4*)x + (size_t)i*2;
    perm_store(g_xr + (size_t)i*8, s[0], s[1]);
  } else if (i < 2*XT8){
    int j = i - XT8;
    int hh8 = j % H8;
    int nn  = (j / H8) % N_;
    int b   = j / (N_*H8);
    bool single = (nn==0) || (nn>=2 && pp[b*N_+nn-2]==1);
    int np = (nn+1)&(N_-1), nm = (nn+N_-1)&(N_-1);
    const float* bp = x + ((size_t)b*N_ + np)*H_ + hh8*8;
    float4 xa = *(const float4*)bp, xb = *(const float4*)(bp+4);
    if (!single){
      const float* bm = x + ((size_t)b*N_ + nm)*H_ + hh8*8;
      float4 ya = *(const float4*)bm, yb = *(const float4*)(bm+4);
      xa.x=0.5f*(xa.x+ya.x); xa.y=0.5f*(xa.y+ya.y); xa.z=0.5f*(xa.z+ya.z); xa.w=0.5f*(xa.w+ya.w);
      xb.x=0.5f*(xb.x+yb.x); xb.y=0.5f*(xb.y+yb.y); xb.z=0.5f*(xb.z+yb.z); xb.w=0.5f*(xb.w+yb.w);
    }
    perm_store(g_vi + (size_t)j*8, xa, xb);
  } else {
    int j = i - 2*XT8;
    if (j < 5*WT8){
      int w = j / WT8, o = j - w*WT8;
      int row = o / H8, rem = o - row*H8;
      int srow = row;
      if (w==2 || w==3){
        int r8 = row & 7;
        srow = (row & ~7) | ((r8&1)*4 + (r8>>1));
      }
      const float* src = (w==0)?W0:(w==1)?W1:(w==2)?W2:(w==3)?W3:W4;
      const float4* s = (const float4*)(src + (size_t)srow*H_ + rem*8);
      perm_store(g_Wr + (size_t)w*H_*H_ + (size_t)o*8, s[0], s[1]);
    }
  }
}

// ---------------- merged projections ----------------
__global__ __launch_bounds__(256,2) void k_proj(
    const float* __restrict__ b_var, const float* __restrict__ b_sym,
    const float* __restrict__ b_q, const float* __restrict__ b_k, const float* __restrict__ b_v,
    const float* __restrict__ Wsc,
    float* __restrict__ Qb, float* __restrict__ Kb, float* __restrict__ Vb){
  extern __shared__ float sm[];
  int mode = blockIdx.z;
  const float* A = (mode==0) ? g_vi : g_xr;
  const float* W = g_Wr + (size_t)mode*H_*H_;
  const float* bias; float* C=nullptr; float alpha=1.f; const float* wsc=nullptr;
  switch(mode){
    case 0: bias=b_var; wsc=Wsc;    break;
    case 1: bias=b_sym; wsc=Wsc+H_; break;
    case 2: bias=b_q;   C=Qb; alpha=0.125f*LOG2E; break;
    case 3: bias=b_k;   C=Kb; break;
    default:bias=b_v;   C=Vb; break;
  }
  int tid=threadIdx.x, lane=tid&31, wid=tid>>5;
  int wr=wid&3, wc=wid>>2;
  int m0 = blockIdx.y*128, n0 = blockIdx.x*128;
  int sr = tid>>3, sq = (tid&7)*4;
  uint32_t smBase = (uint32_t)__cvta_generic_to_shared(sm);
  uint32_t sA0 = smBase + (sr*STP + sq)*4;
  uint32_t sA1 = sA0 + 128*STP*4;
  uint32_t sB0 = sA0 + 2*128*STP*4;
  uint32_t sB1 = sA0 + 3*128*STP*4;
  const float* gA = A + (size_t)(m0+sr)*H_ + sq;
  const float* gW = W + (size_t)(n0+sr)*H_ + sq;
  int mrow = wr*32 + (lane>>2), mc = 2*(lane&3);
  int brow = wc*64 + (lane>>2);
  const float* mA0 = sm + mrow*STP + mc;
  const float* mA1 = mA0 + 128*STP;
  const float* mB0 = sm + 2*128*STP + brow*STP + mc;
  const float* mB1 = mB0 + 128*STP;
  #define STAGE_P(sa, sb) do { \
    cpa16s((sa),            gA); \
    cpa16s((sa)+32*STP*4,   gA+32*H_); \
    cpa16s((sa)+64*STP*4,   gA+64*H_); \
    cpa16s((sa)+96*STP*4,   gA+96*H_); \
    cpa16s((sb),            gW); \
    cpa16s((sb)+32*STP*4,   gW+32*H_); \
    cpa16s((sb)+64*STP*4,   gW+64*H_); \
    cpa16s((sb)+96*STP*4,   gW+96*H_); \
    gA += KT; gW += KT; cp_commit(); } while(0)
  STAGE_P(sA0, sB0);
  float c[2][8][4];
  #pragma unroll
  for(int i=0;i<2;i++)
    #pragma unroll
    for(int j=0;j<8;j++){ c[i][j][0]=0;c[i][j][1]=0;c[i][j][2]=0;c[i][j][3]=0; }
  #pragma unroll 1
  for (int kt2=0; kt2<NKT/2; kt2++){
    cp_wait0(); __syncthreads();
    STAGE_P(sA1, sB1);
    mma_tile_pre<STP,8,4>(mA0, mB0, c);
    cp_wait0(); __syncthreads();
    if (kt2 < NKT/2-1) STAGE_P(sA0, sB0);
    mma_tile_pre<STP,8,4>(mA1, mB1, c);
  }
  #undef STAGE_P
  int t = lane&3;
  if (mode<=1){
    float p[4] = {0,0,0,0};
    #pragma unroll
    for (int rf=0; rf<2; rf++){
      #pragma unroll
      for (int nf=0; nf<8; nf++){
        int col0 = n0 + wc*64 + nf*8 + 2*t;
        float w0 = wsc[col0], w1 = wsc[col0+1];
        float b0v = bias[col0], b1v = bias[col0+1];
        p[rf*2+0] += tanhf(c[rf][nf][0]+b0v)*w0 + tanhf(c[rf][nf][1]+b1v)*w1;
        p[rf*2+1] += tanhf(c[rf][nf][2]+b0v)*w0 + tanhf(c[rf][nf][3]+b1v)*w1;
      }
    }
    #pragma unroll
    for (int i=0;i<4;i++){
      float v = p[i];
      v += __shfl_xor_sync(0xffffffffu, v, 1);
      v += __shfl_xor_sync(0xffffffffu, v, 2);
      if (t==0)
        atomicAdd(&g_sc[m0 + wr*32 + (i>>1)*16 + (lane>>2) + (i&1)*8], v);
    }
  } else if (mode==4){
    #pragma unroll
    for (int rf=0; rf<2; rf++){
      int row = m0 + wr*32 + rf*16 + (lane>>2);
      #pragma unroll
      for (int nf=0; nf<8; nf++){
        int col0 = n0 + wc*64 + nf*8 + 2*t;
        float2 bv = *(const float2*)(bias + col0);
        *(float2*)(C + (size_t)row*H_ + col0)     = make_float2(c[rf][nf][0]+bv.x, c[rf][nf][1]+bv.y);
        *(float2*)(C + (size_t)(row+8)*H_ + col0) = make_float2(c[rf][nf][2]+bv.x, c[rf][nf][3]+bv.y);
      }
    }
  } else {
    #pragma unroll
    for (int rf=0; rf<2; rf++){
      int row = m0 + wr*32 + rf*16 + (lane>>2);
      #pragma unroll
      for (int nf=0; nf<8; nf++){
        int col = n0 + wc*64 + nf*8;
        float b0v = bias[col + t], b1v = bias[col + t + 4];
        *(float2*)(C + (size_t)row*H_ + col + 2*t) =
          make_float2(tf32r(alpha*(c[rf][nf][0]+b0v)), tf32r(alpha*(c[rf][nf][1]+b1v)));
        *(float2*)(C + (size_t)(row+8)*H_ + col + 2*t) =
          make_float2(tf32r(alpha*(c[rf][nf][2]+b0v)), tf32r(alpha*(c[rf][nf][3]+b1v)));
      }
    }
  }
}

// ---------------- attention pass 1 ----------------
__global__ __launch_bounds__(256,2) void k_attn1(){
  extern __shared__ float sm[];
  int tid=threadIdx.x, lane=tid&31, wid=tid>>5;
  int wr=wid&3, wc=wid>>2;
  int bh=blockIdx.x, b=bh/NH_, h=bh-b*NH_;
  int n0=blockIdx.y*128;
  const float* Q = g_Qb + (size_t)b*N_*H_ + h*64;
  const float* K = g_Kb + (size_t)b*N_*H_ + h*64;
  int sr = tid>>4, sq = (tid&15)*4;
  uint32_t smBase = (uint32_t)__cvta_generic_to_shared(sm);
  uint32_t sQ  = smBase + (sr*ST + sq)*4;
  uint32_t sK0 = sQ + 128*ST*4;
  uint32_t sK1 = sQ + 2*128*ST*4;
  const float* gQ = Q + (size_t)(n0+sr)*H_ + sq;
  const float* gK = K + (size_t)sr*H_ + sq;
  int mrow = wr*32 + (lane>>2), mc = 2*(lane&3);
  int brow = wc*64 + (lane>>2);
  const float* mQ  = sm + mrow*ST + mc;
  const float* mK0 = sm + 128*ST + brow*ST + mc;
  const float* mK1 = mK0 + 128*ST;
  #define STAGE_A(sdst) do { \
    cpa16s((sdst),           gK); \
    cpa16s((sdst)+16*ST*4,   gK+16*H_); \
    cpa16s((sdst)+32*ST*4,   gK+32*H_); \
    cpa16s((sdst)+48*ST*4,   gK+48*H_); \
    cpa16s((sdst)+64*ST*4,   gK+64*H_); \
    cpa16s((sdst)+80*ST*4,   gK+80*H_); \
    cpa16s((sdst)+96*ST*4,   gK+96*H_); \
    cpa16s((sdst)+112*ST*4,  gK+112*H_); \
    gK += 128*H_; cp_commit(); } while(0)
  #pragma unroll
  for (int it=0; it<8; it++)
    cpa16s(sQ + it*16*ST*4, gQ + it*16*H_);
  STAGE_A(sK0);
  float z[4]={0,0,0,0};
  #pragma unroll 1
  for (int mt2=0; mt2<4; mt2++){
    cp_wait0(); __syncthreads();
    STAGE_A(sK1);
    {
      float c[2][8][4];
      #pragma unroll
      for(int i=0;i<2;i++)
        #pragma unroll
        for(int j=0;j<8;j++){ c[i][j][0]=0;c[i][j][1]=0;c[i][j][2]=0;c[i][j][3]=0; }
      mma_tile_pre<ST,8,8>(mQ, mK0, c);
      #pragma unroll
      for (int rf=0; rf<2; rf++)
        #pragma unroll
        for (int nf=0; nf<8; nf++){
          z[rf*2+0] += fex2(c[rf][nf][0]) + fex2(c[rf][nf][1]);
          z[rf*2+1] += fex2(c[rf][nf][2]) + fex2(c[rf][nf][3]);
        }
    }
    cp_wait0(); __syncthreads();
    if (mt2 < 3) STAGE_A(sK0);
    {
      float c[2][8][4];
      #pragma unroll
      for(int i=0;i<2;i++)
        #pragma unroll
        for(int j=0;j<8;j++){ c[i][j][0]=0;c[i][j][1]=0;c[i][j][2]=0;c[i][j][3]=0; }
      mma_tile_pre<ST,8,8>(mQ, mK1, c);
      #pragma unroll
      for (int rf=0; rf<2; rf++)
        #pragma unroll
        for (int nf=0; nf<8; nf++){
          z[rf*2+0] += fex2(c[rf][nf][0]) + fex2(c[rf][nf][1]);
          z[rf*2+1] += fex2(c[rf][nf][2]) + fex2(c[rf][nf][3]);
        }
    }
  }
  #undef STAGE_A
  #pragma unroll
  for (int i=0;i<4;i++){
    float v = z[i];
    v += __shfl_xor_sync(0xffffffffu, v, 1);
    v += __shfl_xor_sync(0xffffffffu, v, 2);
    if ((lane&3)==0)
      atomicAdd(&g_Z[(size_t)bh*N_ + n0 + wr*32 + (i>>1)*16 + (lane>>2) + (i&1)*8], v);
  }
}

// ---------------- cross scores ----------------
__global__ __launch_bounds__(128) void k_cross(const float* __restrict__ x, const float* __restrict__ Wc,
                                               const float* __restrict__ bc, const int* __restrict__ occ){
  int pid = blockIdx.x;
  int b = pid / M_;
  int o0 = occ[pid*2], o1 = occ[pid*2+1];
  const float* x0 = x + ((size_t)b*N_+o0)*H_;
  const float* x1 = x + ((size_t)b*N_+o1)*H_;
  float p = 0.f;
  for (int h=threadIdx.x; h<H_; h+=128) p += 0.5f*(x0[h]+x1[h])*Wc[h];
  for (int o=16;o;o>>=1) p += __shfl_xor_sync(0xffffffffu, p, o);
  __shared__ float red[4];
  if ((threadIdx.x&31)==0) red[threadIdx.x>>5] = p;
  __syncthreads();
  if (threadIdx.x==0){
    float t = d_lrelu(bc[0] + red[0]+red[1]+red[2]+red[3]);
    atomicAdd(&g_vg2[b*N_+o0], t*t);
    atomicAdd(&g_vg2[b*N_+o1], t*t);
  }
}

// ---------------- band + sumw + coef ----------------
__global__ __launch_bounds__(1024) void k_post(const int* __restrict__ pp){
  __shared__ float ab[N_], wt[N_], red[32];
  __shared__ float swv;
  int b = blockIdx.x, n = threadIdx.x;
  const int* P = pp + b*N_;
  const float* s = g_sc + b*N_;
  float a = 0.f;
  if (n < N_-1){
    float sl1 = d_pred(P,n+1) ? d_lrelu(s[n+1]) : 0.f;
    bool up0 = d_pred(P,n) && (n<=1 || !d_single(P,n));
    float su0 = up0 ? d_lrelu(s[n]) : 0.f;
    a = sl1 + su0;
  }
  ab[n] = a; g_ab[b*N_+n] = a;
  bool up = d_pred(P,n) && (n<=1 || !d_single(P,n));
  bool tr = up && (n>=1);
  float w = d_pred(P,n) ? (tr?3.f:2.f) : 0.f;
  wt[n] = w;
  float v = w;
  for (int o=16;o;o>>=1) v += __shfl_xor_sync(0xffffffffu, v, o);
  if ((n&31)==0) red[n>>5] = v;
  __syncthreads();
  if (n < 32){
    float t2 = red[n];
    for (int o=16;o;o>>=1) t2 += __shfl_xor_sync(0xffffffffu, t2, o);
    if (n==0){ swv = t2; g_sumw[b] = t2; }
  }
  __syncthreads();
  float am1 = (n>=1) ? ab[n-1] : 0.f;
  g_dg[b*N_+n] = 0.8f*(am1*am1 + a*a) + g_vg2[b*N_+n];
  float sw = swv;
  int nm = (n+N_-1)&(N_-1), np = (n+1)&(N_-1);
  float c1 = wt[nm]*(d_single(P,nm)?1.f:0.5f) + wt[np]*(d_single(P,np)?0.f:0.5f);
  g_c1[b*N_+n] = c1 / sw;
  g_c2[b*N_+n] = wt[n] / sw;
}

// ---------------- band correction ----------------
__global__ __launch_bounds__(256) void k_bandfix(){
  int bh = blockIdx.x, b = bh/NH_, h = bh - b*NH_;
  int wid = threadIdx.x>>5, lane = threadIdx.x&31;
  int n = blockIdx.y*8 + wid;
  const float* Qr = g_Qb + ((size_t)b*N_ + n)*H_ + h*64;
  const float* Kp = g_Kb + (size_t)b*N_*H_ + h*64;
  const float* ab = g_ab + b*N_;
  float q0 = Qr[lane], q1 = Qr[lane+32];
  float anm2=(n>=2)?ab[n-2]:0.f, anm1=(n>=1)?ab[n-1]:0.f;
  float an=ab[n], anp1=(n<N_-1)?ab[n+1]:0.f;
  float biasv[5] = { LOG2E*0.8f*anm2*anm1, LOG2E*0.2f*anm1, LOG2E*g_dg[b*N_+n],
                     LOG2E*0.2f*an, LOG2E*0.8f*an*anp1 };
  float delta[5];
  float dz = 0.f;
  #pragma unroll
  for (int d=-2; d<=2; d++){
    int m = n + d;
    delta[d+2] = 0.f;
    if ((unsigned)m < (unsigned)N_){
      const float* Kr = Kp + (size_t)m*H_;
      float s = q0*Kr[lane] + q1*Kr[lane+32];
      #pragma unroll
      for (int o=16;o;o>>=1) s += __shfl_xor_sync(0xffffffffu, s, o);
      delta[d+2] = fex2(s + biasv[d+2]) - fex2(s);
      dz += delta[d+2];
    }
  }
  float Zf = g_Z[(size_t)bh*N_ + n] + dz;
  if (lane==0) g_Z[(size_t)bh*N_ + n] = Zf;
  float w1 = g_c1[b*N_+n] / Zf;
  float w2 = g_c2[b*N_+n] / Zf;
  if (lane==0 && (w1 != 0.f || w2 != 0.f)){
    #pragma unroll
    for (int d=-2; d<=2; d++){
      int m = n + d;
      if ((unsigned)m < (unsigned)N_ && delta[d+2] != 0.f){
        atomicAdd(&g_r1[(size_t)bh*N_ + m], w1*delta[d+2]);
        atomicAdd(&g_r2[(size_t)bh*N_ + m], w2*delta[d+2]);
      }
    }
  }
}

// ---------------- attention pass 2 ----------------
__global__ __launch_bounds__(256,2) void k_attn2(){
  extern __shared__ float sm[];
  float* colp = sm + 3*128*ST;
  int tid=threadIdx.x, lane=tid&31, wid=tid>>5;
  int wr=wid&3, wc=wid>>2;
  int bh=blockIdx.x, b=bh/NH_, h=bh-b*NH_;
  int m0=blockIdx.y*128;
  const float* Q = g_Qb + (size_t)b*N_*H_ + h*64;
  const float* K = g_Kb + (size_t)b*N_*H_ + h*64;
  int sr = tid>>4, sq = (tid&15)*4;
  uint32_t smBase = (uint32_t)__cvta_generic_to_shared(sm);
  uint32_t sKr = smBase + (sr*ST + sq)*4;
  uint32_t sQ0 = sKr + 128*ST*4;
  uint32_t sQ1 = sKr + 2*128*ST*4;
  const float* gKr = K + (size_t)(m0+sr)*H_ + sq;
  const float* gQ  = Q + (size_t)sr*H_ + sq;
  int mrow = wr*32 + (lane>>2), mc = 2*(lane&3);
  int brow = wc*64 + (lane>>2);
  const float* mK  = sm + mrow*ST + mc;
  const float* mQ0 = sm + 128*ST + brow*ST + mc;
  const float* mQ1 = mQ0 + 128*ST;
  int nctr = 0;
  #define STAGE_Q(sdst, cbuf) do { \
    cpa16s((sdst),           gQ); \
    cpa16s((sdst)+16*ST*4,   gQ+16*H_); \
    cpa16s((sdst)+32*ST*4,   gQ+32*H_); \
    cpa16s((sdst)+48*ST*4,   gQ+48*H_); \
    cpa16s((sdst)+64*ST*4,   gQ+64*H_); \
    cpa16s((sdst)+80*ST*4,   gQ+80*H_); \
    cpa16s((sdst)+96*ST*4,   gQ+96*H_); \
    cpa16s((sdst)+112*ST*4,  gQ+112*H_); \
    gQ += 128*H_; \
    if (tid < 128){ \
      int n = nctr*128 + tid; \
      float iz = 1.f / g_Z[(size_t)bh*N_ + n]; \
      colp[(cbuf)*256 + tid]       = g_c1[b*N_+n]*iz; \
      colp[(cbuf)*256 + 128 + tid] = g_c2[b*N_+n]*iz; \
    } \
    nctr++; cp_commit(); } while(0)
  #pragma unroll
  for (int it=0; it<8; it++)
    cpa16s(sKr + it*16*ST*4, gKr + it*16*H_);
  STAGE_Q(sQ0, 0);
  float r1[4]={0,0,0,0}, r2[4]={0,0,0,0};
  #pragma unroll 1
  for (int nt2=0; nt2<4; nt2++){
    cp_wait0(); __syncthreads();
    STAGE_Q(sQ1, 1);
    {
      float c[2][8][4];
      #pragma unroll
      for(int i=0;i<2;i++)
        #pragma unroll
        for(int j=0;j<8;j++){ c[i][j][0]=0;c[i][j][1]=0;c[i][j][2]=0;c[i][j][3]=0; }
      mma_tile_pre<ST,8,8>(mK, mQ0, c);
      const float* cp0 = colp;
      #pragma unroll
      for (int rf=0; rf<2; rf++)
        #pragma unroll
        for (int nf=0; nf<8; nf++){
          int lc0 = wc*64 + nf*8 + 2*(lane&3);
          float w1a = cp0[lc0], w1b = cp0[lc0+1];
          float w2a = cp0[128+lc0], w2b = cp0[128+lc0+1];
          float P0 = fex2(c[rf][nf][0]), P1 = fex2(c[rf][nf][1]);
          float P2 = fex2(c[rf][nf][2]), P3 = fex2(c[rf][nf][3]);
          r1[rf*2+0] += w1a*P0 + w1b*P1;  r2[rf*2+0] += w2a*P0 + w2b*P1;
          r1[rf*2+1] += w1a*P2 + w1b*P3;  r2[rf*2+1] += w2a*P2 + w2b*P3;
        }
    }
    cp_wait0(); __syncthreads();
    if (nt2 < 3) STAGE_Q(sQ0, 0);
    {
      float c[2][8][4];
      #pragma unroll
      for(int i=0;i<2;i++)
        #pragma unroll
        for(int j=0;j<8;j++){ c[i][j][0]=0;c[i][j][1]=0;c[i][j][2]=0;c[i][j][3]=0; }
      mma_tile_pre<ST,8,8>(mK, mQ1, c);
      const float* cp0 = colp + 256;
      #pragma unroll
      for (int rf=0; rf<2; rf++)
        #pragma unroll
        for (int nf=0; nf<8; nf++){
          int lc0 = wc*64 + nf*8 + 2*(lane&3);
          float w1a = cp0[lc0], w1b = cp0[lc0+1];
          float w2a = cp0[128+lc0], w2b = cp0[128+lc0+1];
          float P0 = fex2(c[rf][nf][0]), P1 = fex2(c[rf][nf][1]);
          float P2 = fex2(c[rf][nf][2]), P3 = fex2(c[rf][nf][3]);
          r1[rf*2+0] += w1a*P0 + w1b*P1;  r2[rf*2+0] += w2a*P0 + w2b*P1;
          r1[rf*2+1] += w1a*P2 + w1b*P3;  r2[rf*2+1] += w2a*P2 + w2b*P3;
        }
    }
  }
  #undef STAGE_Q
  #pragma unroll
  for (int i=0;i<4;i++){
    float v1 = r1[i], v2 = r2[i];
    v1 += __shfl_xor_sync(0xffffffffu, v1, 1);
    v1 += __shfl_xor_sync(0xffffffffu, v1, 2);
    v2 += __shfl_xor_sync(0xffffffffu, v2, 1);
    v2 += __shfl_xor_sync(0xffffffffu, v2, 2);
    if ((lane&3)==0){
      size_t o = (size_t)bh*N_ + m0 + wr*32 + (i>>1)*16 + (lane>>2) + (i&1)*8;
      atomicAdd(&g_r1[o], v1);
      atomicAdd(&g_r2[o], v2);
    }
  }
}

// ---------------- A = r @ V ----------------
__global__ __launch_bounds__(768) void k_matvec(){
  int b = blockIdx.x, f = threadIdx.x, h = f >> 6;
  int m0 = blockIdx.y*64;
  const float* r1 = g_r1 + ((size_t)b*NH_+h)*N_;
  const float* r2 = g_r2 + ((size_t)b*NH_+h)*N_;
  float a1=0.f, a2=0.f;
  for (int m=m0; m<m0+64; m++){
    float vv = g_Vb[((size_t)b*N_+m)*H_+f];
    a1 += r1[m]*vv; a2 += r2[m]*vv;
  }
  atomicAdd(&g_A1[b*H_+f], a1);
  atomicAdd(&g_A2[b*H_+f], a2);
}

// ---------------- final GEMVs: coalesced warp-per-output ----------------
// k_final1: u = Wo @ A + bo  (per batch, two RHS)
__global__ __launch_bounds__(256) void k_final1(const float* __restrict__ Wo, const float* __restrict__ bo){
  __shared__ float A1s[H_], A2s[H_];
  int b = blockIdx.x, tile = blockIdx.y;
  int tid = threadIdx.x, lane = tid&31, w = tid>>5;
  for (int i=tid; i<H_; i+=256){ A1s[i]=g_A1[b*H_+i]; A2s[i]=g_A2[b*H_+i]; }
  __syncthreads();
  #pragma unroll 1
  for (int oo=0; oo<16; oo++){
    int o = tile*128 + w*16 + oo;
    const float* wr = Wo + (size_t)o*H_;
    float u1=0.f, u2=0.f;
    #pragma unroll
    for (int k=0; k<H_/32; k++){
      float wv = wr[lane + k*32];
      u1 += wv*A1s[lane + k*32];
      u2 += wv*A2s[lane + k*32];
    }
    #pragma unroll
    for (int off=16; off; off>>=1){
      u1 += __shfl_xor_sync(0xffffffffu, u1, off);
      u2 += __shfl_xor_sync(0xffffffffu, u2, off);
    }
    if (lane==0){
      g_u1[b*H_+o] = u1 + bo[o];
      g_u2[b*H_+o] = u2 + bo[o];
    }
  }
}

// k_final2: pm = Wa @ [u1;u2] + ba
__global__ __launch_bounds__(256) void k_final2(const float* __restrict__ Wa, const float* __restrict__ ba){
  __shared__ float u1s[H_], u2s[H_];
  int b = blockIdx.x, tile = blockIdx.y;
  int tid = threadIdx.x, lane = tid&31, w = tid>>5;
  for (int i=tid; i<H_; i+=256){ u1s[i]=g_u1[b*H_+i]; u2s[i]=g_u2[b*H_+i]; }
  __syncthreads();
  #pragma unroll 1
  for (int oo=0; oo<16; oo++){
    int o = tile*128 + w*16 + oo;
    const float* wa = Wa + (size_t)o*2*H_;
    float p = 0.f;
    #pragma unroll
    for (int k=0; k<H_/32; k++){
      p += wa[lane + k*32]*u1s[lane + k*32];
      p += wa[H_ + lane + k*32]*u2s[lane + k*32];
    }
    #pragma unroll
    for (int off=16; off; off>>=1)
      p += __shfl_xor_sync(0xffffffffu, p, off);
    if (lane==0) g_pm[b*H_+o] = p + ba[o];
  }
}

__global__ void k_bcast(float* __restrict__ out){
  int idx = blockIdx.x*blockDim.x + threadIdx.x;
  if (idx >= B_*N_*H_) return;
  int f = idx % H_;
  int b = idx / (N_*H_);
  out[idx] = g_pm[b*H_+f];
}

// ---------------- launch ----------------
extern "C" void kernel_launch(void* const* d_in, const int* in_sizes, int n_in,
                              void* d_out, int out_size){
  (void)in_sizes; (void)n_in; (void)out_size;
  const float* x      = (const float*)d_in[0];
  const float* W_var  = (const float*)d_in[3];
  const float* b_var  = (const float*)d_in[4];
  const float* W_sym  = (const float*)d_in[5];
  const float* b_sym  = (const float*)d_in[6];
  const float* W_sc   = (const float*)d_in[7];
  const float* b_scb  = (const float*)d_in[8];
  const float* W_cr   = (const float*)d_in[9];
  const float* b_cr   = (const float*)d_in[10];
  const float* W_atom = (const float*)d_in[11];
  const float* b_atom = (const float*)d_in[12];
  const float* W_q    = (const float*)d_in[13];
  const float* b_q    = (const float*)d_in[14];
  const float* W_k    = (const float*)d_in[15];
  const float* b_k    = (const float*)d_in[16];
  const float* W_v    = (const float*)d_in[17];
  const float* b_v    = (const float*)d_in[18];
  const float* W_o    = (const float*)d_in[19];
  const float* b_o    = (const float*)d_in[20];
  const int*   pp     = (const int*)d_in[21];
  const int*   occ    = (const int*)d_in[24];
  float* out = (float*)d_out;

  float *p_Q, *p_K, *p_V;
  cudaGetSymbolAddress((void**)&p_Q, g_Qb);
  cudaGetSymbolAddress((void**)&p_K, g_Kb);
  cudaGetSymbolAddress((void**)&p_V, g_Vb);

  const int PROJ_SMEM  = (4*128*STP)*4;
  const int ATTN1_SMEM = (3*128*ST)*4;
  const int ATTN2_SMEM = (3*128*ST + 512)*4;
  static bool attr_done = false;
  if (!attr_done){
    cudaFuncSetAttribute(k_proj,  cudaFuncAttributeMaxDynamicSharedMemorySize, PROJ_SMEM);
    cudaFuncSetAttribute(k_attn1, cudaFuncAttributeMaxDynamicSharedMemorySize, ATTN1_SMEM);
    cudaFuncSetAttribute(k_attn2, cudaFuncAttributeMaxDynamicSharedMemorySize, ATTN2_SMEM);
    attr_done = true;
  }

  // launch order: ncu capture slot (#4) = k_attn1
  k_init<<<(B_*NH_*N_+255)/256, 256>>>(b_scb);                                   // 1
  const int PRE = 2*(B_*N_*H_/8) + 5*(H_*H_/8);
  k_preconv<<<(PRE+255)/256, 256>>>(x, pp, W_var, W_sym, W_q, W_k, W_v);         // 2
  dim3 gp(H_/128, (B_*N_)/128, 5);
  k_proj<<<gp, 256, PROJ_SMEM>>>(b_var, b_sym, b_q, b_k, b_v, W_sc, p_Q, p_K, p_V); // 3
  dim3 ga(B_*NH_, N_/128);
  k_attn1<<<ga, 256, ATTN1_SMEM>>>();                                            // 4 <- profiled
  k_cross<<<B_*M_, 128>>>(x, W_cr, b_cr, occ);                                   // 5
  k_post<<<B_, 1024>>>(pp);                                                      // 6
  dim3 gbf(B_*NH_, N_/8);
  k_bandfix<<<gbf, 256>>>();                                                     // 7
  k_attn2<<<ga, 256, ATTN2_SMEM>>>();                                            // 8
  dim3 gmv(B_, 16);
  k_matvec<<<gmv, 768>>>();                                                      // 9
  dim3 gf(B_, H_/128);
  k_final1<<<gf, 256>>>(W_o, b_o);                                               // 10
  k_final2<<<gf, 256>>>(W_atom, b_atom);                                         // 11
  k_bcast<<<(B_*N_*H_+255)/256, 256>>>(out);                                     // 12
}

// round 14
// speedup vs baseline: 2.2674x; 1.0075x over previous
#include <cuda_runtime.h>
#include <mma.h>
#include <cstdint>
using namespace nvcuda;

#define B_ 8
#define N_ 1024
#define H_ 768
#define NH_ 12
#define M_ 256
#define ST 72
#define STP 40
#define KT 32
#define NKT 24
#define LOG2E 1.4426950408889634f

// ---------------- scratch ----------------
__device__ float g_xr[B_*N_*H_];
__device__ float g_vi[B_*N_*H_];
__device__ float g_Wr[5*H_*H_];
__device__ float g_Qb[B_*N_*H_];
__device__ float g_Kb[B_*N_*H_];
__device__ float g_Vb[B_*N_*H_];
__device__ float g_sc[B_*N_];
__device__ float g_vg2[B_*N_];
__device__ float g_ab[B_*N_];
__device__ float g_dg[B_*N_];
__device__ float g_sumw[B_];
__device__ float g_c1[B_*N_];
__device__ float g_c2[B_*N_];
__device__ float g_Z[B_*NH_*N_];
__device__ float g_r1[B_*NH_*N_];
__device__ float g_r2[B_*NH_*N_];
__device__ float g_A1[B_*H_];
__device__ float g_A2[B_*H_];
__device__ float g_u1[B_*H_];
__device__ float g_u2[B_*H_];

__device__ __forceinline__ bool d_pred(const int* P, int i){ return P[i]==1; }
__device__ __forceinline__ bool d_single(const int* P, int i){ return (i==0) || (i>=2 && P[i-2]==1); }
__device__ __forceinline__ float d_lrelu(float t){ return t >= 0.f ? t : 0.02f*t; }
__device__ __forceinline__ float tf32r(float x){ return wmma::__float_to_tf32(x); }
__device__ __forceinline__ float fex2(float x){ float y; asm("ex2.approx.f32 %0, %1;" : "=f"(y) : "f"(x)); return y; }
__device__ __forceinline__ float ftanh(float x){ float y; asm("tanh.approx.f32 %0, %1;" : "=f"(y) : "f"(x)); return y; }

__device__ __forceinline__ void perm_store(float* dst, float4 a, float4 b){
  float4 o0 = make_float4(tf32r(a.x), tf32r(b.x), tf32r(a.y), tf32r(b.y));
  float4 o1 = make_float4(tf32r(a.z), tf32r(b.z), tf32r(a.w), tf32r(b.w));
  *(float4*)dst = o0; *(float4*)(dst+4) = o1;
}

// ---------------- cp.async ----------------
__device__ __forceinline__ void cpa16s(uint32_t s, const float* g){
  asm volatile("cp.async.cg.shared.global [%0], [%1], 16;\n" :: "r"(s), "l"(g));
}
__device__ __forceinline__ void cp_commit(){ asm volatile("cp.async.commit_group;\n"); }
__device__ __forceinline__ void cp_wait0(){ asm volatile("cp.async.wait_group 0;\n"); }

// ---------------- m16n8k8 tf32 mma.sync ----------------
__device__ __forceinline__ void mma8(float c[4], const uint32_t a[4], uint32_t b0, uint32_t b1){
  asm volatile(
    "mma.sync.aligned.m16n8k8.row.col.f32.tf32.tf32.f32 "
    "{%0,%1,%2,%3}, {%4,%5,%6,%7}, {%8,%9}, {%0,%1,%2,%3};\n"
    : "+f"(c[0]), "+f"(c[1]), "+f"(c[2]), "+f"(c[3])
    : "r"(a[0]), "r"(a[1]), "r"(a[2]), "r"(a[3]), "r"(b0), "r"(b1));
}

template<int STRIDE, int NF, int K8>
__device__ __forceinline__ void mma_tile_pre(const float* __restrict__ mA,
                                             const float* __restrict__ mB,
                                             float c[2][NF][4]){
  #pragma unroll
  for (int k8=0;k8<K8;k8++){
    uint32_t a[2][4];
    #pragma unroll
    for (int rf=0; rf<2; rf++){
      float2 v0 = *(const float2*)(mA + rf*16*STRIDE + k8*8);
      float2 v1 = *(const float2*)(mA + rf*16*STRIDE + 8*STRIDE + k8*8);
      a[rf][0]=__float_as_uint(v0.x); a[rf][2]=__float_as_uint(v0.y);
      a[rf][1]=__float_as_uint(v1.x); a[rf][3]=__float_as_uint(v1.y);
    }
    #pragma unroll
    for (int nf=0;nf<NF;nf++){
      float2 bv = *(const float2*)(mB + nf*8*STRIDE + k8*8);
      mma8(c[0][nf], a[0], __float_as_uint(bv.x), __float_as_uint(bv.y));
      mma8(c[1][nf], a[1], __float_as_uint(bv.x), __float_as_uint(bv.y));
    }
  }
}

// ---------------- init ----------------
__global__ void k_init(const float* __restrict__ bsc){
  int i = blockIdx.x*blockDim.x + threadIdx.x;
  if (i < B_*N_){ g_vg2[i] = 0.f; g_sc[i] = bsc[0]; }
  if (i < B_*H_){ g_A1[i]=0.f; g_A2[i]=0.f; }
  if (i < B_*NH_*N_){ g_Z[i]=0.f; g_r1[i]=0.f; g_r2[i]=0.f; }
}

// ---------------- preconv ----------------
__global__ void k_preconv(const float* __restrict__ x, const int* __restrict__ pp,
                          const float* __restrict__ W0, const float* __restrict__ W1,
                          const float* __restrict__ W2, const float* __restrict__ W3,
                          const float* __restrict__ W4){
  const int XT8 = B_*N_*H_/8;
  const int WT8 = H_*H_/8;
  const int H8 = H_/8;
  int i = blockIdx.x*blockDim.x + threadIdx.x;
  if (i < XT8){
    const float4* s = (const float4*)x + (size_t)i*2;
    perm_store(g_xr + (size_t)i*8, s[0], s[1]);
  } else if (i < 2*XT8){
    int j = i - XT8;
    int hh8 = j % H8;
    int nn  = (j / H8) % N_;
    int b   = j / (N_*H8);
    bool single = (nn==0) || (nn>=2 && pp[b*N_+nn-2]==1);
    int np = (nn+1)&(N_-1), nm = (nn+N_-1)&(N_-1);
    const float* bp = x + ((size_t)b*N_ + np)*H_ + hh8*8;
    float4 xa = *(const float4*)bp, xb = *(const float4*)(bp+4);
    if (!single){
      const float* bm = x + ((size_t)b*N_ + nm)*H_ + hh8*8;
      float4 ya = *(const float4*)bm, yb = *(const float4*)(bm+4);
      xa.x=0.5f*(xa.x+ya.x); xa.y=0.5f*(xa.y+ya.y); xa.z=0.5f*(xa.z+ya.z); xa.w=0.5f*(xa.w+ya.w);
      xb.x=0.5f*(xb.x+yb.x); xb.y=0.5f*(xb.y+yb.y); xb.z=0.5f*(xb.z+yb.z); xb.w=0.5f*(xb.w+yb.w);
    }
    perm_store(g_vi + (size_t)j*8, xa, xb);
  } else {
    int j = i - 2*XT8;
    if (j < 5*WT8){
      int w = j / WT8, o = j - w*WT8;
      int row = o / H8, rem = o - row*H8;
      int srow = row;
      if (w==2 || w==3){
        int r8 = row & 7;
        srow = (row & ~7) | ((r8&1)*4 + (r8>>1));
      }
      const float* src = (w==0)?W0:(w==1)?W1:(w==2)?W2:(w==3)?W3:W4;
      const float4* s = (const float4*)(src + (size_t)srow*H_ + rem*8);
      perm_store(g_Wr + (size_t)w*H_*H_ + (size_t)o*8, s[0], s[1]);
    }
  }
}

// ---------------- merged projections ----------------
__global__ __launch_bounds__(256,2) void k_proj(
    const float* __restrict__ b_var, const float* __restrict__ b_sym,
    const float* __restrict__ b_q, const float* __restrict__ b_k, const float* __restrict__ b_v,
    const float* __restrict__ Wsc,
    float* __restrict__ Qb, float* __restrict__ Kb, float* __restrict__ Vb){
  extern __shared__ float sm[];
  int mode = blockIdx.z;
  const float* A = (mode==0) ? g_vi : g_xr;
  const float* W = g_Wr + (size_t)mode*H_*H_;
  const float* bias; float* C=nullptr; float alpha=1.f; const float* wsc=nullptr;
  switch(mode){
    case 0: bias=b_var; wsc=Wsc;    break;
    case 1: bias=b_sym; wsc=Wsc+H_; break;
    case 2: bias=b_q;   C=Qb; alpha=0.125f*LOG2E; break;
    case 3: bias=b_k;   C=Kb; break;
    default:bias=b_v;   C=Vb; break;
  }
  int tid=threadIdx.x, lane=tid&31, wid=tid>>5;
  int wr=wid&3, wc=wid>>2;
  int m0 = blockIdx.y*128, n0 = blockIdx.x*128;
  int sr = tid>>3, sq = (tid&7)*4;
  uint32_t smBase = (uint32_t)__cvta_generic_to_shared(sm);
  uint32_t sA0 = smBase + (sr*STP + sq)*4;
  uint32_t sA1 = sA0 + 128*STP*4;
  uint32_t sB0 = sA0 + 2*128*STP*4;
  uint32_t sB1 = sA0 + 3*128*STP*4;
  const float* gA = A + (size_t)(m0+sr)*H_ + sq;
  const float* gW = W + (size_t)(n0+sr)*H_ + sq;
  int mrow = wr*32 + (lane>>2), mc = 2*(lane&3);
  int brow = wc*64 + (lane>>2);
  const float* mA0 = sm + mrow*STP + mc;
  const float* mA1 = mA0 + 128*STP;
  const float* mB0 = sm + 2*128*STP + brow*STP + mc;
  const float* mB1 = mB0 + 128*STP;
  #define STAGE_P(sa, sb) do { \
    cpa16s((sa),            gA); \
    cpa16s((sa)+32*STP*4,   gA+32*H_); \
    cpa16s((sa)+64*STP*4,   gA+64*H_); \
    cpa16s((sa)+96*STP*4,   gA+96*H_); \
    cpa16s((sb),            gW); \
    cpa16s((sb)+32*STP*4,   gW+32*H_); \
    cpa16s((sb)+64*STP*4,   gW+64*H_); \
    cpa16s((sb)+96*STP*4,   gW+96*H_); \
    gA += KT; gW += KT; cp_commit(); } while(0)
  STAGE_P(sA0, sB0);
  float c[2][8][4];
  #pragma unroll
  for(int i=0;i<2;i++)
    #pragma unroll
    for(int j=0;j<8;j++){ c[i][j][0]=0;c[i][j][1]=0;c[i][j][2]=0;c[i][j][3]=0; }
  #pragma unroll 1
  for (int kt2=0; kt2<NKT/2; kt2++){
    cp_wait0(); __syncthreads();
    STAGE_P(sA1, sB1);
    mma_tile_pre<STP,8,4>(mA0, mB0, c);
    cp_wait0(); __syncthreads();
    if (kt2 < NKT/2-1) STAGE_P(sA0, sB0);
    mma_tile_pre<STP,8,4>(mA1, mB1, c);
  }
  #undef STAGE_P
  int t = lane&3;
  if (mode<=1){
    float p[4] = {0,0,0,0};
    #pragma unroll
    for (int rf=0; rf<2; rf++){
      #pragma unroll
      for (int nf=0; nf<8; nf++){
        int col0 = n0 + wc*64 + nf*8 + 2*t;
        float w0 = wsc[col0], w1 = wsc[col0+1];
        float b0v = bias[col0], b1v = bias[col0+1];
        p[rf*2+0] += ftanh(c[rf][nf][0]+b0v)*w0 + ftanh(c[rf][nf][1]+b1v)*w1;
        p[rf*2+1] += ftanh(c[rf][nf][2]+b0v)*w0 + ftanh(c[rf][nf][3]+b1v)*w1;
      }
    }
    #pragma unroll
    for (int i=0;i<4;i++){
      float v = p[i];
      v += __shfl_xor_sync(0xffffffffu, v, 1);
      v += __shfl_xor_sync(0xffffffffu, v, 2);
      if (t==0)
        atomicAdd(&g_sc[m0 + wr*32 + (i>>1)*16 + (lane>>2) + (i&1)*8], v);
    }
  } else if (mode==4){
    #pragma unroll
    for (int rf=0; rf<2; rf++){
      int row = m0 + wr*32 + rf*16 + (lane>>2);
      #pragma unroll
      for (int nf=0; nf<8; nf++){
        int col0 = n0 + wc*64 + nf*8 + 2*t;
        float2 bv = *(const float2*)(bias + col0);
        *(float2*)(C + (size_t)row*H_ + col0)     = make_float2(c[rf][nf][0]+bv.x, c[rf][nf][1]+bv.y);
        *(float2*)(C + (size_t)(row+8)*H_ + col0) = make_float2(c[rf][nf][2]+bv.x, c[rf][nf][3]+bv.y);
      }
    }
  } else {
    #pragma unroll
    for (int rf=0; rf<2; rf++){
      int row = m0 + wr*32 + rf*16 + (lane>>2);
      #pragma unroll
      for (int nf=0; nf<8; nf++){
        int col = n0 + wc*64 + nf*8;
        float b0v = bias[col + t], b1v = bias[col + t + 4];
        *(float2*)(C + (size_t)row*H_ + col + 2*t) =
          make_float2(tf32r(alpha*(c[rf][nf][0]+b0v)), tf32r(alpha*(c[rf][nf][1]+b1v)));
        *(float2*)(C + (size_t)(row+8)*H_ + col + 2*t) =
          make_float2(tf32r(alpha*(c[rf][nf][2]+b0v)), tf32r(alpha*(c[rf][nf][3]+b1v)));
      }
    }
  }
}

// ---------------- attention pass 1 ----------------
__global__ __launch_bounds__(256,2) void k_attn1(){
  extern __shared__ float sm[];
  int tid=threadIdx.x, lane=tid&31, wid=tid>>5;
  int wr=wid&3, wc=wid>>2;
  int bh=blockIdx.x, b=bh/NH_, h=bh-b*NH_;
  int n0=blockIdx.y*128;
  const float* Q = g_Qb + (size_t)b*N_*H_ + h*64;
  const float* K = g_Kb + (size_t)b*N_*H_ + h*64;
  int sr = tid>>4, sq = (tid&15)*4;
  uint32_t smBase = (uint32_t)__cvta_generic_to_shared(sm);
  uint32_t sQ  = smBase + (sr*ST + sq)*4;
  uint32_t sK0 = sQ + 128*ST*4;
  uint32_t sK1 = sQ + 2*128*ST*4;
  const float* gQ = Q + (size_t)(n0+sr)*H_ + sq;
  const float* gK = K + (size_t)sr*H_ + sq;
  int mrow = wr*32 + (lane>>2), mc = 2*(lane&3);
  int brow = wc*64 + (lane>>2);
  const float* mQ  = sm + mrow*ST + mc;
  const float* mK0 = sm + 128*ST + brow*ST + mc;
  const float* mK1 = mK0 + 128*ST;
  #define STAGE_A(sdst) do { \
    cpa16s((sdst),           gK); \
    cpa16s((sdst)+16*ST*4,   gK+16*H_); \
    cpa16s((sdst)+32*ST*4,   gK+32*H_); \
    cpa16s((sdst)+48*ST*4,   gK+48*H_); \
    cpa16s((sdst)+64*ST*4,   gK+64*H_); \
    cpa16s((sdst)+80*ST*4,   gK+80*H_); \
    cpa16s((sdst)+96*ST*4,   gK+96*H_); \
    cpa16s((sdst)+112*ST*4,  gK+112*H_); \
    gK += 128*H_; cp_commit(); } while(0)
  #pragma unroll
  for (int it=0; it<8; it++)
    cpa16s(sQ + it*16*ST*4, gQ + it*16*H_);
  STAGE_A(sK0);
  float z[4]={0,0,0,0};
  #pragma unroll 1
  for (int mt2=0; mt2<4; mt2++){
    cp_wait0(); __syncthreads();
    STAGE_A(sK1);
    {
      float c[2][8][4];
      #pragma unroll
      for(int i=0;i<2;i++)
        #pragma unroll
        for(int j=0;j<8;j++){ c[i][j][0]=0;c[i][j][1]=0;c[i][j][2]=0;c[i][j][3]=0; }
      mma_tile_pre<ST,8,8>(mQ, mK0, c);
      #pragma unroll
      for (int rf=0; rf<2; rf++)
        #pragma unroll
        for (int nf=0; nf<8; nf++){
          z[rf*2+0] += fex2(c[rf][nf][0]) + fex2(c[rf][nf][1]);
          z[rf*2+1] += fex2(c[rf][nf][2]) + fex2(c[rf][nf][3]);
        }
    }
    cp_wait0(); __syncthreads();
    if (mt2 < 3) STAGE_A(sK0);
    {
      float c[2][8][4];
      #pragma unroll
      for(int i=0;i<2;i++)
        #pragma unroll
        for(int j=0;j<8;j++){ c[i][j][0]=0;c[i][j][1]=0;c[i][j][2]=0;c[i][j][3]=0; }
      mma_tile_pre<ST,8,8>(mQ, mK1, c);
      #pragma unroll
      for (int rf=0; rf<2; rf++)
        #pragma unroll
        for (int nf=0; nf<8; nf++){
          z[rf*2+0] += fex2(c[rf][nf][0]) + fex2(c[rf][nf][1]);
          z[rf*2+1] += fex2(c[rf][nf][2]) + fex2(c[rf][nf][3]);
        }
    }
  }
  #undef STAGE_A
  #pragma unroll
  for (int i=0;i<4;i++){
    float v = z[i];
    v += __shfl_xor_sync(0xffffffffu, v, 1);
    v += __shfl_xor_sync(0xffffffffu, v, 2);
    if ((lane&3)==0)
      atomicAdd(&g_Z[(size_t)bh*N_ + n0 + wr*32 + (i>>1)*16 + (lane>>2) + (i&1)*8], v);
  }
}

// ---------------- cross scores ----------------
__global__ __launch_bounds__(128) void k_cross(const float* __restrict__ x, const float* __restrict__ Wc,
                                               const float* __restrict__ bc, const int* __restrict__ occ){
  int pid = blockIdx.x;
  int b = pid / M_;
  int o0 = occ[pid*2], o1 = occ[pid*2+1];
  const float* x0 = x + ((size_t)b*N_+o0)*H_;
  const float* x1 = x + ((size_t)b*N_+o1)*H_;
  float p = 0.f;
  for (int h=threadIdx.x; h<H_; h+=128) p += 0.5f*(x0[h]+x1[h])*Wc[h];
  for (int o=16;o;o>>=1) p += __shfl_xor_sync(0xffffffffu, p, o);
  __shared__ float red[4];
  if ((threadIdx.x&31)==0) red[threadIdx.x>>5] = p;
  __syncthreads();
  if (threadIdx.x==0){
    float t = d_lrelu(bc[0] + red[0]+red[1]+red[2]+red[3]);
    atomicAdd(&g_vg2[b*N_+o0], t*t);
    atomicAdd(&g_vg2[b*N_+o1], t*t);
  }
}

// ---------------- band + sumw + coef ----------------
__global__ __launch_bounds__(1024) void k_post(const int* __restrict__ pp){
  __shared__ float ab[N_], wt[N_], red[32];
  __shared__ float swv;
  int b = blockIdx.x, n = threadIdx.x;
  const int* P = pp + b*N_;
  const float* s = g_sc + b*N_;
  float a = 0.f;
  if (n < N_-1){
    float sl1 = d_pred(P,n+1) ? d_lrelu(s[n+1]) : 0.f;
    bool up0 = d_pred(P,n) && (n<=1 || !d_single(P,n));
    float su0 = up0 ? d_lrelu(s[n]) : 0.f;
    a = sl1 + su0;
  }
  ab[n] = a; g_ab[b*N_+n] = a;
  bool up = d_pred(P,n) && (n<=1 || !d_single(P,n));
  bool tr = up && (n>=1);
  float w = d_pred(P,n) ? (tr?3.f:2.f) : 0.f;
  wt[n] = w;
  float v = w;
  for (int o=16;o;o>>=1) v += __shfl_xor_sync(0xffffffffu, v, o);
  if ((n&31)==0) red[n>>5] = v;
  __syncthreads();
  if (n < 32){
    float t2 = red[n];
    for (int o=16;o;o>>=1) t2 += __shfl_xor_sync(0xffffffffu, t2, o);
    if (n==0){ swv = t2; g_sumw[b] = t2; }
  }
  __syncthreads();
  float am1 = (n>=1) ? ab[n-1] : 0.f;
  g_dg[b*N_+n] = 0.8f*(am1*am1 + a*a) + g_vg2[b*N_+n];
  float sw = swv;
  int nm = (n+N_-1)&(N_-1), np = (n+1)&(N_-1);
  float c1 = wt[nm]*(d_single(P,nm)?1.f:0.5f) + wt[np]*(d_single(P,np)?0.f:0.5f);
  g_c1[b*N_+n] = c1 / sw;
  g_c2[b*N_+n] = wt[n] / sw;
}

// ---------------- band correction ----------------
__global__ __launch_bounds__(256) void k_bandfix(){
  int bh = blockIdx.x, b = bh/NH_, h = bh - b*NH_;
  int wid = threadIdx.x>>5, lane = threadIdx.x&31;
  int n = blockIdx.y*8 + wid;
  const float* Qr = g_Qb + ((size_t)b*N_ + n)*H_ + h*64;
  const float* Kp = g_Kb + (size_t)b*N_*H_ + h*64;
  const float* ab = g_ab + b*N_;
  float q0 = Qr[lane], q1 = Qr[lane+32];
  float anm2=(n>=2)?ab[n-2]:0.f, anm1=(n>=1)?ab[n-1]:0.f;
  float an=ab[n], anp1=(n<N_-1)?ab[n+1]:0.f;
  float biasv[5] = { LOG2E*0.8f*anm2*anm1, LOG2E*0.2f*anm1, LOG2E*g_dg[b*N_+n],
                     LOG2E*0.2f*an, LOG2E*0.8f*an*anp1 };
  float delta[5];
  float dz = 0.f;
  #pragma unroll
  for (int d=-2; d<=2; d++){
    int m = n + d;
    delta[d+2] = 0.f;
    if ((unsigned)m < (unsigned)N_){
      const float* Kr = Kp + (size_t)m*H_;
      float s = q0*Kr[lane] + q1*Kr[lane+32];
      #pragma unroll
      for (int o=16;o;o>>=1) s += __shfl_xor_sync(0xffffffffu, s, o);
      delta[d+2] = fex2(s + biasv[d+2]) - fex2(s);
      dz += delta[d+2];
    }
  }
  float Zf = g_Z[(size_t)bh*N_ + n] + dz;
  if (lane==0) g_Z[(size_t)bh*N_ + n] = Zf;
  float w1 = g_c1[b*N_+n] / Zf;
  float w2 = g_c2[b*N_+n] / Zf;
  if (lane==0 && (w1 != 0.f || w2 != 0.f)){
    #pragma unroll
    for (int d=-2; d<=2; d++){
      int m = n + d;
      if ((unsigned)m < (unsigned)N_ && delta[d+2] != 0.f){
        atomicAdd(&g_r1[(size_t)bh*N_ + m], w1*delta[d+2]);
        atomicAdd(&g_r2[(size_t)bh*N_ + m], w2*delta[d+2]);
      }
    }
  }
}

// ---------------- attention pass 2 ----------------
__global__ __launch_bounds__(256,2) void k_attn2(){
  extern __shared__ float sm[];
  float* colp = sm + 3*128*ST;
  int tid=threadIdx.x, lane=tid&31, wid=tid>>5;
  int wr=wid&3, wc=wid>>2;
  int bh=blockIdx.x, b=bh/NH_, h=bh-b*NH_;
  int m0=blockIdx.y*128;
  const float* Q = g_Qb + (size_t)b*N_*H_ + h*64;
  const float* K = g_Kb + (size_t)b*N_*H_ + h*64;
  int sr = tid>>4, sq = (tid&15)*4;
  uint32_t smBase = (uint32_t)__cvta_generic_to_shared(sm);
  uint32_t sKr = smBase + (sr*ST + sq)*4;
  uint32_t sQ0 = sKr + 128*ST*4;
  uint32_t sQ1 = sKr + 2*128*ST*4;
  const float* gKr = K + (size_t)(m0+sr)*H_ + sq;
  const float* gQ  = Q + (size_t)sr*H_ + sq;
  int mrow = wr*32 + (lane>>2), mc = 2*(lane&3);
  int brow = wc*64 + (lane>>2);
  const float* mK  = sm + mrow*ST + mc;
  const float* mQ0 = sm + 128*ST + brow*ST + mc;
  const float* mQ1 = mQ0 + 128*ST;
  int nctr = 0;
  #define STAGE_Q(sdst, cbuf) do { \
    cpa16s((sdst),           gQ); \
    cpa16s((sdst)+16*ST*4,   gQ+16*H_); \
    cpa16s((sdst)+32*ST*4,   gQ+32*H_); \
    cpa16s((sdst)+48*ST*4,   gQ+48*H_); \
    cpa16s((sdst)+64*ST*4,   gQ+64*H_); \
    cpa16s((sdst)+80*ST*4,   gQ+80*H_); \
    cpa16s((sdst)+96*ST*4,   gQ+96*H_); \
    cpa16s((sdst)+112*ST*4,  gQ+112*H_); \
    gQ += 128*H_; \
    if (tid < 128){ \
      int n = nctr*128 + tid; \
      float iz = 1.f / g_Z[(size_t)bh*N_ + n]; \
      colp[(cbuf)*256 + tid]       = g_c1[b*N_+n]*iz; \
      colp[(cbuf)*256 + 128 + tid] = g_c2[b*N_+n]*iz; \
    } \
    nctr++; cp_commit(); } while(0)
  #pragma unroll
  for (int it=0; it<8; it++)
    cpa16s(sKr + it*16*ST*4, gKr + it*16*H_);
  STAGE_Q(sQ0, 0);
  float r1[4]={0,0,0,0}, r2[4]={0,0,0,0};
  #pragma unroll 1
  for (int nt2=0; nt2<4; nt2++){
    cp_wait0(); __syncthreads();
    STAGE_Q(sQ1, 1);
    {
      float c[2][8][4];
      #pragma unroll
      for(int i=0;i<2;i++)
        #pragma unroll
        for(int j=0;j<8;j++){ c[i][j][0]=0;c[i][j][1]=0;c[i][j][2]=0;c[i][j][3]=0; }
      mma_tile_pre<ST,8,8>(mK, mQ0, c);
      const float* cp0 = colp;
      #pragma unroll
      for (int rf=0; rf<2; rf++)
        #pragma unroll
        for (int nf=0; nf<8; nf++){
          int lc0 = wc*64 + nf*8 + 2*(lane&3);
          float w1a = cp0[lc0], w1b = cp0[lc0+1];
          float w2a = cp0[128+lc0], w2b = cp0[128+lc0+1];
          float P0 = fex2(c[rf][nf][0]), P1 = fex2(c[rf][nf][1]);
          float P2 = fex2(c[rf][nf][2]), P3 = fex2(c[rf][nf][3]);
          r1[rf*2+0] += w1a*P0 + w1b*P1;  r2[rf*2+0] += w2a*P0 + w2b*P1;
          r1[rf*2+1] += w1a*P2 + w1b*P3;  r2[rf*2+1] += w2a*P2 + w2b*P3;
        }
    }
    cp_wait0(); __syncthreads();
    if (nt2 < 3) STAGE_Q(sQ0, 0);
    {
      float c[2][8][4];
      #pragma unroll
      for(int i=0;i<2;i++)
        #pragma unroll
        for(int j=0;j<8;j++){ c[i][j][0]=0;c[i][j][1]=0;c[i][j][2]=0;c[i][j][3]=0; }
      mma_tile_pre<ST,8,8>(mK, mQ1, c);
      const float* cp0 = colp + 256;
      #pragma unroll
      for (int rf=0; rf<2; rf++)
        #pragma unroll
        for (int nf=0; nf<8; nf++){
          int lc0 = wc*64 + nf*8 + 2*(lane&3);
          float w1a = cp0[lc0], w1b = cp0[lc0+1];
          float w2a = cp0[128+lc0], w2b = cp0[128+lc0+1];
          float P0 = fex2(c[rf][nf][0]), P1 = fex2(c[rf][nf][1]);
          float P2 = fex2(c[rf][nf][2]), P3 = fex2(c[rf][nf][3]);
          r1[rf*2+0] += w1a*P0 + w1b*P1;  r2[rf*2+0] += w2a*P0 + w2b*P1;
          r1[rf*2+1] += w1a*P2 + w1b*P3;  r2[rf*2+1] += w2a*P2 + w2b*P3;
        }
    }
  }
  #undef STAGE_Q
  #pragma unroll
  for (int i=0;i<4;i++){
    float v1 = r1[i], v2 = r2[i];
    v1 += __shfl_xor_sync(0xffffffffu, v1, 1);
    v1 += __shfl_xor_sync(0xffffffffu, v1, 2);
    v2 += __shfl_xor_sync(0xffffffffu, v2, 1);
    v2 += __shfl_xor_sync(0xffffffffu, v2, 2);
    if ((lane&3)==0){
      size_t o = (size_t)bh*N_ + m0 + wr*32 + (i>>1)*16 + (lane>>2) + (i&1)*8;
      atomicAdd(&g_r1[o], v1);
      atomicAdd(&g_r2[o], v2);
    }
  }
}

// ---------------- A = r @ V ----------------
__global__ __launch_bounds__(768) void k_matvec(){
  int b = blockIdx.x, f = threadIdx.x, h = f >> 6;
  int m0 = blockIdx.y*64;
  const float* r1 = g_r1 + ((size_t)b*NH_+h)*N_;
  const float* r2 = g_r2 + ((size_t)b*NH_+h)*N_;
  float a1=0.f, a2=0.f;
  for (int m=m0; m<m0+64; m++){
    float vv = g_Vb[((size_t)b*N_+m)*H_+f];
    a1 += r1[m]*vv; a2 += r2[m]*vv;
  }
  atomicAdd(&g_A1[b*H_+f], a1);
  atomicAdd(&g_A2[b*H_+f], a2);
}

// ---------------- final GEMVs ----------------
__global__ __launch_bounds__(256) void k_final1(const float* __restrict__ Wo, const float* __restrict__ bo){
  __shared__ float A1s[H_], A2s[H_];
  int b = blockIdx.x, tile = blockIdx.y;
  int tid = threadIdx.x, lane = tid&31, w = tid>>5;
  for (int i=tid; i<H_; i+=256){ A1s[i]=g_A1[b*H_+i]; A2s[i]=g_A2[b*H_+i]; }
  __syncthreads();
  #pragma unroll 1
  for (int oo=0; oo<16; oo++){
    int o = tile*128 + w*16 + oo;
    const float* wr = Wo + (size_t)o*H_;
    float u1=0.f, u2=0.f;
    #pragma unroll
    for (int k=0; k<H_/32; k++){
      float wv = wr[lane + k*32];
      u1 += wv*A1s[lane + k*32];
      u2 += wv*A2s[lane + k*32];
    }
    #pragma unroll
    for (int off=16; off; off>>=1){
      u1 += __shfl_xor_sync(0xffffffffu, u1, off);
      u2 += __shfl_xor_sync(0xffffffffu, u2, off);
    }
    if (lane==0){
      g_u1[b*H_+o] = u1 + bo[o];
      g_u2[b*H_+o] = u2 + bo[o];
    }
  }
}

// k_final2: pm = Wa @ [u1;u2] + ba ; writes broadcast output directly
__global__ __launch_bounds__(256) void k_final2(const float* __restrict__ Wa, const float* __restrict__ ba,
                                                float* __restrict__ out){
  __shared__ float u1s[H_], u2s[H_], pms[128];
  int b = blockIdx.x, tile = blockIdx.y;
  int tid = threadIdx.x, lane = tid&31, w = tid>>5;
  for (int i=tid; i<H_; i+=256){ u1s[i]=g_u1[b*H_+i]; u2s[i]=g_u2[b*H_+i]; }
  __syncthreads();
  #pragma unroll 1
  for (int oo=0; oo<16; oo++){
    int o = tile*128 + w*16 + oo;
    const float* wa = Wa + (size_t)o*2*H_;
    float p = 0.f;
    #pragma unroll
    for (int k=0; k<H_/32; k++){
      p += wa[lane + k*32]*u1s[lane + k*32];
      p += wa[H_ + lane + k*32]*u2s[lane + k*32];
    }
    #pragma unroll
    for (int off=16; off; off>>=1)
      p += __shfl_xor_sync(0xffffffffu, p, off);
    if (lane==0) pms[w*16 + oo] = p + ba[o];
  }
  __syncthreads();
  // broadcast: write these 128 features to all N rows (float4, coalesced)
  int f0 = tile*128;
  float4 v0 = *(float4*)(pms + (tid&31)*4);
  int rowstart = tid>>5;  // 8 warps -> 8-row stride
  for (int n = rowstart; n < N_; n += 8){
    *(float4*)(out + ((size_t)b*N_ + n)*H_ + f0 + (tid&31)*4) = v0;
  }
}

// ---------------- launch ----------------
extern "C" void kernel_launch(void* const* d_in, const int* in_sizes, int n_in,
                              void* d_out, int out_size){
  (void)in_sizes; (void)n_in; (void)out_size;
  const float* x      = (const float*)d_in[0];
  const float* W_var  = (const float*)d_in[3];
  const float* b_var  = (const float*)d_in[4];
  const float* W_sym  = (const float*)d_in[5];
  const float* b_sym  = (const float*)d_in[6];
  const float* W_sc   = (const float*)d_in[7];
  const float* b_scb  = (const float*)d_in[8];
  const float* W_cr   = (const float*)d_in[9];
  const float* b_cr   = (const float*)d_in[10];
  const float* W_atom = (const float*)d_in[11];
  const float* b_atom = (const float*)d_in[12];
  const float* W_q    = (const float*)d_in[13];
  const float* b_q    = (const float*)d_in[14];
  const float* W_k    = (const float*)d_in[15];
  const float* b_k    = (const float*)d_in[16];
  const float* W_v    = (const float*)d_in[17];
  const float* b_v    = (const float*)d_in[18];
  const float* W_o    = (const float*)d_in[19];
  const float* b_o    = (const float*)d_in[20];
  const int*   pp     = (const int*)d_in[21];
  const int*   occ    = (const int*)d_in[24];
  float* out = (float*)d_out;

  float *p_Q, *p_K, *p_V;
  cudaGetSymbolAddress((void**)&p_Q, g_Qb);
  cudaGetSymbolAddress((void**)&p_K, g_Kb);
  cudaGetSymbolAddress((void**)&p_V, g_Vb);

  const int PROJ_SMEM  = (4*128*STP)*4;
  const int ATTN1_SMEM = (3*128*ST)*4;
  const int ATTN2_SMEM = (3*128*ST + 512)*4;
  static bool attr_done = false;
  if (!attr_done){
    cudaFuncSetAttribute(k_proj,  cudaFuncAttributeMaxDynamicSharedMemorySize, PROJ_SMEM);
    cudaFuncSetAttribute(k_attn1, cudaFuncAttributeMaxDynamicSharedMemorySize, ATTN1_SMEM);
    cudaFuncSetAttribute(k_attn2, cudaFuncAttributeMaxDynamicSharedMemorySize, ATTN2_SMEM);
    attr_done = true;
  }

  // launch order: ncu capture slot (#4) = k_proj
  k_init<<<(B_*NH_*N_+255)/256, 256>>>(b_scb);                                   // 1
  const int PRE = 2*(B_*N_*H_/8) + 5*(H_*H_/8);
  k_preconv<<<(PRE+255)/256, 256>>>(x, pp, W_var, W_sym, W_q, W_k, W_v);         // 2
  k_cross<<<B_*M_, 128>>>(x, W_cr, b_cr, occ);                                   // 3
  dim3 gp(H_/128, (B_*N_)/128, 5);
  k_proj<<<gp, 256, PROJ_SMEM>>>(b_var, b_sym, b_q, b_k, b_v, W_sc, p_Q, p_K, p_V); // 4 <- profiled
  dim3 ga(B_*NH_, N_/128);
  k_attn1<<<ga, 256, ATTN1_SMEM>>>();                                            // 5
  k_post<<<B_, 1024>>>(pp);                                                      // 6
  dim3 gbf(B_*NH_, N_/8);
  k_bandfix<<<gbf, 256>>>();                                                     // 7
  k_attn2<<<ga, 256, ATTN2_SMEM>>>();                                            // 8
  dim3 gmv(B_, 16);
  k_matvec<<<gmv, 768>>>();                                                      // 9
  dim3 gf(B_, H_/128);
  k_final1<<<gf, 256>>>(W_o, b_o);                                               // 10
  k_final2<<<gf, 256>>>(W_atom, b_atom, out);                                    // 11
}

// round 15
// speedup vs baseline: 2.2841x; 1.0074x over previous
#include <cuda_runtime.h>
#include <mma.h>
#include <cstdint>
using namespace nvcuda;

#define B_ 8
#define N_ 1024
#define H_ 768
#define NH_ 12
#define M_ 256
#define ST 72
#define STP 40
#define KT 32
#define NKT 24
#define LOG2E 1.4426950408889634f

// ---------------- scratch ----------------
__device__ float g_xr[B_*N_*H_];
__device__ float g_vi[B_*N_*H_];
__device__ float g_Wr[5*H_*H_];
__device__ float g_Qb[B_*N_*H_];
__device__ float g_Kb[B_*N_*H_];
__device__ float g_Vb[B_*N_*H_];
__device__ float g_sc[B_*N_];
__device__ float g_vg2[B_*N_];
__device__ float g_ab[B_*N_];
__device__ float g_dg[B_*N_];
__device__ float g_c1[B_*N_];
__device__ float g_c2[B_*N_];
__device__ float g_Z[B_*NH_*N_];
__device__ float g_r1[B_*NH_*N_];
__device__ float g_r2[B_*NH_*N_];
__device__ float g_A1[B_*H_];
__device__ float g_A2[B_*H_];
__device__ float g_u1[B_*H_];
__device__ float g_u2[B_*H_];

__device__ __forceinline__ bool d_pred(const int* P, int i){ return P[i]==1; }
__device__ __forceinline__ bool d_single(const int* P, int i){ return (i==0) || (i>=2 && P[i-2]==1); }
__device__ __forceinline__ float d_lrelu(float t){ return t >= 0.f ? t : 0.02f*t; }
__device__ __forceinline__ float tf32r(float x){ return wmma::__float_to_tf32(x); }
__device__ __forceinline__ float fex2(float x){ float y; asm("ex2.approx.f32 %0, %1;" : "=f"(y) : "f"(x)); return y; }
__device__ __forceinline__ float ftanh(float x){ float y; asm("tanh.approx.f32 %0, %1;" : "=f"(y) : "f"(x)); return y; }

__device__ __forceinline__ void perm_store(float* dst, float4 a, float4 b){
  float4 o0 = make_float4(tf32r(a.x), tf32r(b.x), tf32r(a.y), tf32r(b.y));
  float4 o1 = make_float4(tf32r(a.z), tf32r(b.z), tf32r(a.w), tf32r(b.w));
  *(float4*)dst = o0; *(float4*)(dst+4) = o1;
}

// ---------------- cp.async ----------------
__device__ __forceinline__ void cpa16s(uint32_t s, const float* g){
  asm volatile("cp.async.cg.shared.global [%0], [%1], 16;\n" :: "r"(s), "l"(g));
}
__device__ __forceinline__ void cp_commit(){ asm volatile("cp.async.commit_group;\n"); }
__device__ __forceinline__ void cp_wait0(){ asm volatile("cp.async.wait_group 0;\n"); }

// ---------------- m16n8k8 tf32 mma.sync ----------------
__device__ __forceinline__ void mma8(float c[4], const uint32_t a[4], uint32_t b0, uint32_t b1){
  asm volatile(
    "mma.sync.aligned.m16n8k8.row.col.f32.tf32.tf32.f32 "
    "{%0,%1,%2,%3}, {%4,%5,%6,%7}, {%8,%9}, {%0,%1,%2,%3};\n"
    : "+f"(c[0]), "+f"(c[1]), "+f"(c[2]), "+f"(c[3])
    : "r"(a[0]), "r"(a[1]), "r"(a[2]), "r"(a[3]), "r"(b0), "r"(b1));
}

template<int STRIDE, int NF, int K8>
__device__ __forceinline__ void mma_tile_pre(const float* __restrict__ mA,
                                             const float* __restrict__ mB,
                                             float c[2][NF][4]){
  #pragma unroll
  for (int k8=0;k8<K8;k8++){
    uint32_t a[2][4];
    #pragma unroll
    for (int rf=0; rf<2; rf++){
      float2 v0 = *(const float2*)(mA + rf*16*STRIDE + k8*8);
      float2 v1 = *(const float2*)(mA + rf*16*STRIDE + 8*STRIDE + k8*8);
      a[rf][0]=__float_as_uint(v0.x); a[rf][2]=__float_as_uint(v0.y);
      a[rf][1]=__float_as_uint(v1.x); a[rf][3]=__float_as_uint(v1.y);
    }
    #pragma unroll
    for (int nf=0;nf<NF;nf++){
      float2 bv = *(const float2*)(mB + nf*8*STRIDE + k8*8);
      mma8(c[0][nf], a[0], __float_as_uint(bv.x), __float_as_uint(bv.y));
      mma8(c[1][nf], a[1], __float_as_uint(bv.x), __float_as_uint(bv.y));
    }
  }
}

// ---------------- init ----------------
__global__ void k_init(const float* __restrict__ bsc){
  int i = blockIdx.x*blockDim.x + threadIdx.x;
  if (i < B_*N_){ g_vg2[i] = 0.f; g_sc[i] = bsc[0]; }
  if (i < B_*H_){ g_A1[i]=0.f; g_A2[i]=0.f; }
  if (i < B_*NH_*N_){ g_Z[i]=0.f; g_r1[i]=0.f; g_r2[i]=0.f; }
}

// ---------------- preconv ----------------
__global__ void k_preconv(const float* __restrict__ x, const int* __restrict__ pp,
                          const float* __restrict__ W0, const float* __restrict__ W1,
                          const float* __restrict__ W2, const float* __restrict__ W3,
                          const float* __restrict__ W4){
  const int XT8 = B_*N_*H_/8;
  const int WT8 = H_*H_/8;
  const int H8 = H_/8;
  int i = blockIdx.x*blockDim.x + threadIdx.x;
  if (i < XT8){
    const float4* s = (const float4*)x + (size_t)i*2;
    perm_store(g_xr + (size_t)i*8, s[0], s[1]);
  } else if (i < 2*XT8){
    int j = i - XT8;
    int hh8 = j % H8;
    int nn  = (j / H8) % N_;
    int b   = j / (N_*H8);
    bool single = (nn==0) || (nn>=2 && pp[b*N_+nn-2]==1);
    int np = (nn+1)&(N_-1), nm = (nn+N_-1)&(N_-1);
    const float* bp = x + ((size_t)b*N_ + np)*H_ + hh8*8;
    float4 xa = *(const float4*)bp, xb = *(const float4*)(bp+4);
    if (!single){
      const float* bm = x + ((size_t)b*N_ + nm)*H_ + hh8*8;
      float4 ya = *(const float4*)bm, yb = *(const float4*)(bm+4);
      xa.x=0.5f*(xa.x+ya.x); xa.y=0.5f*(xa.y+ya.y); xa.z=0.5f*(xa.z+ya.z); xa.w=0.5f*(xa.w+ya.w);
      xb.x=0.5f*(xb.x+yb.x); xb.y=0.5f*(xb.y+yb.y); xb.z=0.5f*(xb.z+yb.z); xb.w=0.5f*(xb.w+yb.w);
    }
    perm_store(g_vi + (size_t)j*8, xa, xb);
  } else {
    int j = i - 2*XT8;
    if (j < 5*WT8){
      int w = j / WT8, o = j - w*WT8;
      int row = o / H8, rem = o - row*H8;
      int srow = row;
      if (w==2 || w==3){
        int r8 = row & 7;
        srow = (row & ~7) | ((r8&1)*4 + (r8>>1));
      }
      const float* src = (w==0)?W0:(w==1)?W1:(w==2)?W2:(w==3)?W3:W4;
      const float4* s = (const float4*)(src + (size_t)srow*H_ + rem*8);
      perm_store(g_Wr + (size_t)w*H_*H_ + (size_t)o*8, s[0], s[1]);
    }
  }
}

// ---------------- merged projections: sel=0 -> modes {2,3} (Q,K); sel=1 -> modes {0,1,4} ----------------
__global__ __launch_bounds__(256,2) void k_proj(
    const float* __restrict__ b_var, const float* __restrict__ b_sym,
    const float* __restrict__ b_q, const float* __restrict__ b_k, const float* __restrict__ b_v,
    const float* __restrict__ Wsc,
    float* __restrict__ Qb, float* __restrict__ Kb, float* __restrict__ Vb, int sel){
  extern __shared__ float sm[];
  int z = blockIdx.z;
  int mode = sel ? (z==2 ? 4 : z) : (z+2);
  const float* A = (mode==0) ? g_vi : g_xr;
  const float* W = g_Wr + (size_t)mode*H_*H_;
  const float* bias; float* C=nullptr; float alpha=1.f; const float* wsc=nullptr;
  switch(mode){
    case 0: bias=b_var; wsc=Wsc;    break;
    case 1: bias=b_sym; wsc=Wsc+H_; break;
    case 2: bias=b_q;   C=Qb; alpha=0.125f*LOG2E; break;
    case 3: bias=b_k;   C=Kb; break;
    default:bias=b_v;   C=Vb; break;
  }
  int tid=threadIdx.x, lane=tid&31, wid=tid>>5;
  int wr=wid&3, wc=wid>>2;
  int m0 = blockIdx.y*128, n0 = blockIdx.x*128;
  int sr = tid>>3, sq = (tid&7)*4;
  uint32_t smBase = (uint32_t)__cvta_generic_to_shared(sm);
  uint32_t sA0 = smBase + (sr*STP + sq)*4;
  uint32_t sA1 = sA0 + 128*STP*4;
  uint32_t sB0 = sA0 + 2*128*STP*4;
  uint32_t sB1 = sA0 + 3*128*STP*4;
  const float* gA = A + (size_t)(m0+sr)*H_ + sq;
  const float* gW = W + (size_t)(n0+sr)*H_ + sq;
  int mrow = wr*32 + (lane>>2), mc = 2*(lane&3);
  int brow = wc*64 + (lane>>2);
  const float* mA0 = sm + mrow*STP + mc;
  const float* mA1 = mA0 + 128*STP;
  const float* mB0 = sm + 2*128*STP + brow*STP + mc;
  const float* mB1 = mB0 + 128*STP;
  #define STAGE_P(sa, sb) do { \
    cpa16s((sa),            gA); \
    cpa16s((sa)+32*STP*4,   gA+32*H_); \
    cpa16s((sa)+64*STP*4,   gA+64*H_); \
    cpa16s((sa)+96*STP*4,   gA+96*H_); \
    cpa16s((sb),            gW); \
    cpa16s((sb)+32*STP*4,   gW+32*H_); \
    cpa16s((sb)+64*STP*4,   gW+64*H_); \
    cpa16s((sb)+96*STP*4,   gW+96*H_); \
    gA += KT; gW += KT; cp_commit(); } while(0)
  STAGE_P(sA0, sB0);
  float c[2][8][4];
  #pragma unroll
  for(int i=0;i<2;i++)
    #pragma unroll
    for(int j=0;j<8;j++){ c[i][j][0]=0;c[i][j][1]=0;c[i][j][2]=0;c[i][j][3]=0; }
  #pragma unroll 1
  for (int kt2=0; kt2<NKT/2; kt2++){
    cp_wait0(); __syncthreads();
    STAGE_P(sA1, sB1);
    mma_tile_pre<STP,8,4>(mA0, mB0, c);
    cp_wait0(); __syncthreads();
    if (kt2 < NKT/2-1) STAGE_P(sA0, sB0);
    mma_tile_pre<STP,8,4>(mA1, mB1, c);
  }
  #undef STAGE_P
  int t = lane&3;
  if (mode<=1){
    float p[4] = {0,0,0,0};
    #pragma unroll
    for (int rf=0; rf<2; rf++){
      #pragma unroll
      for (int nf=0; nf<8; nf++){
        int col0 = n0 + wc*64 + nf*8 + 2*t;
        float w0 = wsc[col0], w1 = wsc[col0+1];
        float b0v = bias[col0], b1v = bias[col0+1];
        p[rf*2+0] += ftanh(c[rf][nf][0]+b0v)*w0 + ftanh(c[rf][nf][1]+b1v)*w1;
        p[rf*2+1] += ftanh(c[rf][nf][2]+b0v)*w0 + ftanh(c[rf][nf][3]+b1v)*w1;
      }
    }
    #pragma unroll
    for (int i=0;i<4;i++){
      float v = p[i];
      v += __shfl_xor_sync(0xffffffffu, v, 1);
      v += __shfl_xor_sync(0xffffffffu, v, 2);
      if (t==0)
        atomicAdd(&g_sc[m0 + wr*32 + (i>>1)*16 + (lane>>2) + (i&1)*8], v);
    }
  } else if (mode==4){
    #pragma unroll
    for (int rf=0; rf<2; rf++){
      int row = m0 + wr*32 + rf*16 + (lane>>2);
      #pragma unroll
      for (int nf=0; nf<8; nf++){
        int col0 = n0 + wc*64 + nf*8 + 2*t;
        float2 bv = *(const float2*)(bias + col0);
        *(float2*)(C + (size_t)row*H_ + col0)     = make_float2(c[rf][nf][0]+bv.x, c[rf][nf][1]+bv.y);
        *(float2*)(C + (size_t)(row+8)*H_ + col0) = make_float2(c[rf][nf][2]+bv.x, c[rf][nf][3]+bv.y);
      }
    }
  } else {
    #pragma unroll
    for (int rf=0; rf<2; rf++){
      int row = m0 + wr*32 + rf*16 + (lane>>2);
      #pragma unroll
      for (int nf=0; nf<8; nf++){
        int col = n0 + wc*64 + nf*8;
        float b0v = bias[col + t], b1v = bias[col + t + 4];
        *(float2*)(C + (size_t)row*H_ + col + 2*t) =
          make_float2(tf32r(alpha*(c[rf][nf][0]+b0v)), tf32r(alpha*(c[rf][nf][1]+b1v)));
        *(float2*)(C + (size_t)(row+8)*H_ + col + 2*t) =
          make_float2(tf32r(alpha*(c[rf][nf][2]+b0v)), tf32r(alpha*(c[rf][nf][3]+b1v)));
      }
    }
  }
}

// ---------------- attention pass 1 ----------------
__global__ __launch_bounds__(256,2) void k_attn1(){
  extern __shared__ float sm[];
  int tid=threadIdx.x, lane=tid&31, wid=tid>>5;
  int wr=wid&3, wc=wid>>2;
  int bh=blockIdx.x, b=bh/NH_, h=bh-b*NH_;
  int n0=blockIdx.y*128;
  const float* Q = g_Qb + (size_t)b*N_*H_ + h*64;
  const float* K = g_Kb + (size_t)b*N_*H_ + h*64;
  int sr = tid>>4, sq = (tid&15)*4;
  uint32_t smBase = (uint32_t)__cvta_generic_to_shared(sm);
  uint32_t sQ  = smBase + (sr*ST + sq)*4;
  uint32_t sK0 = sQ + 128*ST*4;
  uint32_t sK1 = sQ + 2*128*ST*4;
  const float* gQ = Q + (size_t)(n0+sr)*H_ + sq;
  const float* gK = K + (size_t)sr*H_ + sq;
  int mrow = wr*32 + (lane>>2), mc = 2*(lane&3);
  int brow = wc*64 + (lane>>2);
  const float* mQ  = sm + mrow*ST + mc;
  const float* mK0 = sm + 128*ST + brow*ST + mc;
  const float* mK1 = mK0 + 128*ST;
  #define STAGE_A(sdst) do { \
    cpa16s((sdst),           gK); \
    cpa16s((sdst)+16*ST*4,   gK+16*H_); \
    cpa16s((sdst)+32*ST*4,   gK+32*H_); \
    cpa16s((sdst)+48*ST*4,   gK+48*H_); \
    cpa16s((sdst)+64*ST*4,   gK+64*H_); \
    cpa16s((sdst)+80*ST*4,   gK+80*H_); \
    cpa16s((sdst)+96*ST*4,   gK+96*H_); \
    cpa16s((sdst)+112*ST*4,  gK+112*H_); \
    gK += 128*H_; cp_commit(); } while(0)
  #pragma unroll
  for (int it=0; it<8; it++)
    cpa16s(sQ + it*16*ST*4, gQ + it*16*H_);
  STAGE_A(sK0);
  float z[4]={0,0,0,0};
  #pragma unroll 1
  for (int mt2=0; mt2<4; mt2++){
    cp_wait0(); __syncthreads();
    STAGE_A(sK1);
    {
      float c[2][8][4];
      #pragma unroll
      for(int i=0;i<2;i++)
        #pragma unroll
        for(int j=0;j<8;j++){ c[i][j][0]=0;c[i][j][1]=0;c[i][j][2]=0;c[i][j][3]=0; }
      mma_tile_pre<ST,8,8>(mQ, mK0, c);
      #pragma unroll
      for (int rf=0; rf<2; rf++)
        #pragma unroll
        for (int nf=0; nf<8; nf++){
          z[rf*2+0] += fex2(c[rf][nf][0]) + fex2(c[rf][nf][1]);
          z[rf*2+1] += fex2(c[rf][nf][2]) + fex2(c[rf][nf][3]);
        }
    }
    cp_wait0(); __syncthreads();
    if (mt2 < 3) STAGE_A(sK0);
    {
      float c[2][8][4];
      #pragma unroll
      for(int i=0;i<2;i++)
        #pragma unroll
        for(int j=0;j<8;j++){ c[i][j][0]=0;c[i][j][1]=0;c[i][j][2]=0;c[i][j][3]=0; }
      mma_tile_pre<ST,8,8>(mQ, mK1, c);
      #pragma unroll
      for (int rf=0; rf<2; rf++)
        #pragma unroll
        for (int nf=0; nf<8; nf++){
          z[rf*2+0] += fex2(c[rf][nf][0]) + fex2(c[rf][nf][1]);
          z[rf*2+1] += fex2(c[rf][nf][2]) + fex2(c[rf][nf][3]);
        }
    }
  }
  #undef STAGE_A
  #pragma unroll
  for (int i=0;i<4;i++){
    float v = z[i];
    v += __shfl_xor_sync(0xffffffffu, v, 1);
    v += __shfl_xor_sync(0xffffffffu, v, 2);
    if ((lane&3)==0)
      atomicAdd(&g_Z[(size_t)bh*N_ + n0 + wr*32 + (i>>1)*16 + (lane>>2) + (i&1)*8], v);
  }
}

// ---------------- cross scores ----------------
__global__ __launch_bounds__(128) void k_cross(const float* __restrict__ x, const float* __restrict__ Wc,
                                               const float* __restrict__ bc, const int* __restrict__ occ){
  int pid = blockIdx.x;
  int b = pid / M_;
  int o0 = occ[pid*2], o1 = occ[pid*2+1];
  const float* x0 = x + ((size_t)b*N_+o0)*H_;
  const float* x1 = x + ((size_t)b*N_+o1)*H_;
  float p = 0.f;
  for (int h=threadIdx.x; h<H_; h+=128) p += 0.5f*(x0[h]+x1[h])*Wc[h];
  for (int o=16;o;o>>=1) p += __shfl_xor_sync(0xffffffffu, p, o);
  __shared__ float red[4];
  if ((threadIdx.x&31)==0) red[threadIdx.x>>5] = p;
  __syncthreads();
  if (threadIdx.x==0){
    float t = d_lrelu(bc[0] + red[0]+red[1]+red[2]+red[3]);
    atomicAdd(&g_vg2[b*N_+o0], t*t);
    atomicAdd(&g_vg2[b*N_+o1], t*t);
  }
}

// ---------------- band + sumw + coef ----------------
__global__ __launch_bounds__(1024) void k_post(const int* __restrict__ pp){
  __shared__ float ab[N_], wt[N_], red[32];
  __shared__ float swv;
  int b = blockIdx.x, n = threadIdx.x;
  const int* P = pp + b*N_;
  const float* s = g_sc + b*N_;
  float a = 0.f;
  if (n < N_-1){
    float sl1 = d_pred(P,n+1) ? d_lrelu(s[n+1]) : 0.f;
    bool up0 = d_pred(P,n) && (n<=1 || !d_single(P,n));
    float su0 = up0 ? d_lrelu(s[n]) : 0.f;
    a = sl1 + su0;
  }
  ab[n] = a; g_ab[b*N_+n] = a;
  bool up = d_pred(P,n) && (n<=1 || !d_single(P,n));
  bool tr = up && (n>=1);
  float w = d_pred(P,n) ? (tr?3.f:2.f) : 0.f;
  wt[n] = w;
  float v = w;
  for (int o=16;o;o>>=1) v += __shfl_xor_sync(0xffffffffu, v, o);
  if ((n&31)==0) red[n>>5] = v;
  __syncthreads();
  if (n < 32){
    float t2 = red[n];
    for (int o=16;o;o>>=1) t2 += __shfl_xor_sync(0xffffffffu, t2, o);
    if (n==0) swv = t2;
  }
  __syncthreads();
  float am1 = (n>=1) ? ab[n-1] : 0.f;
  g_dg[b*N_+n] = 0.8f*(am1*am1 + a*a) + g_vg2[b*N_+n];
  float sw = swv;
  int nm = (n+N_-1)&(N_-1), np = (n+1)&(N_-1);
  float c1 = wt[nm]*(d_single(P,nm)?1.f:0.5f) + wt[np]*(d_single(P,np)?0.f:0.5f);
  g_c1[b*N_+n] = c1 / sw;
  g_c2[b*N_+n] = wt[n] / sw;
}

// ---------------- band correction ----------------
__global__ __launch_bounds__(256) void k_bandfix(){
  int bh = blockIdx.x, b = bh/NH_, h = bh - b*NH_;
  int wid = threadIdx.x>>5, lane = threadIdx.x&31;
  int n = blockIdx.y*8 + wid;
  const float* Qr = g_Qb + ((size_t)b*N_ + n)*H_ + h*64;
  const float* Kp = g_Kb + (size_t)b*N_*H_ + h*64;
  const float* ab = g_ab + b*N_;
  float q0 = Qr[lane], q1 = Qr[lane+32];
  float anm2=(n>=2)?ab[n-2]:0.f, anm1=(n>=1)?ab[n-1]:0.f;
  float an=ab[n], anp1=(n<N_-1)?ab[n+1]:0.f;
  float biasv[5] = { LOG2E*0.8f*anm2*anm1, LOG2E*0.2f*anm1, LOG2E*g_dg[b*N_+n],
                     LOG2E*0.2f*an, LOG2E*0.8f*an*anp1 };
  float delta[5];
  float dz = 0.f;
  #pragma unroll
  for (int d=-2; d<=2; d++){
    int m = n + d;
    delta[d+2] = 0.f;
    if ((unsigned)m < (unsigned)N_){
      const float* Kr = Kp + (size_t)m*H_;
      float s = q0*Kr[lane] + q1*Kr[lane+32];
      #pragma unroll
      for (int o=16;o;o>>=1) s += __shfl_xor_sync(0xffffffffu, s, o);
      delta[d+2] = fex2(s + biasv[d+2]) - fex2(s);
      dz += delta[d+2];
    }
  }
  float Zf = g_Z[(size_t)bh*N_ + n] + dz;
  if (lane==0) g_Z[(size_t)bh*N_ + n] = Zf;
  float w1 = g_c1[b*N_+n] / Zf;
  float w2 = g_c2[b*N_+n] / Zf;
  if (lane==0 && (w1 != 0.f || w2 != 0.f)){
    #pragma unroll
    for (int d=-2; d<=2; d++){
      int m = n + d;
      if ((unsigned)m < (unsigned)N_ && delta[d+2] != 0.f){
        atomicAdd(&g_r1[(size_t)bh*N_ + m], w1*delta[d+2]);
        atomicAdd(&g_r2[(size_t)bh*N_ + m], w2*delta[d+2]);
      }
    }
  }
}

// ---------------- attention pass 2 ----------------
__global__ __launch_bounds__(256,2) void k_attn2(){
  extern __shared__ float sm[];
  float* colp = sm + 3*128*ST;
  int tid=threadIdx.x, lane=tid&31, wid=tid>>5;
  int wr=wid&3, wc=wid>>2;
  int bh=blockIdx.x, b=bh/NH_, h=bh-b*NH_;
  int m0=blockIdx.y*128;
  const float* Q = g_Qb + (size_t)b*N_*H_ + h*64;
  const float* K = g_Kb + (size_t)b*N_*H_ + h*64;
  int sr = tid>>4, sq = (tid&15)*4;
  uint32_t smBase = (uint32_t)__cvta_generic_to_shared(sm);
  uint32_t sKr = smBase + (sr*ST + sq)*4;
  uint32_t sQ0 = sKr + 128*ST*4;
  uint32_t sQ1 = sKr + 2*128*ST*4;
  const float* gKr = K + (size_t)(m0+sr)*H_ + sq;
  const float* gQ  = Q + (size_t)sr*H_ + sq;
  int mrow = wr*32 + (lane>>2), mc = 2*(lane&3);
  int brow = wc*64 + (lane>>2);
  const float* mK  = sm + mrow*ST + mc;
  const float* mQ0 = sm + 128*ST + brow*ST + mc;
  const float* mQ1 = mQ0 + 128*ST;
  int nctr = 0;
  #define STAGE_Q(sdst, cbuf) do { \
    cpa16s((sdst),           gQ); \
    cpa16s((sdst)+16*ST*4,   gQ+16*H_); \
    cpa16s((sdst)+32*ST*4,   gQ+32*H_); \
    cpa16s((sdst)+48*ST*4,   gQ+48*H_); \
    cpa16s((sdst)+64*ST*4,   gQ+64*H_); \
    cpa16s((sdst)+80*ST*4,   gQ+80*H_); \
    cpa16s((sdst)+96*ST*4,   gQ+96*H_); \
    cpa16s((sdst)+112*ST*4,  gQ+112*H_); \
    gQ += 128*H_; \
    if (tid < 128){ \
      int n = nctr*128 + tid; \
      float iz = 1.f / g_Z[(size_t)bh*N_ + n]; \
      colp[(cbuf)*256 + tid]       = g_c1[b*N_+n]*iz; \
      colp[(cbuf)*256 + 128 + tid] = g_c2[b*N_+n]*iz; \
    } \
    nctr++; cp_commit(); } while(0)
  #pragma unroll
  for (int it=0; it<8; it++)
    cpa16s(sKr + it*16*ST*4, gKr + it*16*H_);
  STAGE_Q(sQ0, 0);
  float r1[4]={0,0,0,0}, r2[4]={0,0,0,0};
  #pragma unroll 1
  for (int nt2=0; nt2<4; nt2++){
    cp_wait0(); __syncthreads();
    STAGE_Q(sQ1, 1);
    {
      float c[2][8][4];
      #pragma unroll
      for(int i=0;i<2;i++)
        #pragma unroll
        for(int j=0;j<8;j++){ c[i][j][0]=0;c[i][j][1]=0;c[i][j][2]=0;c[i][j][3]=0; }
      mma_tile_pre<ST,8,8>(mK, mQ0, c);
      const float* cp0 = colp;
      #pragma unroll
      for (int rf=0; rf<2; rf++)
        #pragma unroll
        for (int nf=0; nf<8; nf++){
          int lc0 = wc*64 + nf*8 + 2*(lane&3);
          float w1a = cp0[lc0], w1b = cp0[lc0+1];
          float w2a = cp0[128+lc0], w2b = cp0[128+lc0+1];
          float P0 = fex2(c[rf][nf][0]), P1 = fex2(c[rf][nf][1]);
          float P2 = fex2(c[rf][nf][2]), P3 = fex2(c[rf][nf][3]);
          r1[rf*2+0] += w1a*P0 + w1b*P1;  r2[rf*2+0] += w2a*P0 + w2b*P1;
          r1[rf*2+1] += w1a*P2 + w1b*P3;  r2[rf*2+1] += w2a*P2 + w2b*P3;
        }
    }
    cp_wait0(); __syncthreads();
    if (nt2 < 3) STAGE_Q(sQ0, 0);
    {
      float c[2][8][4];
      #pragma unroll
      for(int i=0;i<2;i++)
        #pragma unroll
        for(int j=0;j<8;j++){ c[i][j][0]=0;c[i][j][1]=0;c[i][j][2]=0;c[i][j][3]=0; }
      mma_tile_pre<ST,8,8>(mK, mQ1, c);
      const float* cp0 = colp + 256;
      #pragma unroll
      for (int rf=0; rf<2; rf++)
        #pragma unroll
        for (int nf=0; nf<8; nf++){
          int lc0 = wc*64 + nf*8 + 2*(lane&3);
          float w1a = cp0[lc0], w1b = cp0[lc0+1];
          float w2a = cp0[128+lc0], w2b = cp0[128+lc0+1];
          float P0 = fex2(c[rf][nf][0]), P1 = fex2(c[rf][nf][1]);
          float P2 = fex2(c[rf][nf][2]), P3 = fex2(c[rf][nf][3]);
          r1[rf*2+0] += w1a*P0 + w1b*P1;  r2[rf*2+0] += w2a*P0 + w2b*P1;
          r1[rf*2+1] += w1a*P2 + w1b*P3;  r2[rf*2+1] += w2a*P2 + w2b*P3;
        }
    }
  }
  #undef STAGE_Q
  #pragma unroll
  for (int i=0;i<4;i++){
    float v1 = r1[i], v2 = r2[i];
    v1 += __shfl_xor_sync(0xffffffffu, v1, 1);
    v1 += __shfl_xor_sync(0xffffffffu, v1, 2);
    v2 += __shfl_xor_sync(0xffffffffu, v2, 1);
    v2 += __shfl_xor_sync(0xffffffffu, v2, 2);
    if ((lane&3)==0){
      size_t o = (size_t)bh*N_ + m0 + wr*32 + (i>>1)*16 + (lane>>2) + (i&1)*8;
      atomicAdd(&g_r1[o], v1);
      atomicAdd(&g_r2[o], v2);
    }
  }
}

// ---------------- A = r @ V ----------------
__global__ __launch_bounds__(768) void k_matvec(){
  int b = blockIdx.x, f = threadIdx.x, h = f >> 6;
  int m0 = blockIdx.y*64;
  const float* r1 = g_r1 + ((size_t)b*NH_+h)*N_;
  const float* r2 = g_r2 + ((size_t)b*NH_+h)*N_;
  float a1=0.f, a2=0.f;
  for (int m=m0; m<m0+64; m++){
    float vv = g_Vb[((size_t)b*N_+m)*H_+f];
    a1 += r1[m]*vv; a2 += r2[m]*vv;
  }
  atomicAdd(&g_A1[b*H_+f], a1);
  atomicAdd(&g_A2[b*H_+f], a2);
}

// ---------------- final GEMVs ----------------
__global__ __launch_bounds__(256) void k_final1(const float* __restrict__ Wo, const float* __restrict__ bo){
  __shared__ float A1s[H_], A2s[H_];
  int b = blockIdx.x, tile = blockIdx.y;
  int tid = threadIdx.x, lane = tid&31, w = tid>>5;
  for (int i=tid; i<H_; i+=256){ A1s[i]=g_A1[b*H_+i]; A2s[i]=g_A2[b*H_+i]; }
  __syncthreads();
  #pragma unroll 1
  for (int oo=0; oo<16; oo++){
    int o = tile*128 + w*16 + oo;
    const float* wr = Wo + (size_t)o*H_;
    float u1=0.f, u2=0.f;
    #pragma unroll
    for (int k=0; k<H_/32; k++){
      float wv = wr[lane + k*32];
      u1 += wv*A1s[lane + k*32];
      u2 += wv*A2s[lane + k*32];
    }
    #pragma unroll
    for (int off=16; off; off>>=1){
      u1 += __shfl_xor_sync(0xffffffffu, u1, off);
      u2 += __shfl_xor_sync(0xffffffffu, u2, off);
    }
    if (lane==0){
      g_u1[b*H_+o] = u1 + bo[o];
      g_u2[b*H_+o] = u2 + bo[o];
    }
  }
}

__global__ __launch_bounds__(256) void k_final2(const float* __restrict__ Wa, const float* __restrict__ ba,
                                                float* __restrict__ out){
  __shared__ float u1s[H_], u2s[H_], pms[128];
  int b = blockIdx.x, tile = blockIdx.y;
  int tid = threadIdx.x, lane = tid&31, w = tid>>5;
  for (int i=tid; i<H_; i+=256){ u1s[i]=g_u1[b*H_+i]; u2s[i]=g_u2[b*H_+i]; }
  __syncthreads();
  #pragma unroll 1
  for (int oo=0; oo<16; oo++){
    int o = tile*128 + w*16 + oo;
    const float* wa = Wa + (size_t)o*2*H_;
    float p = 0.f;
    #pragma unroll
    for (int k=0; k<H_/32; k++){
      p += wa[lane + k*32]*u1s[lane + k*32];
      p += wa[H_ + lane + k*32]*u2s[lane + k*32];
    }
    #pragma unroll
    for (int off=16; off; off>>=1)
      p += __shfl_xor_sync(0xffffffffu, p, off);
    if (lane==0) pms[w*16 + oo] = p + ba[o];
  }
  __syncthreads();
  int f0 = tile*128;
  float4 v0 = *(float4*)(pms + (tid&31)*4);
  int rowstart = tid>>5;
  for (int n = rowstart; n < N_; n += 8){
    *(float4*)(out + ((size_t)b*N_ + n)*H_ + f0 + (tid&31)*4) = v0;
  }
}

// ---------------- launch ----------------
extern "C" void kernel_launch(void* const* d_in, const int* in_sizes, int n_in,
                              void* d_out, int out_size){
  (void)in_sizes; (void)n_in; (void)out_size;
  const float* x      = (const float*)d_in[0];
  const float* W_var  = (const float*)d_in[3];
  const float* b_var  = (const float*)d_in[4];
  const float* W_sym  = (const float*)d_in[5];
  const float* b_sym  = (const float*)d_in[6];
  const float* W_sc   = (const float*)d_in[7];
  const float* b_scb  = (const float*)d_in[8];
  const float* W_cr   = (const float*)d_in[9];
  const float* b_cr   = (const float*)d_in[10];
  const float* W_atom = (const float*)d_in[11];
  const float* b_atom = (const float*)d_in[12];
  const float* W_q    = (const float*)d_in[13];
  const float* b_q    = (const float*)d_in[14];
  const float* W_k    = (const float*)d_in[15];
  const float* b_k    = (const float*)d_in[16];
  const float* W_v    = (const float*)d_in[17];
  const float* b_v    = (const float*)d_in[18];
  const float* W_o    = (const float*)d_in[19];
  const float* b_o    = (const float*)d_in[20];
  const int*   pp     = (const int*)d_in[21];
  const int*   occ    = (const int*)d_in[24];
  float* out = (float*)d_out;

  float *p_Q, *p_K, *p_V;
  cudaGetSymbolAddress((void**)&p_Q, g_Qb);
  cudaGetSymbolAddress((void**)&p_K, g_Kb);
  cudaGetSymbolAddress((void**)&p_V, g_Vb);

  const int PROJ_SMEM  = (4*128*STP)*4;
  const int ATTN1_SMEM = (3*128*ST)*4;
  const int ATTN2_SMEM = (3*128*ST + 512)*4;
  static bool attr_done = false;
  static cudaStream_t s2 = nullptr;
  static cudaEvent_t eF = nullptr, eJ = nullptr;
  if (!attr_done){
    cudaFuncSetAttribute(k_proj,  cudaFuncAttributeMaxDynamicSharedMemorySize, PROJ_SMEM);
    cudaFuncSetAttribute(k_attn1, cudaFuncAttributeMaxDynamicSharedMemorySize, ATTN1_SMEM);
    cudaFuncSetAttribute(k_attn2, cudaFuncAttributeMaxDynamicSharedMemorySize, ATTN2_SMEM);
    cudaStreamCreateWithFlags(&s2, cudaStreamNonBlocking);
    cudaEventCreateWithFlags(&eF, cudaEventDisableTiming);
    cudaEventCreateWithFlags(&eJ, cudaEventDisableTiming);
    attr_done = true;
  }

  // stream 0 (capture origin)
  k_init<<<(B_*NH_*N_+255)/256, 256>>>(b_scb);                                   // 1
  const int PRE = 2*(B_*N_*H_/8) + 5*(H_*H_/8);
  k_preconv<<<(PRE+255)/256, 256>>>(x, pp, W_var, W_sym, W_q, W_k, W_v);         // 2
  // fork: s2 runs var/sym/V projections + cross + post, overlapped with QK proj + attn1
  cudaEventRecord(eF, 0);
  cudaStreamWaitEvent(s2, eF, 0);
  dim3 gpR(H_/128, (B_*N_)/128, 3);
  k_proj<<<gpR, 256, PROJ_SMEM, s2>>>(b_var, b_sym, b_q, b_k, b_v, W_sc, p_Q, p_K, p_V, 1);
  k_cross<<<B_*M_, 128, 0, s2>>>(x, W_cr, b_cr, occ);
  k_post<<<B_, 1024, 0, s2>>>(pp);
  dim3 gpQK(H_/128, (B_*N_)/128, 2);
  k_proj<<<gpQK, 256, PROJ_SMEM>>>(b_var, b_sym, b_q, b_k, b_v, W_sc, p_Q, p_K, p_V, 0); // slot 4
  dim3 ga(B_*NH_, N_/128);
  k_attn1<<<ga, 256, ATTN1_SMEM>>>();
  // join
  cudaEventRecord(eJ, s2);
  cudaStreamWaitEvent(0, eJ, 0);
  dim3 gbf(B_*NH_, N_/8);
  k_bandfix<<<gbf, 256>>>();
  k_attn2<<<ga, 256, ATTN2_SMEM>>>();
  dim3 gmv(B_, 16);
  k_matvec<<<gmv, 768>>>();
  dim3 gf(B_, H_/128);
  k_final1<<<gf, 256>>>(W_o, b_o);
  k_final2<<<gf, 256>>>(W_atom, b_atom, out);
}